// round 11
// baseline (speedup 1.0000x reference)
#include <cuda_runtime.h>
#include <cuda_bf16.h>
#include <math.h>
#include <stdint.h>

#define NL   6
#define DD   512
#define NH   8
#define DKH  64
#define DFF  2048
#define WWIN 256
#define NB   4
#define TT   1024
#define NT   (NB * TT)

typedef __nv_bfloat16 bf16;
typedef __nv_bfloat162 bf162;

__device__ float g_h    [NT * DD];
__device__ bf16  g_hn_h [NT * DD];
__device__ bf16  g_hn_l [NT * DD];
__device__ bf16  g_qkv_h[NT * 3 * DD];
__device__ bf16  g_qkv_l[NT * 3 * DD];
__device__ bf16  g_o_h  [NT * DD];
__device__ bf16  g_o_l  [NT * DD];
__device__ bf16  g_ff_h [NT * DFF];
__device__ bf16  g_ff_l [NT * DFF];
__device__ bf16  g_hs_h [NT * DD];
__device__ bf16  g_hs_l [NT * DD];
__device__ float g_ho   [NT * DD];
__device__ int   g_pad  [NT];

__device__ bf16 w_qkv_h[NL * DD * 3 * DD];
__device__ bf16 w_qkv_l[NL * DD * 3 * DD];
__device__ bf16 w_wo_h [NL * DD * DD];
__device__ bf16 w_wo_l [NL * DD * DD];
__device__ bf16 w_w1_h [NL * DD * DFF];
__device__ bf16 w_w1_l [NL * DD * DFF];
__device__ bf16 w_w2_h [NL * DFF * DD];
__device__ bf16 w_w2_l [NL * DFF * DD];
__device__ bf16 w_hd_h [DD * DD];
__device__ bf16 w_hd_l [DD * DD];
__device__ float b_qkv [NL * 3 * DD];
__device__ float b_hd  [DD];

__device__ __forceinline__ float gelu_f(float x) {
    return 0.5f * x * (1.0f + erff(x * 0.7071067811865476f));
}
__device__ __forceinline__ void split2(float v, bf16& h, bf16& l) {
    h = __float2bfloat16(v);
    l = __float2bfloat16(v - __bfloat162float(h));
}
__device__ __forceinline__ void splitpack2(float x, float y, uint32_t& hi, uint32_t& lo) {
    bf162 H = __floats2bfloat162_rn(x, y);
    bf162 L = __floats2bfloat162_rn(x - __bfloat162float(H.x), y - __bfloat162float(H.y));
    hi = *reinterpret_cast<uint32_t*>(&H);
    lo = *reinterpret_cast<uint32_t*>(&L);
}
__device__ __forceinline__ float fexp(float x) {
    float y = fmaxf(x * 1.4426950408889634f, -126.0f);
    int i = __float2int_rn(y);
    float f = y - (float)i;
    float p = 1.5356298e-4f;
    p = fmaf(p, f, 1.3333558e-3f);
    p = fmaf(p, f, 9.6181291e-3f);
    p = fmaf(p, f, 5.5504109e-2f);
    p = fmaf(p, f, 2.4022651e-1f);
    p = fmaf(p, f, 6.9314718e-1f);
    p = fmaf(p, f, 1.0f);
    return p * __int_as_float((i + 127) << 23);
}
__device__ __forceinline__ void mma_bf16(float* c, const uint32_t* a, const uint32_t* b) {
    asm volatile(
        "mma.sync.aligned.m16n8k16.row.col.f32.bf16.bf16.f32 "
        "{%0,%1,%2,%3},{%4,%5,%6,%7},{%8,%9},{%0,%1,%2,%3};"
        : "+f"(c[0]), "+f"(c[1]), "+f"(c[2]), "+f"(c[3])
        : "r"(a[0]), "r"(a[1]), "r"(a[2]), "r"(a[3]), "r"(b[0]), "r"(b[1]));
}
__device__ __forceinline__ void ldm_x4(uint32_t& r0, uint32_t& r1, uint32_t& r2, uint32_t& r3, uint32_t a) {
    asm volatile("ldmatrix.sync.aligned.m8n8.x4.shared.b16 {%0,%1,%2,%3},[%4];"
                 : "=r"(r0), "=r"(r1), "=r"(r2), "=r"(r3) : "r"(a));
}
__device__ __forceinline__ void ldm_x4t(uint32_t& r0, uint32_t& r1, uint32_t& r2, uint32_t& r3, uint32_t a) {
    asm volatile("ldmatrix.sync.aligned.m8n8.x4.trans.shared.b16 {%0,%1,%2,%3},[%4];"
                 : "=r"(r0), "=r"(r1), "=r"(r2), "=r"(r3) : "r"(a));
}
#define CP_ASYNC16(dst, src) \
    asm volatile("cp.async.cg.shared.global [%0], [%1], 16;\n" :: "r"(dst), "l"(src))
#define CP_COMMIT() asm volatile("cp.async.commit_group;\n")
#define CP_WAIT(n)  asm volatile("cp.async.wait_group %0;\n" :: "n"(n))

__device__ __forceinline__ void split4store(float4 v, bf16* hi, bf16* lo) {
    bf162 h0 = __floats2bfloat162_rn(v.x, v.y);
    bf162 h1 = __floats2bfloat162_rn(v.z, v.w);
    bf162 l0 = __floats2bfloat162_rn(v.x - __bfloat162float(h0.x), v.y - __bfloat162float(h0.y));
    bf162 l1 = __floats2bfloat162_rn(v.z - __bfloat162float(h1.x), v.w - __bfloat162float(h1.y));
    uint2 H = {*(uint32_t*)&h0, *(uint32_t*)&h1};
    uint2 L = {*(uint32_t*)&l0, *(uint32_t*)&l1};
    *reinterpret_cast<uint2*>(hi) = H;
    *reinterpret_cast<uint2*>(lo) = L;
}

// ---------------- single merged prep kernel ----------------
#define N4_QKV (NL * DD * 3 * DD / 4)
#define N4_WO  (NL * DD * DD / 4)
#define N4_W1  (NL * DD * DFF / 4)
#define N4_W2  (NL * DFF * DD / 4)
#define N4_HD  (DD * DD / 4)
#define N4_TOT (N4_QKV + N4_WO + N4_W1 + N4_W2 + N4_HD)

__global__ void prep_all(const float* __restrict__ Wq, const float* __restrict__ Wk,
                         const float* __restrict__ Wv, const float* __restrict__ bq,
                         const float* __restrict__ bk, const float* __restrict__ bv,
                         const float* __restrict__ Wo, const float* __restrict__ W1,
                         const float* __restrict__ W2,
                         const float* __restrict__ bhW1, const float* __restrict__ bhb1,
                         const float* __restrict__ ahW1, const float* __restrict__ ahb1,
                         const float* __restrict__ chW1, const float* __restrict__ chb1)
{
    for (int i4 = blockIdx.x * blockDim.x + threadIdx.x; i4 < N4_TOT; i4 += gridDim.x * blockDim.x) {
        if (i4 < N4_QKV) {
            int idx = i4 * 4;
            int l = idx / (DD * 3 * DD);
            int r = idx % (DD * 3 * DD);
            int k = r / (3 * DD);
            int n = r % (3 * DD);
            const float* src;
            if (n < DD)           src = Wq + (size_t)l * DD * DD + k * DD + n;
            else if (n < 2 * DD)  src = Wk + (size_t)l * DD * DD + k * DD + (n - DD);
            else                  src = Wv + (size_t)l * DD * DD + k * DD + (n - 2 * DD);
            split4store(*reinterpret_cast<const float4*>(src), &w_qkv_h[idx], &w_qkv_l[idx]);
        } else if (i4 < N4_QKV + N4_WO) {
            int j = i4 - N4_QKV, idx = j * 4;
            split4store(reinterpret_cast<const float4*>(Wo)[j], &w_wo_h[idx], &w_wo_l[idx]);
        } else if (i4 < N4_QKV + N4_WO + N4_W1) {
            int j = i4 - N4_QKV - N4_WO, idx = j * 4;
            split4store(reinterpret_cast<const float4*>(W1)[j], &w_w1_h[idx], &w_w1_l[idx]);
        } else if (i4 < N4_QKV + N4_WO + N4_W1 + N4_W2) {
            int j = i4 - N4_QKV - N4_WO - N4_W1, idx = j * 4;
            split4store(reinterpret_cast<const float4*>(W2)[j], &w_w2_h[idx], &w_w2_l[idx]);
        } else {
            int j = i4 - (N4_QKV + N4_WO + N4_W1 + N4_W2);
            int idx = j * 4;
            int k = idx / DD, n = idx % DD;
            const float* src;
            if (n < 256)      src = bhW1 + k * 256 + n;
            else if (n < 384) src = ahW1 + k * 128 + (n - 256);
            else              src = chW1 + k * 128 + (n - 384);
            split4store(*reinterpret_cast<const float4*>(src), &w_hd_h[idx], &w_hd_l[idx]);
        }
    }
    for (int i = blockIdx.x * blockDim.x + threadIdx.x; i < NL * 3 * DD; i += gridDim.x * blockDim.x) {
        int l = i / (3 * DD), n = i % (3 * DD);
        b_qkv[i] = (n < DD) ? bq[l * DD + n] : (n < 2 * DD) ? bk[l * DD + n - DD] : bv[l * DD + n - 2 * DD];
    }
    for (int n = blockIdx.x * blockDim.x + threadIdx.x; n < DD; n += gridDim.x * blockDim.x)
        b_hd[n] = (n < 256) ? bhb1[n] : (n < 384) ? ahb1[n - 256] : chb1[n - 384];
}

__global__ void embed_kernel(const float* __restrict__ x, const float* __restrict__ pos,
                             const float* __restrict__ Wp, const float* __restrict__ bp)
{
    int token = blockIdx.x;
    int t = token % TT;
    float xv = x[token];
    if (threadIdx.x == 0) g_pad[token] = (xv == -1.0f) ? 1 : 0;
    for (int d = threadIdx.x; d < DD; d += blockDim.x)
        g_h[(size_t)token * DD + d] = xv * Wp[d] + bp[d] + pos[(size_t)t * DD + d];
}

__global__ void ln_kernel(const float* __restrict__ in, const float* __restrict__ gg,
                          const float* __restrict__ bb, bf16* __restrict__ outh,
                          bf16* __restrict__ outl)
{
    int token = blockIdx.x;
    int tid = threadIdx.x;
    const float* row = in + (size_t)token * DD;
    float v0 = row[tid];
    float v1 = row[tid + 256];
    __shared__ float red[8];
    __shared__ float stat[2];
    float s = v0 + v1;
    #pragma unroll
    for (int o = 16; o; o >>= 1) s += __shfl_down_sync(0xffffffffu, s, o);
    if ((tid & 31) == 0) red[tid >> 5] = s;
    __syncthreads();
    if (tid == 0) {
        float tt = 0.f;
        #pragma unroll
        for (int i = 0; i < 8; i++) tt += red[i];
        stat[0] = tt * (1.0f / DD);
    }
    __syncthreads();
    float mean = stat[0];
    float d0 = v0 - mean, d1 = v1 - mean;
    float q = d0 * d0 + d1 * d1;
    #pragma unroll
    for (int o = 16; o; o >>= 1) q += __shfl_down_sync(0xffffffffu, q, o);
    __syncthreads();
    if ((tid & 31) == 0) red[tid >> 5] = q;
    __syncthreads();
    if (tid == 0) {
        float tt = 0.f;
        #pragma unroll
        for (int i = 0; i < 8; i++) tt += red[i];
        stat[1] = rsqrtf(tt * (1.0f / DD) + 1e-5f);
    }
    __syncthreads();
    float inv = stat[1];
    float y0 = d0 * inv * gg[tid]       + bb[tid];
    float y1 = d1 * inv * gg[tid + 256] + bb[tid + 256];
    split2(y0, outh[(size_t)token * DD + tid],       outl[(size_t)token * DD + tid]);
    split2(y1, outh[(size_t)token * DD + tid + 256], outl[(size_t)token * DD + tid + 256]);
}

// ---------------- bf16x3 GEMM (R5/R9 config, plane-major mma order) ----------
#define A_STR 40
#define B_STR 72
#define ASZ (128 * A_STR)
#define BSZ (32 * B_STR)
#define GEMM_SMEM ((4 * ASZ + 4 * BSZ) * 2)

__global__ void __launch_bounds__(256)
gemm_bf3(const bf16* __restrict__ Ah, const bf16* __restrict__ Al,
         const bf16* __restrict__ Wh, const bf16* __restrict__ Wl,
         const float* __restrict__ bias, const float* __restrict__ res,
         float* __restrict__ Cf, bf16* __restrict__ Chi, bf16* __restrict__ Clo,
         int M, int N, int K, int act)
{
    extern __shared__ bf16 smem[];
    const uint32_t smb = (uint32_t)__cvta_generic_to_shared(smem);
    const uint32_t oAl = 2 * ASZ * 2;
    const uint32_t oBh = 4 * ASZ * 2;
    const uint32_t oBl = oBh + 2 * BSZ * 2;

    const int tid  = threadIdx.x;
    const int bm   = blockIdx.y * 128;
    const int bn   = blockIdx.x * 64;
    const int warp = tid >> 5, lane = tid & 31;
    const int wm   = (warp & 3) * 32;
    const int wn   = (warp >> 2) * 32;
    const int group = lane >> 2, tig = lane & 3;
    const int matm = (lane >> 3) & 1;
    const int math = (lane >> 4) & 1;
    const int r7   = lane & 7;
    const uint32_t aLane = (uint32_t)((matm * 8 + r7) * (A_STR * 2) + math * 16);
    const uint32_t bLane = (uint32_t)((matm * 8 + r7) * (B_STR * 2) + math * 16);

    float acc[2][4][4] = {};
    const int nkb = K >> 5;

    auto loadA = [&](int kb, int st) {
        const uint32_t sb = smb + st * (ASZ * 2);
        #pragma unroll
        for (int i = 0; i < 2; i++) {
            int s = tid + i * 256;
            int row = s >> 2, c8 = (s & 3) * 8;
            uint32_t off = (uint32_t)((row * A_STR + c8) * 2);
            size_t gsrc = (size_t)(bm + row) * K + kb * 32 + c8;
            CP_ASYNC16(sb + off, Ah + gsrc);
            CP_ASYNC16(sb + oAl + off, Al + gsrc);
        }
    };
    auto loadB = [&](int kb, int st) {
        const uint32_t sb = smb + st * (BSZ * 2);
        int row = tid >> 3, c8 = (tid & 7) * 8;
        uint32_t off = (uint32_t)((row * B_STR + c8) * 2);
        size_t gsrc = (size_t)(kb * 32 + row) * N + bn + c8;
        CP_ASYNC16(sb + oBh + off, Wh + gsrc);
        CP_ASYNC16(sb + oBl + off, Wl + gsrc);
    };

    loadA(0, 0); loadB(0, 0); CP_COMMIT();

    for (int kb = 0; kb < nkb; kb++) {
        int cur = kb & 1;
        if (kb + 1 < nkb) {
            loadA(kb + 1, cur ^ 1); loadB(kb + 1, cur ^ 1);
            CP_COMMIT();
            CP_WAIT(1);
        } else {
            CP_WAIT(0);
        }
        __syncthreads();
        const uint32_t aBase = smb + cur * (ASZ * 2);
        const uint32_t bBase = smb + cur * (BSZ * 2) + oBh;
        #pragma unroll
        for (int ks = 0; ks < 2; ks++) {
            uint32_t ah[2][4], al[2][4], bh[4][2], bl[4][2];
            #pragma unroll
            for (int mt = 0; mt < 2; mt++) {
                uint32_t addr = aBase + (uint32_t)((wm + mt * 16) * (A_STR * 2) + ks * 32) + aLane;
                ldm_x4(ah[mt][0], ah[mt][1], ah[mt][2], ah[mt][3], addr);
                ldm_x4(al[mt][0], al[mt][1], al[mt][2], al[mt][3], addr + oAl);
            }
            #pragma unroll
            for (int p = 0; p < 2; p++) {
                uint32_t addr = bBase + (uint32_t)(ks * 16 * (B_STR * 2) + (wn + p * 16) * 2) + bLane;
                uint32_t t0, t1, t2, t3;
                ldm_x4t(t0, t1, t2, t3, addr);
                bh[2 * p][0] = t0; bh[2 * p][1] = t1; bh[2 * p + 1][0] = t2; bh[2 * p + 1][1] = t3;
                ldm_x4t(t0, t1, t2, t3, addr + (oBl - oBh));
                bl[2 * p][0] = t0; bl[2 * p][1] = t1; bl[2 * p + 1][0] = t2; bl[2 * p + 1][1] = t3;
            }
            // plane-major order: 8 independent mmas between accumulator reuse
            #pragma unroll
            for (int mt = 0; mt < 2; mt++)
                #pragma unroll
                for (int nt = 0; nt < 4; nt++)
                    mma_bf16(acc[mt][nt], ah[mt], bh[nt]);
            #pragma unroll
            for (int mt = 0; mt < 2; mt++)
                #pragma unroll
                for (int nt = 0; nt < 4; nt++)
                    mma_bf16(acc[mt][nt], ah[mt], bl[nt]);
            #pragma unroll
            for (int mt = 0; mt < 2; mt++)
                #pragma unroll
                for (int nt = 0; nt < 4; nt++)
                    mma_bf16(acc[mt][nt], al[mt], bh[nt]);
        }
        __syncthreads();
    }

    #pragma unroll
    for (int mt = 0; mt < 2; mt++) {
        int r0 = bm + wm + mt * 16 + group;
        #pragma unroll
        for (int nt = 0; nt < 4; nt++) {
            int cc = bn + wn + nt * 8 + tig * 2;
            float b0 = bias[cc], b1 = bias[cc + 1];
            float v00 = acc[mt][nt][0] + b0;
            float v01 = acc[mt][nt][1] + b1;
            float v10 = acc[mt][nt][2] + b0;
            float v11 = acc[mt][nt][3] + b1;
            if (act) { v00 = gelu_f(v00); v01 = gelu_f(v01); v10 = gelu_f(v10); v11 = gelu_f(v11); }
            if (Chi) {
                uint32_t hh, ll;
                splitpack2(v00, v01, hh, ll);
                *reinterpret_cast<uint32_t*>(&Chi[(size_t)r0 * N + cc]) = hh;
                *reinterpret_cast<uint32_t*>(&Clo[(size_t)r0 * N + cc]) = ll;
                splitpack2(v10, v11, hh, ll);
                *reinterpret_cast<uint32_t*>(&Chi[(size_t)(r0 + 8) * N + cc]) = hh;
                *reinterpret_cast<uint32_t*>(&Clo[(size_t)(r0 + 8) * N + cc]) = ll;
            } else {
                if (res) {
                    v00 += res[(size_t)r0 * N + cc];       v01 += res[(size_t)r0 * N + cc + 1];
                    v10 += res[(size_t)(r0 + 8) * N + cc]; v11 += res[(size_t)(r0 + 8) * N + cc + 1];
                }
                Cf[(size_t)r0 * N + cc]           = v00;
                Cf[(size_t)r0 * N + cc + 1]       = v01;
                Cf[(size_t)(r0 + 8) * N + cc]     = v10;
                Cf[(size_t)(r0 + 8) * N + cc + 1] = v11;
            }
        }
    }
}

// ---------------- tensor-core flash attention (plane-major mma order) ---------
#define AST 72
#define PLB (64 * AST * 2)
#define ATTN_SMEM (8 * PLB + 512)

__global__ void __launch_bounds__(128)
flash_attn_mma(const bf16* __restrict__ qkvh, const bf16* __restrict__ qkvl,
               const int* __restrict__ pad, bf16* __restrict__ ohi, bf16* __restrict__ olo)
{
    extern __shared__ char smraw[];
    const uint32_t smb = (uint32_t)__cvta_generic_to_shared(smraw);
    const uint32_t oQ = 0, oK = 2 * PLB, oV0 = 6 * PLB, oPS = 8 * PLB;

    const int tid  = threadIdx.x;
    const int lane = tid & 31;
    const int w    = tid >> 5;
    const int qt0  = blockIdx.x * 64;
    const int b    = blockIdx.y;
    const int h    = blockIdx.z;

    const int r7 = lane & 7;
    const int bA = (lane >> 3) & 1;
    const int bB = (lane >> 4) & 1;
    const int kRow = bB * 8 + r7;
    const int kCol = bA * 16;
    const int qg0 = qt0 + w * 16 + (lane >> 2);
    const int qg1 = qg0 + 8;

    #pragma unroll
    for (int i = 0; i < 4; i++) {
        int s = tid + i * 128;
        int r = s >> 3, c8 = (s & 7) * 8;
        size_t g = (size_t)(b * TT + qt0 + r) * (3 * DD) + h * DKH + c8;
        uint32_t d = smb + oQ + (uint32_t)((r * AST + c8) * 2);
        CP_ASYNC16(d, qkvh + g);
        CP_ASYNC16(d + PLB, qkvl + g);
    }
    CP_COMMIT();

    int c_start = 4 - (qt0 >> 6);
    if (c_start < 0) c_start = 0;

    auto issueK = [&](int c, int st) {
        int kc0 = qt0 - WWIN + 64 * c;
        #pragma unroll
        for (int i = 0; i < 4; i++) {
            int s = tid + i * 128;
            int r = s >> 3, c8 = (s & 7) * 8;
            size_t g = (size_t)(b * TT + kc0 + r) * (3 * DD) + DD + h * DKH + c8;
            uint32_t d = smb + oK + (uint32_t)(st * 2 * PLB) + (uint32_t)((r * AST + c8) * 2);
            CP_ASYNC16(d, qkvh + g);
            CP_ASYNC16(d + PLB, qkvl + g);
        }
        if (tid < 16)
            CP_ASYNC16(smb + oPS + (uint32_t)(st * 256 + tid * 16), pad + b * TT + kc0 + tid * 4);
    };
    auto issueV = [&](int c, int st) {
        int kc0 = qt0 - WWIN + 64 * c;
        uint32_t base = st ? (smb + oQ) : (smb + oV0);
        #pragma unroll
        for (int i = 0; i < 4; i++) {
            int s = tid + i * 128;
            int r = s >> 3, c8 = (s & 7) * 8;
            size_t g = (size_t)(b * TT + kc0 + r) * (3 * DD) + 2 * DD + h * DKH + c8;
            uint32_t d = base + (uint32_t)((r * AST + c8) * 2);
            CP_ASYNC16(d, qkvh + g);
            CP_ASYNC16(d + PLB, qkvl + g);
        }
    };

    issueK(c_start, 0); CP_COMMIT();
    issueV(c_start, 0); CP_COMMIT();

    CP_WAIT(2);
    __syncthreads();

    uint32_t qfh[4][4], qfl[4][4];
    #pragma unroll
    for (int ks = 0; ks < 4; ks++) {
        uint32_t ad = smb + oQ + (uint32_t)(((w * 16 + bA * 8 + r7) * AST) * 2 + ks * 32 + bB * 16);
        ldm_x4(qfh[ks][0], qfh[ks][1], qfh[ks][2], qfh[ks][3], ad);
        ldm_x4(qfl[ks][0], qfl[ks][1], qfl[ks][2], qfl[ks][3], ad + PLB);
    }

    float Oa[8][4];
    #pragma unroll
    for (int i = 0; i < 8; i++)
        #pragma unroll
        for (int j = 0; j < 4; j++) Oa[i][j] = 0.f;
    float mold[2] = {-1e30f, -1e30f};
    float lrun[2] = {0.f, 0.f};

    int stage = 0;
    for (int c = c_start; c < 5; c++) {
        const int kc0 = qt0 - WWIN + 64 * c;
        CP_WAIT(1);
        __syncthreads();

        float s4[8][4];
        #pragma unroll
        for (int i = 0; i < 8; i++)
            #pragma unroll
            for (int j = 0; j < 4; j++) s4[i][j] = 0.f;
        const uint32_t kb0 = smb + oK + (uint32_t)(stage * 2 * PLB);
        #pragma unroll
        for (int ks = 0; ks < 4; ks++) {
            uint32_t kh[8][2], kl[8][2];
            #pragma unroll
            for (int p = 0; p < 4; p++) {
                uint32_t ad = kb0 + (uint32_t)(((p * 16 + kRow) * AST) * 2 + ks * 32 + kCol);
                ldm_x4(kh[2 * p][0], kh[2 * p][1], kh[2 * p + 1][0], kh[2 * p + 1][1], ad);
                ldm_x4(kl[2 * p][0], kl[2 * p][1], kl[2 * p + 1][0], kl[2 * p + 1][1], ad + PLB);
            }
            #pragma unroll
            for (int nt = 0; nt < 8; nt++) mma_bf16(s4[nt], qfh[ks], kh[nt]);
            #pragma unroll
            for (int nt = 0; nt < 8; nt++) mma_bf16(s4[nt], qfh[ks], kl[nt]);
            #pragma unroll
            for (int nt = 0; nt < 8; nt++) mma_bf16(s4[nt], qfl[ks], kh[nt]);
        }

        if (c < 4) { issueK(c + 1, stage ^ 1); CP_COMMIT(); }

        const int* psS = (const int*)(smraw + oPS + stage * 256);
        const int jb = 2 * (lane & 3);
        #pragma unroll
        for (int nt = 0; nt < 8; nt++) {
            int jj = nt * 8 + jb;
            int j  = kc0 + jj;
            int pd0 = psS[jj], pd1 = psS[jj + 1];
            bool v00 = (j     <= qg0) && (j     >= qg0 - (WWIN - 1)) && !pd0;
            bool v01 = (j + 1 <= qg0) && (j + 1 >= qg0 - (WWIN - 1)) && !pd1;
            bool v10 = (j     <= qg1) && (j     >= qg1 - (WWIN - 1)) && !pd0;
            bool v11 = (j + 1 <= qg1) && (j + 1 >= qg1 - (WWIN - 1)) && !pd1;
            s4[nt][0] = v00 ? s4[nt][0] * 0.125f : -1e30f;
            s4[nt][1] = v01 ? s4[nt][1] * 0.125f : -1e30f;
            s4[nt][2] = v10 ? s4[nt][2] * 0.125f : -1e30f;
            s4[nt][3] = v11 ? s4[nt][3] * 0.125f : -1e30f;
        }

        float mc0 = -1e30f, mc1 = -1e30f;
        #pragma unroll
        for (int nt = 0; nt < 8; nt++) {
            mc0 = fmaxf(mc0, fmaxf(s4[nt][0], s4[nt][1]));
            mc1 = fmaxf(mc1, fmaxf(s4[nt][2], s4[nt][3]));
        }
        mc0 = fmaxf(mc0, __shfl_xor_sync(0xffffffffu, mc0, 1));
        mc0 = fmaxf(mc0, __shfl_xor_sync(0xffffffffu, mc0, 2));
        mc1 = fmaxf(mc1, __shfl_xor_sync(0xffffffffu, mc1, 1));
        mc1 = fmaxf(mc1, __shfl_xor_sync(0xffffffffu, mc1, 2));
        float mn0 = fmaxf(mold[0], mc0);
        float mn1 = fmaxf(mold[1], mc1);
        float al0 = fexp(mold[0] - mn0);
        float al1 = fexp(mold[1] - mn1);
        mold[0] = mn0; mold[1] = mn1;
        float ps0 = 0.f, ps1 = 0.f;
        #pragma unroll
        for (int nt = 0; nt < 8; nt++) {
            float p0 = (s4[nt][0] <= -1e29f) ? 0.f : fexp(s4[nt][0] - mn0);
            float p1 = (s4[nt][1] <= -1e29f) ? 0.f : fexp(s4[nt][1] - mn0);
            float p2 = (s4[nt][2] <= -1e29f) ? 0.f : fexp(s4[nt][2] - mn1);
            float p3 = (s4[nt][3] <= -1e29f) ? 0.f : fexp(s4[nt][3] - mn1);
            s4[nt][0] = p0; s4[nt][1] = p1; s4[nt][2] = p2; s4[nt][3] = p3;
            ps0 += p0 + p1; ps1 += p2 + p3;
        }
        ps0 += __shfl_xor_sync(0xffffffffu, ps0, 1);
        ps0 += __shfl_xor_sync(0xffffffffu, ps0, 2);
        ps1 += __shfl_xor_sync(0xffffffffu, ps1, 1);
        ps1 += __shfl_xor_sync(0xffffffffu, ps1, 2);
        lrun[0] = lrun[0] * al0 + ps0;
        lrun[1] = lrun[1] * al1 + ps1;

        #pragma unroll
        for (int nt = 0; nt < 8; nt++) {
            Oa[nt][0] *= al0; Oa[nt][1] *= al0;
            Oa[nt][2] *= al1; Oa[nt][3] *= al1;
        }

        uint32_t aPh[4][4], aPl[4][4];
        #pragma unroll
        for (int t = 0; t < 4; t++) {
            splitpack2(s4[2 * t][0],     s4[2 * t][1],     aPh[t][0], aPl[t][0]);
            splitpack2(s4[2 * t][2],     s4[2 * t][3],     aPh[t][1], aPl[t][1]);
            splitpack2(s4[2 * t + 1][0], s4[2 * t + 1][1], aPh[t][2], aPl[t][2]);
            splitpack2(s4[2 * t + 1][2], s4[2 * t + 1][3], aPh[t][3], aPl[t][3]);
        }

        if (c < 4) { CP_WAIT(1); } else { CP_WAIT(0); }
        __syncthreads();
        if (c < 4) { issueV(c + 1, stage ^ 1); CP_COMMIT(); }

        const uint32_t vb0 = stage ? (smb + oQ) : (smb + oV0);
        #pragma unroll
        for (int t = 0; t < 4; t++) {
            uint32_t vh[8][2], vl[8][2];
            #pragma unroll
            for (int p = 0; p < 4; p++) {
                uint32_t ad = vb0 + (uint32_t)(((t * 16 + bA * 8 + r7) * AST) * 2 + p * 32 + bB * 16);
                uint32_t t0, t1, t2, t3;
                ldm_x4t(t0, t1, t2, t3, ad);
                vh[2 * p][0] = t0; vh[2 * p][1] = t1; vh[2 * p + 1][0] = t2; vh[2 * p + 1][1] = t3;
                ldm_x4t(t0, t1, t2, t3, ad + PLB);
                vl[2 * p][0] = t0; vl[2 * p][1] = t1; vl[2 * p + 1][0] = t2; vl[2 * p + 1][1] = t3;
            }
            #pragma unroll
            for (int nt = 0; nt < 8; nt++) mma_bf16(Oa[nt], aPh[t], vh[nt]);
            #pragma unroll
            for (int nt = 0; nt < 8; nt++) mma_bf16(Oa[nt], aPh[t], vl[nt]);
            #pragma unroll
            for (int nt = 0; nt < 8; nt++) mma_bf16(Oa[nt], aPl[t], vh[nt]);
        }
        stage ^= 1;
    }

    float inv0 = (lrun[0] > 0.f) ? 1.0f / lrun[0] : 0.f;
    float inv1 = (lrun[1] > 0.f) ? 1.0f / lrun[1] : 0.f;
    int tok0 = b * TT + qt0 + w * 16 + (lane >> 2);
    #pragma unroll
    for (int nt = 0; nt < 8; nt++) {
        int col = h * DKH + nt * 8 + 2 * (lane & 3);
        uint32_t hi, lo;
        splitpack2(Oa[nt][0] * inv0, Oa[nt][1] * inv0, hi, lo);
        *reinterpret_cast<uint32_t*>(&ohi[(size_t)tok0 * DD + col]) = hi;
        *reinterpret_cast<uint32_t*>(&olo[(size_t)tok0 * DD + col]) = lo;
        splitpack2(Oa[nt][2] * inv1, Oa[nt][3] * inv1, hi, lo);
        *reinterpret_cast<uint32_t*>(&ohi[(size_t)(tok0 + 8) * DD + col]) = hi;
        *reinterpret_cast<uint32_t*>(&olo[(size_t)(tok0 + 8) * DD + col]) = lo;
    }
}

__global__ void split_h4(const float4* __restrict__ src, bf16* __restrict__ hi,
                         bf16* __restrict__ lo, int n4)
{
    for (int i = blockIdx.x * blockDim.x + threadIdx.x; i < n4; i += gridDim.x * blockDim.x)
        split4store(src[i], hi + i * 4, lo + i * 4);
}

__global__ void finish_heads(const float* __restrict__ ho,
                             const float* __restrict__ bhW2, const float* __restrict__ bhb2,
                             const float* __restrict__ ahW2, const float* __restrict__ ahb2,
                             const float* __restrict__ chW2, const float* __restrict__ chb2,
                             float* __restrict__ out)
{
    int token = blockIdx.x;
    int tid = threadIdx.x;
    __shared__ float red[128];
    const float* row = ho + (size_t)token * DD;

    float t0 = row[tid] * bhW2[tid * 2]     + row[tid + 128] * bhW2[(tid + 128) * 2];
    float t1 = row[tid] * bhW2[tid * 2 + 1] + row[tid + 128] * bhW2[(tid + 128) * 2 + 1];
    red[tid] = t0; __syncthreads();
    for (int s = 64; s > 0; s >>= 1) { if (tid < s) red[tid] += red[tid + s]; __syncthreads(); }
    float s0 = red[0]; __syncthreads();
    red[tid] = t1; __syncthreads();
    for (int s = 64; s > 0; s >>= 1) { if (tid < s) red[tid] += red[tid + s]; __syncthreads(); }
    float s1 = red[0]; __syncthreads();
    red[tid] = row[256 + tid] * ahW2[tid]; __syncthreads();
    for (int s = 64; s > 0; s >>= 1) { if (tid < s) red[tid] += red[tid + s]; __syncthreads(); }
    float sa = red[0]; __syncthreads();
    red[tid] = row[384 + tid] * chW2[tid]; __syncthreads();
    for (int s = 64; s > 0; s >>= 1) { if (tid < s) red[tid] += red[tid + s]; __syncthreads(); }
    float sc = red[0];

    if (tid == 0) {
        out[token * 2 + 0] = s0 + bhb2[0];
        out[token * 2 + 1] = s1 + bhb2[1];
        out[2 * NT + token] = sa + ahb2[0];
        out[3 * NT + token] = 1.0f / (1.0f + expf(-(sc + chb2[0])));
    }
}

#define SYM(p, s) cudaGetSymbolAddress((void**)&p, s)

extern "C" void kernel_launch(void* const* d_in, const int* in_sizes, int n_in,
                              void* d_out, int out_size)
{
    const float* x    = (const float*)d_in[0];
    const float* pos  = (const float*)d_in[1];
    const float* Wp   = (const float*)d_in[2];
    const float* bp   = (const float*)d_in[3];
    const float* Wq   = (const float*)d_in[4];
    const float* bq   = (const float*)d_in[5];
    const float* Wk   = (const float*)d_in[6];
    const float* bk   = (const float*)d_in[7];
    const float* Wv   = (const float*)d_in[8];
    const float* bv   = (const float*)d_in[9];
    const float* Wo   = (const float*)d_in[10];
    const float* bo   = (const float*)d_in[11];
    const float* ln1g = (const float*)d_in[12];
    const float* ln1b = (const float*)d_in[13];
    const float* W1   = (const float*)d_in[14];
    const float* b1   = (const float*)d_in[15];
    const float* W2   = (const float*)d_in[16];
    const float* b2   = (const float*)d_in[17];
    const float* ln2g = (const float*)d_in[18];
    const float* ln2b = (const float*)d_in[19];
    const float* bhW1 = (const float*)d_in[20];
    const float* bhb1 = (const float*)d_in[21];
    const float* bhW2 = (const float*)d_in[22];
    const float* bhb2 = (const float*)d_in[23];
    const float* ahW1 = (const float*)d_in[24];
    const float* ahb1 = (const float*)d_in[25];
    const float* ahW2 = (const float*)d_in[26];
    const float* ahb2 = (const float*)d_in[27];
    const float* chW1 = (const float*)d_in[28];
    const float* chb1 = (const float*)d_in[29];
    const float* chW2 = (const float*)d_in[30];
    const float* chb2 = (const float*)d_in[31];
    float* out = (float*)d_out;

    float *p_h, *p_ho, *p_bqkv, *p_bhd;
    bf16 *p_hnh, *p_hnl, *p_qkvh, *p_qkvl, *p_oh, *p_ol, *p_ffh, *p_ffl, *p_hsh, *p_hsl;
    bf16 *pw_qkvh, *pw_qkvl, *pw_woh, *pw_wol, *pw_w1h, *pw_w1l, *pw_w2h, *pw_w2l, *pw_hdh, *pw_hdl;
    int* p_pad;
    SYM(p_h, g_h);       SYM(p_hnh, g_hn_h);   SYM(p_hnl, g_hn_l);
    SYM(p_qkvh, g_qkv_h); SYM(p_qkvl, g_qkv_l);
    SYM(p_oh, g_o_h);    SYM(p_ol, g_o_l);
    SYM(p_ffh, g_ff_h);  SYM(p_ffl, g_ff_l);
    SYM(p_hsh, g_hs_h);  SYM(p_hsl, g_hs_l);
    SYM(p_ho, g_ho);     SYM(p_pad, g_pad);
    SYM(pw_qkvh, w_qkv_h); SYM(pw_qkvl, w_qkv_l);
    SYM(pw_woh, w_wo_h); SYM(pw_wol, w_wo_l);
    SYM(pw_w1h, w_w1_h); SYM(pw_w1l, w_w1_l);
    SYM(pw_w2h, w_w2_h); SYM(pw_w2l, w_w2_l);
    SYM(pw_hdh, w_hd_h); SYM(pw_hdl, w_hd_l);
    SYM(p_bqkv, b_qkv);  SYM(p_bhd, b_hd);

    cudaFuncSetAttribute(gemm_bf3, cudaFuncAttributeMaxDynamicSharedMemorySize, GEMM_SMEM);
    cudaFuncSetAttribute(flash_attn_mma, cudaFuncAttributeMaxDynamicSharedMemorySize, ATTN_SMEM);

    prep_all<<<4096, 256>>>(Wq, Wk, Wv, bq, bk, bv, Wo, W1, W2,
                            bhW1, bhb1, ahW1, ahb1, chW1, chb1);
    embed_kernel<<<NT, 128>>>(x, pos, Wp, bp);

    dim3 gQKV(3 * DD / 64, NT / 128);
    dim3 gD  (DD / 64,     NT / 128);
    dim3 gFF (DFF / 64,    NT / 128);
    dim3 gAtt(TT / 64, NB, NH);

    for (int l = 0; l < NL; l++) {
        ln_kernel<<<NT, 256>>>(p_h, ln1g + l * DD, ln1b + l * DD, p_hnh, p_hnl);
        gemm_bf3<<<gQKV, 256, GEMM_SMEM>>>(p_hnh, p_hnl,
            pw_qkvh + (size_t)l * DD * 3 * DD, pw_qkvl + (size_t)l * DD * 3 * DD,
            p_bqkv + l * 3 * DD, nullptr, nullptr, p_qkvh, p_qkvl, NT, 3 * DD, DD, 0);
        flash_attn_mma<<<gAtt, 128, ATTN_SMEM>>>(p_qkvh, p_qkvl, p_pad, p_oh, p_ol);
        gemm_bf3<<<gD, 256, GEMM_SMEM>>>(p_oh, p_ol,
            pw_woh + (size_t)l * DD * DD, pw_wol + (size_t)l * DD * DD,
            bo + l * DD, p_h, p_h, nullptr, nullptr, NT, DD, DD, 0);
        ln_kernel<<<NT, 256>>>(p_h, ln2g + l * DD, ln2b + l * DD, p_hnh, p_hnl);
        gemm_bf3<<<gFF, 256, GEMM_SMEM>>>(p_hnh, p_hnl,
            pw_w1h + (size_t)l * DD * DFF, pw_w1l + (size_t)l * DD * DFF,
            b1 + l * DFF, nullptr, nullptr, p_ffh, p_ffl, NT, DFF, DD, 1);
        gemm_bf3<<<gD, 256, GEMM_SMEM>>>(p_ffh, p_ffl,
            pw_w2h + (size_t)l * DFF * DD, pw_w2l + (size_t)l * DFF * DD,
            b2 + l * DD, p_h, p_h, nullptr, nullptr, NT, DD, DFF, 0);
    }

    split_h4<<<1024, 256>>>((const float4*)p_h, p_hsh, p_hsl, NT * DD / 4);
    gemm_bf3<<<gD, 256, GEMM_SMEM>>>(p_hsh, p_hsl, pw_hdh, pw_hdl,
        p_bhd, nullptr, p_ho, nullptr, nullptr, NT, DD, DD, 1);
    finish_heads<<<NT, 128>>>(p_ho, bhW2, bhb2, ahW2, ahb2, chW2, chb2, out);
}

// round 12
// speedup vs baseline: 1.0141x; 1.0141x over previous
#include <cuda_runtime.h>
#include <cuda_bf16.h>
#include <math.h>
#include <stdint.h>

#define NL   6
#define DD   512
#define NH   8
#define DKH  64
#define DFF  2048
#define WWIN 256
#define NB   4
#define TT   1024
#define NT   (NB * TT)

typedef __nv_bfloat16 bf16;
typedef __nv_bfloat162 bf162;

__device__ float g_h    [NT * DD];
__device__ bf16  g_hn_h [NT * DD];
__device__ bf16  g_hn_l [NT * DD];
__device__ bf16  g_qkv_h[NT * 3 * DD];
__device__ bf16  g_qkv_l[NT * 3 * DD];
__device__ bf16  g_o_h  [NT * DD];
__device__ bf16  g_o_l  [NT * DD];
__device__ bf16  g_ff_h [NT * DFF];
__device__ bf16  g_ff_l [NT * DFF];
__device__ bf16  g_hs_h [NT * DD];
__device__ bf16  g_hs_l [NT * DD];
__device__ float g_ho   [NT * DD];
__device__ int   g_pad  [NT];

__device__ bf16 w_qkv_h[NL * DD * 3 * DD];
__device__ bf16 w_qkv_l[NL * DD * 3 * DD];
__device__ bf16 w_wo_h [NL * DD * DD];
__device__ bf16 w_wo_l [NL * DD * DD];
__device__ bf16 w_w1_h [NL * DD * DFF];
__device__ bf16 w_w1_l [NL * DD * DFF];
__device__ bf16 w_w2_h [NL * DFF * DD];
__device__ bf16 w_w2_l [NL * DFF * DD];
__device__ bf16 w_hd_h [DD * DD];
__device__ bf16 w_hd_l [DD * DD];
__device__ float b_qkv [NL * 3 * DD];
__device__ float b_hd  [DD];

__device__ __forceinline__ float gelu_f(float x) {
    return 0.5f * x * (1.0f + erff(x * 0.7071067811865476f));
}
__device__ __forceinline__ void split2(float v, bf16& h, bf16& l) {
    h = __float2bfloat16(v);
    l = __float2bfloat16(v - __bfloat162float(h));
}
__device__ __forceinline__ void splitpack2(float x, float y, uint32_t& hi, uint32_t& lo) {
    bf162 H = __floats2bfloat162_rn(x, y);
    bf162 L = __floats2bfloat162_rn(x - __bfloat162float(H.x), y - __bfloat162float(H.y));
    hi = *reinterpret_cast<uint32_t*>(&H);
    lo = *reinterpret_cast<uint32_t*>(&L);
}
__device__ __forceinline__ float fexp(float x) {
    float y = fmaxf(x * 1.4426950408889634f, -126.0f);
    int i = __float2int_rn(y);
    float f = y - (float)i;
    float p = 1.5356298e-4f;
    p = fmaf(p, f, 1.3333558e-3f);
    p = fmaf(p, f, 9.6181291e-3f);
    p = fmaf(p, f, 5.5504109e-2f);
    p = fmaf(p, f, 2.4022651e-1f);
    p = fmaf(p, f, 6.9314718e-1f);
    p = fmaf(p, f, 1.0f);
    return p * __int_as_float((i + 127) << 23);
}
__device__ __forceinline__ void mma_bf16(float* c, const uint32_t* a, const uint32_t* b) {
    asm volatile(
        "mma.sync.aligned.m16n8k16.row.col.f32.bf16.bf16.f32 "
        "{%0,%1,%2,%3},{%4,%5,%6,%7},{%8,%9},{%0,%1,%2,%3};"
        : "+f"(c[0]), "+f"(c[1]), "+f"(c[2]), "+f"(c[3])
        : "r"(a[0]), "r"(a[1]), "r"(a[2]), "r"(a[3]), "r"(b[0]), "r"(b[1]));
}
__device__ __forceinline__ void ldm_x4(uint32_t& r0, uint32_t& r1, uint32_t& r2, uint32_t& r3, uint32_t a) {
    asm volatile("ldmatrix.sync.aligned.m8n8.x4.shared.b16 {%0,%1,%2,%3},[%4];"
                 : "=r"(r0), "=r"(r1), "=r"(r2), "=r"(r3) : "r"(a));
}
__device__ __forceinline__ void ldm_x4t(uint32_t& r0, uint32_t& r1, uint32_t& r2, uint32_t& r3, uint32_t a) {
    asm volatile("ldmatrix.sync.aligned.m8n8.x4.trans.shared.b16 {%0,%1,%2,%3},[%4];"
                 : "=r"(r0), "=r"(r1), "=r"(r2), "=r"(r3) : "r"(a));
}
#define CP_ASYNC16(dst, src) \
    asm volatile("cp.async.cg.shared.global [%0], [%1], 16;\n" :: "r"(dst), "l"(src))
#define CP_COMMIT() asm volatile("cp.async.commit_group;\n")
#define CP_WAIT(n)  asm volatile("cp.async.wait_group %0;\n" :: "n"(n))

__device__ __forceinline__ void split4store(float4 v, bf16* hi, bf16* lo) {
    bf162 h0 = __floats2bfloat162_rn(v.x, v.y);
    bf162 h1 = __floats2bfloat162_rn(v.z, v.w);
    bf162 l0 = __floats2bfloat162_rn(v.x - __bfloat162float(h0.x), v.y - __bfloat162float(h0.y));
    bf162 l1 = __floats2bfloat162_rn(v.z - __bfloat162float(h1.x), v.w - __bfloat162float(h1.y));
    uint2 H = {*(uint32_t*)&h0, *(uint32_t*)&h1};
    uint2 L = {*(uint32_t*)&l0, *(uint32_t*)&l1};
    *reinterpret_cast<uint2*>(hi) = H;
    *reinterpret_cast<uint2*>(lo) = L;
}

// ---------------- single merged prep kernel ----------------
#define N4_QKV (NL * DD * 3 * DD / 4)
#define N4_WO  (NL * DD * DD / 4)
#define N4_W1  (NL * DD * DFF / 4)
#define N4_W2  (NL * DFF * DD / 4)
#define N4_HD  (DD * DD / 4)
#define N4_TOT (N4_QKV + N4_WO + N4_W1 + N4_W2 + N4_HD)

__global__ void prep_all(const float* __restrict__ Wq, const float* __restrict__ Wk,
                         const float* __restrict__ Wv, const float* __restrict__ bq,
                         const float* __restrict__ bk, const float* __restrict__ bv,
                         const float* __restrict__ Wo, const float* __restrict__ W1,
                         const float* __restrict__ W2,
                         const float* __restrict__ bhW1, const float* __restrict__ bhb1,
                         const float* __restrict__ ahW1, const float* __restrict__ ahb1,
                         const float* __restrict__ chW1, const float* __restrict__ chb1)
{
    for (int i4 = blockIdx.x * blockDim.x + threadIdx.x; i4 < N4_TOT; i4 += gridDim.x * blockDim.x) {
        if (i4 < N4_QKV) {
            int idx = i4 * 4;
            int l = idx / (DD * 3 * DD);
            int r = idx % (DD * 3 * DD);
            int k = r / (3 * DD);
            int n = r % (3 * DD);
            const float* src;
            if (n < DD)           src = Wq + (size_t)l * DD * DD + k * DD + n;
            else if (n < 2 * DD)  src = Wk + (size_t)l * DD * DD + k * DD + (n - DD);
            else                  src = Wv + (size_t)l * DD * DD + k * DD + (n - 2 * DD);
            split4store(*reinterpret_cast<const float4*>(src), &w_qkv_h[idx], &w_qkv_l[idx]);
        } else if (i4 < N4_QKV + N4_WO) {
            int j = i4 - N4_QKV, idx = j * 4;
            split4store(reinterpret_cast<const float4*>(Wo)[j], &w_wo_h[idx], &w_wo_l[idx]);
        } else if (i4 < N4_QKV + N4_WO + N4_W1) {
            int j = i4 - N4_QKV - N4_WO, idx = j * 4;
            split4store(reinterpret_cast<const float4*>(W1)[j], &w_w1_h[idx], &w_w1_l[idx]);
        } else if (i4 < N4_QKV + N4_WO + N4_W1 + N4_W2) {
            int j = i4 - N4_QKV - N4_WO - N4_W1, idx = j * 4;
            split4store(reinterpret_cast<const float4*>(W2)[j], &w_w2_h[idx], &w_w2_l[idx]);
        } else {
            int j = i4 - (N4_QKV + N4_WO + N4_W1 + N4_W2);
            int idx = j * 4;
            int k = idx / DD, n = idx % DD;
            const float* src;
            if (n < 256)      src = bhW1 + k * 256 + n;
            else if (n < 384) src = ahW1 + k * 128 + (n - 256);
            else              src = chW1 + k * 128 + (n - 384);
            split4store(*reinterpret_cast<const float4*>(src), &w_hd_h[idx], &w_hd_l[idx]);
        }
    }
    for (int i = blockIdx.x * blockDim.x + threadIdx.x; i < NL * 3 * DD; i += gridDim.x * blockDim.x) {
        int l = i / (3 * DD), n = i % (3 * DD);
        b_qkv[i] = (n < DD) ? bq[l * DD + n] : (n < 2 * DD) ? bk[l * DD + n - DD] : bv[l * DD + n - 2 * DD];
    }
    for (int n = blockIdx.x * blockDim.x + threadIdx.x; n < DD; n += gridDim.x * blockDim.x)
        b_hd[n] = (n < 256) ? bhb1[n] : (n < 384) ? ahb1[n - 256] : chb1[n - 384];
}

__global__ void embed_kernel(const float* __restrict__ x, const float* __restrict__ pos,
                             const float* __restrict__ Wp, const float* __restrict__ bp)
{
    int token = blockIdx.x;
    int t = token % TT;
    float xv = x[token];
    if (threadIdx.x == 0) g_pad[token] = (xv == -1.0f) ? 1 : 0;
    for (int d = threadIdx.x; d < DD; d += blockDim.x)
        g_h[(size_t)token * DD + d] = xv * Wp[d] + bp[d] + pos[(size_t)t * DD + d];
}

__global__ void ln_kernel(const float* __restrict__ in, const float* __restrict__ gg,
                          const float* __restrict__ bb, bf16* __restrict__ outh,
                          bf16* __restrict__ outl)
{
    int token = blockIdx.x;
    int tid = threadIdx.x;
    const float* row = in + (size_t)token * DD;
    float v0 = row[tid];
    float v1 = row[tid + 256];
    __shared__ float red[8];
    __shared__ float stat[2];
    float s = v0 + v1;
    #pragma unroll
    for (int o = 16; o; o >>= 1) s += __shfl_down_sync(0xffffffffu, s, o);
    if ((tid & 31) == 0) red[tid >> 5] = s;
    __syncthreads();
    if (tid == 0) {
        float tt = 0.f;
        #pragma unroll
        for (int i = 0; i < 8; i++) tt += red[i];
        stat[0] = tt * (1.0f / DD);
    }
    __syncthreads();
    float mean = stat[0];
    float d0 = v0 - mean, d1 = v1 - mean;
    float q = d0 * d0 + d1 * d1;
    #pragma unroll
    for (int o = 16; o; o >>= 1) q += __shfl_down_sync(0xffffffffu, q, o);
    __syncthreads();
    if ((tid & 31) == 0) red[tid >> 5] = q;
    __syncthreads();
    if (tid == 0) {
        float tt = 0.f;
        #pragma unroll
        for (int i = 0; i < 8; i++) tt += red[i];
        stat[1] = rsqrtf(tt * (1.0f / DD) + 1e-5f);
    }
    __syncthreads();
    float inv = stat[1];
    float y0 = d0 * inv * gg[tid]       + bb[tid];
    float y1 = d1 * inv * gg[tid + 256] + bb[tid + 256];
    split2(y0, outh[(size_t)token * DD + tid],       outl[(size_t)token * DD + tid]);
    split2(y1, outh[(size_t)token * DD + tid + 256], outl[(size_t)token * DD + tid + 256]);
}

// ---------------- bf16x3 GEMM narrow (128x64, 2-stage, 3 CTA/SM) ----------
#define A_STR 40
#define B_STR 72
#define ASZ (128 * A_STR)
#define BSZ (32 * B_STR)
#define GEMM_SMEM ((4 * ASZ + 4 * BSZ) * 2)

__global__ void __launch_bounds__(256)
gemm_bf3(const bf16* __restrict__ Ah, const bf16* __restrict__ Al,
         const bf16* __restrict__ Wh, const bf16* __restrict__ Wl,
         const float* __restrict__ bias, const float* __restrict__ res,
         float* __restrict__ Cf, bf16* __restrict__ Chi, bf16* __restrict__ Clo,
         int M, int N, int K, int act)
{
    extern __shared__ bf16 smem[];
    const uint32_t smb = (uint32_t)__cvta_generic_to_shared(smem);
    const uint32_t oAl = 2 * ASZ * 2;
    const uint32_t oBh = 4 * ASZ * 2;
    const uint32_t oBl = oBh + 2 * BSZ * 2;

    const int tid  = threadIdx.x;
    const int bm   = blockIdx.y * 128;
    const int bn   = blockIdx.x * 64;
    const int warp = tid >> 5, lane = tid & 31;
    const int wm   = (warp & 3) * 32;
    const int wn   = (warp >> 2) * 32;
    const int group = lane >> 2, tig = lane & 3;
    const int matm = (lane >> 3) & 1;
    const int math = (lane >> 4) & 1;
    const int r7   = lane & 7;
    const uint32_t aLane = (uint32_t)((matm * 8 + r7) * (A_STR * 2) + math * 16);
    const uint32_t bLane = (uint32_t)((matm * 8 + r7) * (B_STR * 2) + math * 16);

    float acc[2][4][4] = {};
    const int nkb = K >> 5;

    auto loadA = [&](int kb, int st) {
        const uint32_t sb = smb + st * (ASZ * 2);
        #pragma unroll
        for (int i = 0; i < 2; i++) {
            int s = tid + i * 256;
            int row = s >> 2, c8 = (s & 3) * 8;
            uint32_t off = (uint32_t)((row * A_STR + c8) * 2);
            size_t gsrc = (size_t)(bm + row) * K + kb * 32 + c8;
            CP_ASYNC16(sb + off, Ah + gsrc);
            CP_ASYNC16(sb + oAl + off, Al + gsrc);
        }
    };
    auto loadB = [&](int kb, int st) {
        const uint32_t sb = smb + st * (BSZ * 2);
        int row = tid >> 3, c8 = (tid & 7) * 8;
        uint32_t off = (uint32_t)((row * B_STR + c8) * 2);
        size_t gsrc = (size_t)(kb * 32 + row) * N + bn + c8;
        CP_ASYNC16(sb + oBh + off, Wh + gsrc);
        CP_ASYNC16(sb + oBl + off, Wl + gsrc);
    };

    loadA(0, 0); loadB(0, 0); CP_COMMIT();

    for (int kb = 0; kb < nkb; kb++) {
        int cur = kb & 1;
        if (kb + 1 < nkb) {
            loadA(kb + 1, cur ^ 1); loadB(kb + 1, cur ^ 1);
            CP_COMMIT();
            CP_WAIT(1);
        } else {
            CP_WAIT(0);
        }
        __syncthreads();
        const uint32_t aBase = smb + cur * (ASZ * 2);
        const uint32_t bBase = smb + cur * (BSZ * 2) + oBh;
        #pragma unroll
        for (int ks = 0; ks < 2; ks++) {
            uint32_t ah[2][4], al[2][4], bh[4][2], bl[4][2];
            #pragma unroll
            for (int mt = 0; mt < 2; mt++) {
                uint32_t addr = aBase + (uint32_t)((wm + mt * 16) * (A_STR * 2) + ks * 32) + aLane;
                ldm_x4(ah[mt][0], ah[mt][1], ah[mt][2], ah[mt][3], addr);
                ldm_x4(al[mt][0], al[mt][1], al[mt][2], al[mt][3], addr + oAl);
            }
            #pragma unroll
            for (int p = 0; p < 2; p++) {
                uint32_t addr = bBase + (uint32_t)(ks * 16 * (B_STR * 2) + (wn + p * 16) * 2) + bLane;
                uint32_t t0, t1, t2, t3;
                ldm_x4t(t0, t1, t2, t3, addr);
                bh[2 * p][0] = t0; bh[2 * p][1] = t1; bh[2 * p + 1][0] = t2; bh[2 * p + 1][1] = t3;
                ldm_x4t(t0, t1, t2, t3, addr + (oBl - oBh));
                bl[2 * p][0] = t0; bl[2 * p][1] = t1; bl[2 * p + 1][0] = t2; bl[2 * p + 1][1] = t3;
            }
            #pragma unroll
            for (int mt = 0; mt < 2; mt++)
                #pragma unroll
                for (int nt = 0; nt < 4; nt++)
                    mma_bf16(acc[mt][nt], ah[mt], bh[nt]);
            #pragma unroll
            for (int mt = 0; mt < 2; mt++)
                #pragma unroll
                for (int nt = 0; nt < 4; nt++)
                    mma_bf16(acc[mt][nt], ah[mt], bl[nt]);
            #pragma unroll
            for (int mt = 0; mt < 2; mt++)
                #pragma unroll
                for (int nt = 0; nt < 4; nt++)
                    mma_bf16(acc[mt][nt], al[mt], bh[nt]);
        }
        __syncthreads();
    }

    #pragma unroll
    for (int mt = 0; mt < 2; mt++) {
        int r0 = bm + wm + mt * 16 + group;
        #pragma unroll
        for (int nt = 0; nt < 4; nt++) {
            int cc = bn + wn + nt * 8 + tig * 2;
            float b0 = bias[cc], b1 = bias[cc + 1];
            float v00 = acc[mt][nt][0] + b0;
            float v01 = acc[mt][nt][1] + b1;
            float v10 = acc[mt][nt][2] + b0;
            float v11 = acc[mt][nt][3] + b1;
            if (act) { v00 = gelu_f(v00); v01 = gelu_f(v01); v10 = gelu_f(v10); v11 = gelu_f(v11); }
            if (Chi) {
                uint32_t hh, ll;
                splitpack2(v00, v01, hh, ll);
                *reinterpret_cast<uint32_t*>(&Chi[(size_t)r0 * N + cc]) = hh;
                *reinterpret_cast<uint32_t*>(&Clo[(size_t)r0 * N + cc]) = ll;
                splitpack2(v10, v11, hh, ll);
                *reinterpret_cast<uint32_t*>(&Chi[(size_t)(r0 + 8) * N + cc]) = hh;
                *reinterpret_cast<uint32_t*>(&Clo[(size_t)(r0 + 8) * N + cc]) = ll;
            } else {
                if (res) {
                    v00 += res[(size_t)r0 * N + cc];       v01 += res[(size_t)r0 * N + cc + 1];
                    v10 += res[(size_t)(r0 + 8) * N + cc]; v11 += res[(size_t)(r0 + 8) * N + cc + 1];
                }
                Cf[(size_t)r0 * N + cc]           = v00;
                Cf[(size_t)r0 * N + cc + 1]       = v01;
                Cf[(size_t)(r0 + 8) * N + cc]     = v10;
                Cf[(size_t)(r0 + 8) * N + cc + 1] = v11;
            }
        }
    }
}

// ---------------- bf16x3 GEMM wide (128x128, 2-stage, 2 CTA/SM) --------------
#define BW_STR 136
#define BWSZ (32 * BW_STR)
#define GEMMW_SMEM ((4 * ASZ + 4 * BWSZ) * 2)   // 75776 B

__global__ void __launch_bounds__(256, 2)
gemm_bf3w(const bf16* __restrict__ Ah, const bf16* __restrict__ Al,
          const bf16* __restrict__ Wh, const bf16* __restrict__ Wl,
          const float* __restrict__ bias,
          bf16* __restrict__ Chi, bf16* __restrict__ Clo,
          int M, int N, int K, int act)
{
    extern __shared__ bf16 smem[];
    const uint32_t smb = (uint32_t)__cvta_generic_to_shared(smem);
    const uint32_t oAl = 2 * ASZ * 2;
    const uint32_t oBh = 4 * ASZ * 2;
    const uint32_t oBl = oBh + 2 * BWSZ * 2;

    const int tid  = threadIdx.x;
    const int bm   = blockIdx.y * 128;
    const int bn   = blockIdx.x * 128;
    const int warp = tid >> 5, lane = tid & 31;
    const int wm   = (warp & 3) * 32;
    const int wn   = (warp >> 2) * 64;
    const int group = lane >> 2, tig = lane & 3;
    const int matm = (lane >> 3) & 1;
    const int math = (lane >> 4) & 1;
    const int r7   = lane & 7;
    const uint32_t aLane = (uint32_t)((matm * 8 + r7) * (A_STR * 2) + math * 16);
    const uint32_t bLane = (uint32_t)((matm * 8 + r7) * (BW_STR * 2) + math * 16);

    float acc[2][8][4] = {};
    const int nkb = K >> 5;

    auto loadA = [&](int kb, int st) {
        const uint32_t sb = smb + st * (ASZ * 2);
        #pragma unroll
        for (int i = 0; i < 2; i++) {
            int s = tid + i * 256;
            int row = s >> 2, c8 = (s & 3) * 8;
            uint32_t off = (uint32_t)((row * A_STR + c8) * 2);
            size_t gsrc = (size_t)(bm + row) * K + kb * 32 + c8;
            CP_ASYNC16(sb + off, Ah + gsrc);
            CP_ASYNC16(sb + oAl + off, Al + gsrc);
        }
    };
    auto loadB = [&](int kb, int st) {
        const uint32_t sb = smb + st * (BWSZ * 2);
        #pragma unroll
        for (int i = 0; i < 2; i++) {
            int s = tid + i * 256;
            int row = s >> 4, c8 = (s & 15) * 8;
            uint32_t off = (uint32_t)((row * BW_STR + c8) * 2);
            size_t gsrc = (size_t)(kb * 32 + row) * N + bn + c8;
            CP_ASYNC16(sb + oBh + off, Wh + gsrc);
            CP_ASYNC16(sb + oBl + off, Wl + gsrc);
        }
    };

    loadA(0, 0); loadB(0, 0); CP_COMMIT();

    for (int kb = 0; kb < nkb; kb++) {
        int cur = kb & 1;
        if (kb + 1 < nkb) {
            loadA(kb + 1, cur ^ 1); loadB(kb + 1, cur ^ 1);
            CP_COMMIT();
            CP_WAIT(1);
        } else {
            CP_WAIT(0);
        }
        __syncthreads();
        const uint32_t aBase = smb + cur * (ASZ * 2);
        const uint32_t bBase = smb + cur * (BWSZ * 2) + oBh;
        #pragma unroll
        for (int ks = 0; ks < 2; ks++) {
            uint32_t ah[2][4], al[2][4], bh[8][2], bl[8][2];
            #pragma unroll
            for (int mt = 0; mt < 2; mt++) {
                uint32_t addr = aBase + (uint32_t)((wm + mt * 16) * (A_STR * 2) + ks * 32) + aLane;
                ldm_x4(ah[mt][0], ah[mt][1], ah[mt][2], ah[mt][3], addr);
                ldm_x4(al[mt][0], al[mt][1], al[mt][2], al[mt][3], addr + oAl);
            }
            #pragma unroll
            for (int p = 0; p < 4; p++) {
                uint32_t addr = bBase + (uint32_t)(ks * 16 * (BW_STR * 2) + (wn + p * 16) * 2) + bLane;
                uint32_t t0, t1, t2, t3;
                ldm_x4t(t0, t1, t2, t3, addr);
                bh[2 * p][0] = t0; bh[2 * p][1] = t1; bh[2 * p + 1][0] = t2; bh[2 * p + 1][1] = t3;
                ldm_x4t(t0, t1, t2, t3, addr + (oBl - oBh));
                bl[2 * p][0] = t0; bl[2 * p][1] = t1; bl[2 * p + 1][0] = t2; bl[2 * p + 1][1] = t3;
            }
            #pragma unroll
            for (int mt = 0; mt < 2; mt++)
                #pragma unroll
                for (int nt = 0; nt < 8; nt++)
                    mma_bf16(acc[mt][nt], ah[mt], bh[nt]);
            #pragma unroll
            for (int mt = 0; mt < 2; mt++)
                #pragma unroll
                for (int nt = 0; nt < 8; nt++)
                    mma_bf16(acc[mt][nt], ah[mt], bl[nt]);
            #pragma unroll
            for (int mt = 0; mt < 2; mt++)
                #pragma unroll
                for (int nt = 0; nt < 8; nt++)
                    mma_bf16(acc[mt][nt], al[mt], bh[nt]);
        }
        __syncthreads();
    }

    #pragma unroll
    for (int mt = 0; mt < 2; mt++) {
        int r0 = bm + wm + mt * 16 + group;
        #pragma unroll
        for (int nt = 0; nt < 8; nt++) {
            int cc = bn + wn + nt * 8 + tig * 2;
            float b0 = bias[cc], b1 = bias[cc + 1];
            float v00 = acc[mt][nt][0] + b0;
            float v01 = acc[mt][nt][1] + b1;
            float v10 = acc[mt][nt][2] + b0;
            float v11 = acc[mt][nt][3] + b1;
            if (act) { v00 = gelu_f(v00); v01 = gelu_f(v01); v10 = gelu_f(v10); v11 = gelu_f(v11); }
            uint32_t hh, ll;
            splitpack2(v00, v01, hh, ll);
            *reinterpret_cast<uint32_t*>(&Chi[(size_t)r0 * N + cc]) = hh;
            *reinterpret_cast<uint32_t*>(&Clo[(size_t)r0 * N + cc]) = ll;
            splitpack2(v10, v11, hh, ll);
            *reinterpret_cast<uint32_t*>(&Chi[(size_t)(r0 + 8) * N + cc]) = hh;
            *reinterpret_cast<uint32_t*>(&Clo[(size_t)(r0 + 8) * N + cc]) = ll;
        }
    }
}

// ---------------- tensor-core flash attention ----------------
#define AST 72
#define PLB (64 * AST * 2)
#define ATTN_SMEM (8 * PLB + 512)

__global__ void __launch_bounds__(128)
flash_attn_mma(const bf16* __restrict__ qkvh, const bf16* __restrict__ qkvl,
               const int* __restrict__ pad, bf16* __restrict__ ohi, bf16* __restrict__ olo)
{
    extern __shared__ char smraw[];
    const uint32_t smb = (uint32_t)__cvta_generic_to_shared(smraw);
    const uint32_t oQ = 0, oK = 2 * PLB, oV0 = 6 * PLB, oPS = 8 * PLB;

    const int tid  = threadIdx.x;
    const int lane = tid & 31;
    const int w    = tid >> 5;
    const int qt0  = blockIdx.x * 64;
    const int b    = blockIdx.y;
    const int h    = blockIdx.z;

    const int r7 = lane & 7;
    const int bA = (lane >> 3) & 1;
    const int bB = (lane >> 4) & 1;
    const int kRow = bB * 8 + r7;
    const int kCol = bA * 16;
    const int qg0 = qt0 + w * 16 + (lane >> 2);
    const int qg1 = qg0 + 8;

    #pragma unroll
    for (int i = 0; i < 4; i++) {
        int s = tid + i * 128;
        int r = s >> 3, c8 = (s & 7) * 8;
        size_t g = (size_t)(b * TT + qt0 + r) * (3 * DD) + h * DKH + c8;
        uint32_t d = smb + oQ + (uint32_t)((r * AST + c8) * 2);
        CP_ASYNC16(d, qkvh + g);
        CP_ASYNC16(d + PLB, qkvl + g);
    }
    CP_COMMIT();

    int c_start = 4 - (qt0 >> 6);
    if (c_start < 0) c_start = 0;

    auto issueK = [&](int c, int st) {
        int kc0 = qt0 - WWIN + 64 * c;
        #pragma unroll
        for (int i = 0; i < 4; i++) {
            int s = tid + i * 128;
            int r = s >> 3, c8 = (s & 7) * 8;
            size_t g = (size_t)(b * TT + kc0 + r) * (3 * DD) + DD + h * DKH + c8;
            uint32_t d = smb + oK + (uint32_t)(st * 2 * PLB) + (uint32_t)((r * AST + c8) * 2);
            CP_ASYNC16(d, qkvh + g);
            CP_ASYNC16(d + PLB, qkvl + g);
        }
        if (tid < 16)
            CP_ASYNC16(smb + oPS + (uint32_t)(st * 256 + tid * 16), pad + b * TT + kc0 + tid * 4);
    };
    auto issueV = [&](int c, int st) {
        int kc0 = qt0 - WWIN + 64 * c;
        uint32_t base = st ? (smb + oQ) : (smb + oV0);
        #pragma unroll
        for (int i = 0; i < 4; i++) {
            int s = tid + i * 128;
            int r = s >> 3, c8 = (s & 7) * 8;
            size_t g = (size_t)(b * TT + kc0 + r) * (3 * DD) + 2 * DD + h * DKH + c8;
            uint32_t d = base + (uint32_t)((r * AST + c8) * 2);
            CP_ASYNC16(d, qkvh + g);
            CP_ASYNC16(d + PLB, qkvl + g);
        }
    };

    issueK(c_start, 0); CP_COMMIT();
    issueV(c_start, 0); CP_COMMIT();

    CP_WAIT(2);
    __syncthreads();

    uint32_t qfh[4][4], qfl[4][4];
    #pragma unroll
    for (int ks = 0; ks < 4; ks++) {
        uint32_t ad = smb + oQ + (uint32_t)(((w * 16 + bA * 8 + r7) * AST) * 2 + ks * 32 + bB * 16);
        ldm_x4(qfh[ks][0], qfh[ks][1], qfh[ks][2], qfh[ks][3], ad);
        ldm_x4(qfl[ks][0], qfl[ks][1], qfl[ks][2], qfl[ks][3], ad + PLB);
    }

    float Oa[8][4];
    #pragma unroll
    for (int i = 0; i < 8; i++)
        #pragma unroll
        for (int j = 0; j < 4; j++) Oa[i][j] = 0.f;
    float mold[2] = {-1e30f, -1e30f};
    float lrun[2] = {0.f, 0.f};

    int stage = 0;
    for (int c = c_start; c < 5; c++) {
        const int kc0 = qt0 - WWIN + 64 * c;
        CP_WAIT(1);
        __syncthreads();

        float s4[8][4];
        #pragma unroll
        for (int i = 0; i < 8; i++)
            #pragma unroll
            for (int j = 0; j < 4; j++) s4[i][j] = 0.f;
        const uint32_t kb0 = smb + oK + (uint32_t)(stage * 2 * PLB);
        #pragma unroll
        for (int ks = 0; ks < 4; ks++) {
            uint32_t kh[8][2], kl[8][2];
            #pragma unroll
            for (int p = 0; p < 4; p++) {
                uint32_t ad = kb0 + (uint32_t)(((p * 16 + kRow) * AST) * 2 + ks * 32 + kCol);
                ldm_x4(kh[2 * p][0], kh[2 * p][1], kh[2 * p + 1][0], kh[2 * p + 1][1], ad);
                ldm_x4(kl[2 * p][0], kl[2 * p][1], kl[2 * p + 1][0], kl[2 * p + 1][1], ad + PLB);
            }
            #pragma unroll
            for (int nt = 0; nt < 8; nt++) mma_bf16(s4[nt], qfh[ks], kh[nt]);
            #pragma unroll
            for (int nt = 0; nt < 8; nt++) mma_bf16(s4[nt], qfh[ks], kl[nt]);
            #pragma unroll
            for (int nt = 0; nt < 8; nt++) mma_bf16(s4[nt], qfl[ks], kh[nt]);
        }

        if (c < 4) { issueK(c + 1, stage ^ 1); CP_COMMIT(); }

        const int* psS = (const int*)(smraw + oPS + stage * 256);
        const int jb = 2 * (lane & 3);
        #pragma unroll
        for (int nt = 0; nt < 8; nt++) {
            int jj = nt * 8 + jb;
            int j  = kc0 + jj;
            int pd0 = psS[jj], pd1 = psS[jj + 1];
            bool v00 = (j     <= qg0) && (j     >= qg0 - (WWIN - 1)) && !pd0;
            bool v01 = (j + 1 <= qg0) && (j + 1 >= qg0 - (WWIN - 1)) && !pd1;
            bool v10 = (j     <= qg1) && (j     >= qg1 - (WWIN - 1)) && !pd0;
            bool v11 = (j + 1 <= qg1) && (j + 1 >= qg1 - (WWIN - 1)) && !pd1;
            s4[nt][0] = v00 ? s4[nt][0] * 0.125f : -1e30f;
            s4[nt][1] = v01 ? s4[nt][1] * 0.125f : -1e30f;
            s4[nt][2] = v10 ? s4[nt][2] * 0.125f : -1e30f;
            s4[nt][3] = v11 ? s4[nt][3] * 0.125f : -1e30f;
        }

        float mc0 = -1e30f, mc1 = -1e30f;
        #pragma unroll
        for (int nt = 0; nt < 8; nt++) {
            mc0 = fmaxf(mc0, fmaxf(s4[nt][0], s4[nt][1]));
            mc1 = fmaxf(mc1, fmaxf(s4[nt][2], s4[nt][3]));
        }
        mc0 = fmaxf(mc0, __shfl_xor_sync(0xffffffffu, mc0, 1));
        mc0 = fmaxf(mc0, __shfl_xor_sync(0xffffffffu, mc0, 2));
        mc1 = fmaxf(mc1, __shfl_xor_sync(0xffffffffu, mc1, 1));
        mc1 = fmaxf(mc1, __shfl_xor_sync(0xffffffffu, mc1, 2));
        float mn0 = fmaxf(mold[0], mc0);
        float mn1 = fmaxf(mold[1], mc1);
        float al0 = fexp(mold[0] - mn0);
        float al1 = fexp(mold[1] - mn1);
        mold[0] = mn0; mold[1] = mn1;
        float ps0 = 0.f, ps1 = 0.f;
        #pragma unroll
        for (int nt = 0; nt < 8; nt++) {
            float p0 = (s4[nt][0] <= -1e29f) ? 0.f : fexp(s4[nt][0] - mn0);
            float p1 = (s4[nt][1] <= -1e29f) ? 0.f : fexp(s4[nt][1] - mn0);
            float p2 = (s4[nt][2] <= -1e29f) ? 0.f : fexp(s4[nt][2] - mn1);
            float p3 = (s4[nt][3] <= -1e29f) ? 0.f : fexp(s4[nt][3] - mn1);
            s4[nt][0] = p0; s4[nt][1] = p1; s4[nt][2] = p2; s4[nt][3] = p3;
            ps0 += p0 + p1; ps1 += p2 + p3;
        }
        ps0 += __shfl_xor_sync(0xffffffffu, ps0, 1);
        ps0 += __shfl_xor_sync(0xffffffffu, ps0, 2);
        ps1 += __shfl_xor_sync(0xffffffffu, ps1, 1);
        ps1 += __shfl_xor_sync(0xffffffffu, ps1, 2);
        lrun[0] = lrun[0] * al0 + ps0;
        lrun[1] = lrun[1] * al1 + ps1;

        #pragma unroll
        for (int nt = 0; nt < 8; nt++) {
            Oa[nt][0] *= al0; Oa[nt][1] *= al0;
            Oa[nt][2] *= al1; Oa[nt][3] *= al1;
        }

        uint32_t aPh[4][4], aPl[4][4];
        #pragma unroll
        for (int t = 0; t < 4; t++) {
            splitpack2(s4[2 * t][0],     s4[2 * t][1],     aPh[t][0], aPl[t][0]);
            splitpack2(s4[2 * t][2],     s4[2 * t][3],     aPh[t][1], aPl[t][1]);
            splitpack2(s4[2 * t + 1][0], s4[2 * t + 1][1], aPh[t][2], aPl[t][2]);
            splitpack2(s4[2 * t + 1][2], s4[2 * t + 1][3], aPh[t][3], aPl[t][3]);
        }

        if (c < 4) { CP_WAIT(1); } else { CP_WAIT(0); }
        __syncthreads();
        if (c < 4) { issueV(c + 1, stage ^ 1); CP_COMMIT(); }

        const uint32_t vb0 = stage ? (smb + oQ) : (smb + oV0);
        #pragma unroll
        for (int t = 0; t < 4; t++) {
            uint32_t vh[8][2], vl[8][2];
            #pragma unroll
            for (int p = 0; p < 4; p++) {
                uint32_t ad = vb0 + (uint32_t)(((t * 16 + bA * 8 + r7) * AST) * 2 + p * 32 + bB * 16);
                uint32_t t0, t1, t2, t3;
                ldm_x4t(t0, t1, t2, t3, ad);
                vh[2 * p][0] = t0; vh[2 * p][1] = t1; vh[2 * p + 1][0] = t2; vh[2 * p + 1][1] = t3;
                ldm_x4t(t0, t1, t2, t3, ad + PLB);
                vl[2 * p][0] = t0; vl[2 * p][1] = t1; vl[2 * p + 1][0] = t2; vl[2 * p + 1][1] = t3;
            }
            #pragma unroll
            for (int nt = 0; nt < 8; nt++) mma_bf16(Oa[nt], aPh[t], vh[nt]);
            #pragma unroll
            for (int nt = 0; nt < 8; nt++) mma_bf16(Oa[nt], aPh[t], vl[nt]);
            #pragma unroll
            for (int nt = 0; nt < 8; nt++) mma_bf16(Oa[nt], aPl[t], vh[nt]);
        }
        stage ^= 1;
    }

    float inv0 = (lrun[0] > 0.f) ? 1.0f / lrun[0] : 0.f;
    float inv1 = (lrun[1] > 0.f) ? 1.0f / lrun[1] : 0.f;
    int tok0 = b * TT + qt0 + w * 16 + (lane >> 2);
    #pragma unroll
    for (int nt = 0; nt < 8; nt++) {
        int col = h * DKH + nt * 8 + 2 * (lane & 3);
        uint32_t hi, lo;
        splitpack2(Oa[nt][0] * inv0, Oa[nt][1] * inv0, hi, lo);
        *reinterpret_cast<uint32_t*>(&ohi[(size_t)tok0 * DD + col]) = hi;
        *reinterpret_cast<uint32_t*>(&olo[(size_t)tok0 * DD + col]) = lo;
        splitpack2(Oa[nt][2] * inv1, Oa[nt][3] * inv1, hi, lo);
        *reinterpret_cast<uint32_t*>(&ohi[(size_t)(tok0 + 8) * DD + col]) = hi;
        *reinterpret_cast<uint32_t*>(&olo[(size_t)(tok0 + 8) * DD + col]) = lo;
    }
}

__global__ void split_h4(const float4* __restrict__ src, bf16* __restrict__ hi,
                         bf16* __restrict__ lo, int n4)
{
    for (int i = blockIdx.x * blockDim.x + threadIdx.x; i < n4; i += gridDim.x * blockDim.x)
        split4store(src[i], hi + i * 4, lo + i * 4);
}

__global__ void finish_heads(const float* __restrict__ ho,
                             const float* __restrict__ bhW2, const float* __restrict__ bhb2,
                             const float* __restrict__ ahW2, const float* __restrict__ ahb2,
                             const float* __restrict__ chW2, const float* __restrict__ chb2,
                             float* __restrict__ out)
{
    int token = blockIdx.x;
    int tid = threadIdx.x;
    __shared__ float red[128];
    const float* row = ho + (size_t)token * DD;

    float t0 = row[tid] * bhW2[tid * 2]     + row[tid + 128] * bhW2[(tid + 128) * 2];
    float t1 = row[tid] * bhW2[tid * 2 + 1] + row[tid + 128] * bhW2[(tid + 128) * 2 + 1];
    red[tid] = t0; __syncthreads();
    for (int s = 64; s > 0; s >>= 1) { if (tid < s) red[tid] += red[tid + s]; __syncthreads(); }
    float s0 = red[0]; __syncthreads();
    red[tid] = t1; __syncthreads();
    for (int s = 64; s > 0; s >>= 1) { if (tid < s) red[tid] += red[tid + s]; __syncthreads(); }
    float s1 = red[0]; __syncthreads();
    red[tid] = row[256 + tid] * ahW2[tid]; __syncthreads();
    for (int s = 64; s > 0; s >>= 1) { if (tid < s) red[tid] += red[tid + s]; __syncthreads(); }
    float sa = red[0]; __syncthreads();
    red[tid] = row[384 + tid] * chW2[tid]; __syncthreads();
    for (int s = 64; s > 0; s >>= 1) { if (tid < s) red[tid] += red[tid + s]; __syncthreads(); }
    float sc = red[0];

    if (tid == 0) {
        out[token * 2 + 0] = s0 + bhb2[0];
        out[token * 2 + 1] = s1 + bhb2[1];
        out[2 * NT + token] = sa + ahb2[0];
        out[3 * NT + token] = 1.0f / (1.0f + expf(-(sc + chb2[0])));
    }
}

#define SYM(p, s) cudaGetSymbolAddress((void**)&p, s)

extern "C" void kernel_launch(void* const* d_in, const int* in_sizes, int n_in,
                              void* d_out, int out_size)
{
    const float* x    = (const float*)d_in[0];
    const float* pos  = (const float*)d_in[1];
    const float* Wp   = (const float*)d_in[2];
    const float* bp   = (const float*)d_in[3];
    const float* Wq   = (const float*)d_in[4];
    const float* bq   = (const float*)d_in[5];
    const float* Wk   = (const float*)d_in[6];
    const float* bk   = (const float*)d_in[7];
    const float* Wv   = (const float*)d_in[8];
    const float* bv   = (const float*)d_in[9];
    const float* Wo   = (const float*)d_in[10];
    const float* bo   = (const float*)d_in[11];
    const float* ln1g = (const float*)d_in[12];
    const float* ln1b = (const float*)d_in[13];
    const float* W1   = (const float*)d_in[14];
    const float* b1   = (const float*)d_in[15];
    const float* W2   = (const float*)d_in[16];
    const float* b2   = (const float*)d_in[17];
    const float* ln2g = (const float*)d_in[18];
    const float* ln2b = (const float*)d_in[19];
    const float* bhW1 = (const float*)d_in[20];
    const float* bhb1 = (const float*)d_in[21];
    const float* bhW2 = (const float*)d_in[22];
    const float* bhb2 = (const float*)d_in[23];
    const float* ahW1 = (const float*)d_in[24];
    const float* ahb1 = (const float*)d_in[25];
    const float* ahW2 = (const float*)d_in[26];
    const float* ahb2 = (const float*)d_in[27];
    const float* chW1 = (const float*)d_in[28];
    const float* chb1 = (const float*)d_in[29];
    const float* chW2 = (const float*)d_in[30];
    const float* chb2 = (const float*)d_in[31];
    float* out = (float*)d_out;

    float *p_h, *p_ho, *p_bqkv, *p_bhd;
    bf16 *p_hnh, *p_hnl, *p_qkvh, *p_qkvl, *p_oh, *p_ol, *p_ffh, *p_ffl, *p_hsh, *p_hsl;
    bf16 *pw_qkvh, *pw_qkvl, *pw_woh, *pw_wol, *pw_w1h, *pw_w1l, *pw_w2h, *pw_w2l, *pw_hdh, *pw_hdl;
    int* p_pad;
    SYM(p_h, g_h);       SYM(p_hnh, g_hn_h);   SYM(p_hnl, g_hn_l);
    SYM(p_qkvh, g_qkv_h); SYM(p_qkvl, g_qkv_l);
    SYM(p_oh, g_o_h);    SYM(p_ol, g_o_l);
    SYM(p_ffh, g_ff_h);  SYM(p_ffl, g_ff_l);
    SYM(p_hsh, g_hs_h);  SYM(p_hsl, g_hs_l);
    SYM(p_ho, g_ho);     SYM(p_pad, g_pad);
    SYM(pw_qkvh, w_qkv_h); SYM(pw_qkvl, w_qkv_l);
    SYM(pw_woh, w_wo_h); SYM(pw_wol, w_wo_l);
    SYM(pw_w1h, w_w1_h); SYM(pw_w1l, w_w1_l);
    SYM(pw_w2h, w_w2_h); SYM(pw_w2l, w_w2_l);
    SYM(pw_hdh, w_hd_h); SYM(pw_hdl, w_hd_l);
    SYM(p_bqkv, b_qkv);  SYM(p_bhd, b_hd);

    cudaFuncSetAttribute(gemm_bf3, cudaFuncAttributeMaxDynamicSharedMemorySize, GEMM_SMEM);
    cudaFuncSetAttribute(gemm_bf3w, cudaFuncAttributeMaxDynamicSharedMemorySize, GEMMW_SMEM);
    cudaFuncSetAttribute(flash_attn_mma, cudaFuncAttributeMaxDynamicSharedMemorySize, ATTN_SMEM);

    prep_all<<<4096, 256>>>(Wq, Wk, Wv, bq, bk, bv, Wo, W1, W2,
                            bhW1, bhb1, ahW1, ahb1, chW1, chb1);
    embed_kernel<<<NT, 128>>>(x, pos, Wp, bp);

    dim3 gQKVw(3 * DD / 128, NT / 128);  // (12, 32) wide
    dim3 gFFw (DFF / 128,    NT / 128);  // (16, 32) wide
    dim3 gD   (DD / 64,      NT / 128);  // (8, 32)  narrow
    dim3 gAtt(TT / 64, NB, NH);

    for (int l = 0; l < NL; l++) {
        ln_kernel<<<NT, 256>>>(p_h, ln1g + l * DD, ln1b + l * DD, p_hnh, p_hnl);
        gemm_bf3w<<<gQKVw, 256, GEMMW_SMEM>>>(p_hnh, p_hnl,
            pw_qkvh + (size_t)l * DD * 3 * DD, pw_qkvl + (size_t)l * DD * 3 * DD,
            p_bqkv + l * 3 * DD, p_qkvh, p_qkvl, NT, 3 * DD, DD, 0);
        flash_attn_mma<<<gAtt, 128, ATTN_SMEM>>>(p_qkvh, p_qkvl, p_pad, p_oh, p_ol);
        gemm_bf3<<<gD, 256, GEMM_SMEM>>>(p_oh, p_ol,
            pw_woh + (size_t)l * DD * DD, pw_wol + (size_t)l * DD * DD,
            bo + l * DD, p_h, p_h, nullptr, nullptr, NT, DD, DD, 0);
        ln_kernel<<<NT, 256>>>(p_h, ln2g + l * DD, ln2b + l * DD, p_hnh, p_hnl);
        gemm_bf3w<<<gFFw, 256, GEMMW_SMEM>>>(p_hnh, p_hnl,
            pw_w1h + (size_t)l * DD * DFF, pw_w1l + (size_t)l * DD * DFF,
            b1 + l * DFF, p_ffh, p_ffl, NT, DFF, DD, 1);
        gemm_bf3<<<gD, 256, GEMM_SMEM>>>(p_ffh, p_ffl,
            pw_w2h + (size_t)l * DFF * DD, pw_w2l + (size_t)l * DFF * DD,
            b2 + l * DD, p_h, p_h, nullptr, nullptr, NT, DD, DFF, 0);
    }

    split_h4<<<1024, 256>>>((const float4*)p_h, p_hsh, p_hsl, NT * DD / 4);
    gemm_bf3<<<gD, 256, GEMM_SMEM>>>(p_hsh, p_hsl, pw_hdh, pw_hdl,
        p_bhd, nullptr, p_ho, nullptr, nullptr, NT, DD, DD, 1);
    finish_heads<<<NT, 128>>>(p_ho, bhW2, bhb2, ahW2, ahb2, chW2, chb2, out);
}

// round 13
// speedup vs baseline: 1.0306x; 1.0162x over previous
#include <cuda_runtime.h>
#include <cuda_bf16.h>
#include <math.h>
#include <stdint.h>

#define NL   6
#define DD   512
#define NH   8
#define DKH  64
#define DFF  2048
#define WWIN 256
#define NB   4
#define TT   1024
#define NT   (NB * TT)

typedef __nv_bfloat16 bf16;
typedef __nv_bfloat162 bf162;

__device__ float g_h    [NT * DD];
__device__ float g_p    [2 * NT * DD];   // splitK partials
__device__ bf16  g_hn_h [NT * DD];
__device__ bf16  g_hn_l [NT * DD];
__device__ bf16  g_qkv_h[NT * 3 * DD];
__device__ bf16  g_qkv_l[NT * 3 * DD];
__device__ bf16  g_o_h  [NT * DD];
__device__ bf16  g_o_l  [NT * DD];
__device__ bf16  g_ff_h [NT * DFF];
__device__ bf16  g_ff_l [NT * DFF];
__device__ bf16  g_hs_h [NT * DD];
__device__ bf16  g_hs_l [NT * DD];
__device__ float g_ho   [NT * DD];
__device__ int   g_pad  [NT];

__device__ bf16 w_qkv_h[NL * DD * 3 * DD];
__device__ bf16 w_qkv_l[NL * DD * 3 * DD];
__device__ bf16 w_wo_h [NL * DD * DD];
__device__ bf16 w_wo_l [NL * DD * DD];
__device__ bf16 w_w1_h [NL * DD * DFF];
__device__ bf16 w_w1_l [NL * DD * DFF];
__device__ bf16 w_w2_h [NL * DFF * DD];
__device__ bf16 w_w2_l [NL * DFF * DD];
__device__ bf16 w_hd_h [DD * DD];
__device__ bf16 w_hd_l [DD * DD];
__device__ float b_qkv [NL * 3 * DD];
__device__ float b_hd  [DD];

__device__ __forceinline__ float gelu_f(float x) {
    return 0.5f * x * (1.0f + erff(x * 0.7071067811865476f));
}
__device__ __forceinline__ void split2(float v, bf16& h, bf16& l) {
    h = __float2bfloat16(v);
    l = __float2bfloat16(v - __bfloat162float(h));
}
__device__ __forceinline__ void splitpack2(float x, float y, uint32_t& hi, uint32_t& lo) {
    bf162 H = __floats2bfloat162_rn(x, y);
    bf162 L = __floats2bfloat162_rn(x - __bfloat162float(H.x), y - __bfloat162float(H.y));
    hi = *reinterpret_cast<uint32_t*>(&H);
    lo = *reinterpret_cast<uint32_t*>(&L);
}
__device__ __forceinline__ float fexp(float x) {
    float y = fmaxf(x * 1.4426950408889634f, -126.0f);
    int i = __float2int_rn(y);
    float f = y - (float)i;
    float p = 1.5356298e-4f;
    p = fmaf(p, f, 1.3333558e-3f);
    p = fmaf(p, f, 9.6181291e-3f);
    p = fmaf(p, f, 5.5504109e-2f);
    p = fmaf(p, f, 2.4022651e-1f);
    p = fmaf(p, f, 6.9314718e-1f);
    p = fmaf(p, f, 1.0f);
    return p * __int_as_float((i + 127) << 23);
}
__device__ __forceinline__ void mma_bf16(float* c, const uint32_t* a, const uint32_t* b) {
    asm volatile(
        "mma.sync.aligned.m16n8k16.row.col.f32.bf16.bf16.f32 "
        "{%0,%1,%2,%3},{%4,%5,%6,%7},{%8,%9},{%0,%1,%2,%3};"
        : "+f"(c[0]), "+f"(c[1]), "+f"(c[2]), "+f"(c[3])
        : "r"(a[0]), "r"(a[1]), "r"(a[2]), "r"(a[3]), "r"(b[0]), "r"(b[1]));
}
__device__ __forceinline__ void ldm_x4(uint32_t& r0, uint32_t& r1, uint32_t& r2, uint32_t& r3, uint32_t a) {
    asm volatile("ldmatrix.sync.aligned.m8n8.x4.shared.b16 {%0,%1,%2,%3},[%4];"
                 : "=r"(r0), "=r"(r1), "=r"(r2), "=r"(r3) : "r"(a));
}
__device__ __forceinline__ void ldm_x4t(uint32_t& r0, uint32_t& r1, uint32_t& r2, uint32_t& r3, uint32_t a) {
    asm volatile("ldmatrix.sync.aligned.m8n8.x4.trans.shared.b16 {%0,%1,%2,%3},[%4];"
                 : "=r"(r0), "=r"(r1), "=r"(r2), "=r"(r3) : "r"(a));
}
#define CP_ASYNC16(dst, src) \
    asm volatile("cp.async.cg.shared.global [%0], [%1], 16;\n" :: "r"(dst), "l"(src))
#define CP_COMMIT() asm volatile("cp.async.commit_group;\n")
#define CP_WAIT(n)  asm volatile("cp.async.wait_group %0;\n" :: "n"(n))

__device__ __forceinline__ void split4store(float4 v, bf16* hi, bf16* lo) {
    bf162 h0 = __floats2bfloat162_rn(v.x, v.y);
    bf162 h1 = __floats2bfloat162_rn(v.z, v.w);
    bf162 l0 = __floats2bfloat162_rn(v.x - __bfloat162float(h0.x), v.y - __bfloat162float(h0.y));
    bf162 l1 = __floats2bfloat162_rn(v.z - __bfloat162float(h1.x), v.w - __bfloat162float(h1.y));
    uint2 H = {*(uint32_t*)&h0, *(uint32_t*)&h1};
    uint2 L = {*(uint32_t*)&l0, *(uint32_t*)&l1};
    *reinterpret_cast<uint2*>(hi) = H;
    *reinterpret_cast<uint2*>(lo) = L;
}

// ---------------- merged prep ----------------
#define N4_QKV (NL * DD * 3 * DD / 4)
#define N4_WO  (NL * DD * DD / 4)
#define N4_W1  (NL * DD * DFF / 4)
#define N4_W2  (NL * DFF * DD / 4)
#define N4_HD  (DD * DD / 4)
#define N4_TOT (N4_QKV + N4_WO + N4_W1 + N4_W2 + N4_HD)

__global__ void prep_all(const float* __restrict__ Wq, const float* __restrict__ Wk,
                         const float* __restrict__ Wv, const float* __restrict__ bq,
                         const float* __restrict__ bk, const float* __restrict__ bv,
                         const float* __restrict__ Wo, const float* __restrict__ W1,
                         const float* __restrict__ W2,
                         const float* __restrict__ bhW1, const float* __restrict__ bhb1,
                         const float* __restrict__ ahW1, const float* __restrict__ ahb1,
                         const float* __restrict__ chW1, const float* __restrict__ chb1)
{
    for (int i4 = blockIdx.x * blockDim.x + threadIdx.x; i4 < N4_TOT; i4 += gridDim.x * blockDim.x) {
        if (i4 < N4_QKV) {
            int idx = i4 * 4;
            int l = idx / (DD * 3 * DD);
            int r = idx % (DD * 3 * DD);
            int k = r / (3 * DD);
            int n = r % (3 * DD);
            const float* src;
            if (n < DD)           src = Wq + (size_t)l * DD * DD + k * DD + n;
            else if (n < 2 * DD)  src = Wk + (size_t)l * DD * DD + k * DD + (n - DD);
            else                  src = Wv + (size_t)l * DD * DD + k * DD + (n - 2 * DD);
            split4store(*reinterpret_cast<const float4*>(src), &w_qkv_h[idx], &w_qkv_l[idx]);
        } else if (i4 < N4_QKV + N4_WO) {
            int j = i4 - N4_QKV, idx = j * 4;
            split4store(reinterpret_cast<const float4*>(Wo)[j], &w_wo_h[idx], &w_wo_l[idx]);
        } else if (i4 < N4_QKV + N4_WO + N4_W1) {
            int j = i4 - N4_QKV - N4_WO, idx = j * 4;
            split4store(reinterpret_cast<const float4*>(W1)[j], &w_w1_h[idx], &w_w1_l[idx]);
        } else if (i4 < N4_QKV + N4_WO + N4_W1 + N4_W2) {
            int j = i4 - N4_QKV - N4_WO - N4_W1, idx = j * 4;
            split4store(reinterpret_cast<const float4*>(W2)[j], &w_w2_h[idx], &w_w2_l[idx]);
        } else {
            int j = i4 - (N4_QKV + N4_WO + N4_W1 + N4_W2);
            int idx = j * 4;
            int k = idx / DD, n = idx % DD;
            const float* src;
            if (n < 256)      src = bhW1 + k * 256 + n;
            else if (n < 384) src = ahW1 + k * 128 + (n - 256);
            else              src = chW1 + k * 128 + (n - 384);
            split4store(*reinterpret_cast<const float4*>(src), &w_hd_h[idx], &w_hd_l[idx]);
        }
    }
    for (int i = blockIdx.x * blockDim.x + threadIdx.x; i < NL * 3 * DD; i += gridDim.x * blockDim.x) {
        int l = i / (3 * DD), n = i % (3 * DD);
        b_qkv[i] = (n < DD) ? bq[l * DD + n] : (n < 2 * DD) ? bk[l * DD + n - DD] : bv[l * DD + n - 2 * DD];
    }
    for (int n = blockIdx.x * blockDim.x + threadIdx.x; n < DD; n += gridDim.x * blockDim.x)
        b_hd[n] = (n < 256) ? bhb1[n] : (n < 384) ? ahb1[n - 256] : chb1[n - 384];
}

__global__ void embed_kernel(const float* __restrict__ x, const float* __restrict__ pos,
                             const float* __restrict__ Wp, const float* __restrict__ bp)
{
    int token = blockIdx.x;
    int t = token % TT;
    float xv = x[token];
    if (threadIdx.x == 0) g_pad[token] = (xv == -1.0f) ? 1 : 0;
    for (int d = threadIdx.x; d < DD; d += blockDim.x)
        g_h[(size_t)token * DD + d] = xv * Wp[d] + bp[d] + pos[(size_t)t * DD + d];
}

// ---------------- LN core (shared by plain & combine) ----------------
__device__ __forceinline__ void ln_core(int token, int tid, float v0, float v1,
                                        const float* gg, const float* bb,
                                        bf16* outh, bf16* outl)
{
    __shared__ float red[8];
    __shared__ float stat[2];
    float s = v0 + v1;
    #pragma unroll
    for (int o = 16; o; o >>= 1) s += __shfl_down_sync(0xffffffffu, s, o);
    if ((tid & 31) == 0) red[tid >> 5] = s;
    __syncthreads();
    if (tid == 0) {
        float tt = 0.f;
        #pragma unroll
        for (int i = 0; i < 8; i++) tt += red[i];
        stat[0] = tt * (1.0f / DD);
    }
    __syncthreads();
    float mean = stat[0];
    float d0 = v0 - mean, d1 = v1 - mean;
    float q = d0 * d0 + d1 * d1;
    #pragma unroll
    for (int o = 16; o; o >>= 1) q += __shfl_down_sync(0xffffffffu, q, o);
    __syncthreads();
    if ((tid & 31) == 0) red[tid >> 5] = q;
    __syncthreads();
    if (tid == 0) {
        float tt = 0.f;
        #pragma unroll
        for (int i = 0; i < 8; i++) tt += red[i];
        stat[1] = rsqrtf(tt * (1.0f / DD) + 1e-5f);
    }
    __syncthreads();
    float inv = stat[1];
    float y0 = d0 * inv * gg[tid]       + bb[tid];
    float y1 = d1 * inv * gg[tid + 256] + bb[tid + 256];
    split2(y0, outh[(size_t)token * DD + tid],       outl[(size_t)token * DD + tid]);
    split2(y1, outh[(size_t)token * DD + tid + 256], outl[(size_t)token * DD + tid + 256]);
}

__global__ void ln_kernel(const float* __restrict__ in, const float* __restrict__ gg,
                          const float* __restrict__ bb, bf16* __restrict__ outh,
                          bf16* __restrict__ outl)
{
    int token = blockIdx.x;
    int tid = threadIdx.x;
    size_t i0 = (size_t)token * DD + tid;
    ln_core(token, tid, in[i0], in[i0 + 256], gg, bb, outh, outl);
}

// h = h + p0 + p1, then LN(h) -> planes; writes updated h
__global__ void ln_comb(float* __restrict__ h, const float* __restrict__ p,
                        const float* __restrict__ gg, const float* __restrict__ bb,
                        bf16* __restrict__ outh, bf16* __restrict__ outl)
{
    int token = blockIdx.x;
    int tid = threadIdx.x;
    size_t i0 = (size_t)token * DD + tid, i1 = i0 + 256;
    const size_t PO = (size_t)NT * DD;
    float v0 = h[i0] + p[i0] + p[PO + i0];
    float v1 = h[i1] + p[i1] + p[PO + i1];
    h[i0] = v0; h[i1] = v1;
    ln_core(token, tid, v0, v1, gg, bb, outh, outl);
}

// h += p0+p1 then split (for heads input); h not written back (not needed after)
__global__ void comb_split(const float4* __restrict__ h, const float4* __restrict__ p,
                           bf16* __restrict__ hi, bf16* __restrict__ lo, int n4)
{
    for (int i = blockIdx.x * blockDim.x + threadIdx.x; i < n4; i += gridDim.x * blockDim.x) {
        float4 a = h[i], b0 = p[i], b1 = p[n4 + i];
        float4 v = make_float4(a.x + b0.x + b1.x, a.y + b0.y + b1.y,
                               a.z + b0.z + b1.z, a.w + b0.w + b1.w);
        split4store(v, hi + i * 4, lo + i * 4);
    }
}

// ---------------- bf16x3 GEMM narrow (128x64, 2-stage, single-barrier) -------
#define A_STR 40
#define B_STR 72
#define ASZ (128 * A_STR)
#define BSZ (32 * B_STR)
#define GEMM_SMEM ((4 * ASZ + 4 * BSZ) * 2)

__global__ void __launch_bounds__(256)
gemm_bf3(const bf16* __restrict__ Ah, const bf16* __restrict__ Al,
         const bf16* __restrict__ Wh, const bf16* __restrict__ Wl,
         const float* __restrict__ bias, const float* __restrict__ res,
         float* __restrict__ Cf, bf16* __restrict__ Chi, bf16* __restrict__ Clo,
         int M, int N, int K, int act)
{
    extern __shared__ bf16 smem[];
    const uint32_t smb = (uint32_t)__cvta_generic_to_shared(smem);
    const uint32_t oAl = 2 * ASZ * 2;
    const uint32_t oBh = 4 * ASZ * 2;
    const uint32_t oBl = oBh + 2 * BSZ * 2;

    const int tid  = threadIdx.x;
    const int bm   = blockIdx.y * 128;
    const int bn   = blockIdx.x * 64;
    const int warp = tid >> 5, lane = tid & 31;
    const int wm   = (warp & 3) * 32;
    const int wn   = (warp >> 2) * 32;
    const int group = lane >> 2, tig = lane & 3;
    const int matm = (lane >> 3) & 1;
    const int math = (lane >> 4) & 1;
    const int r7   = lane & 7;
    const uint32_t aLane = (uint32_t)((matm * 8 + r7) * (A_STR * 2) + math * 16);
    const uint32_t bLane = (uint32_t)((matm * 8 + r7) * (B_STR * 2) + math * 16);

    float acc[2][4][4] = {};
    const int nkb = K >> 5;

    auto loadAB = [&](int kb, int st) {
        const uint32_t sbA = smb + st * (ASZ * 2);
        #pragma unroll
        for (int i = 0; i < 2; i++) {
            int s = tid + i * 256;
            int row = s >> 2, c8 = (s & 3) * 8;
            uint32_t off = (uint32_t)((row * A_STR + c8) * 2);
            size_t gsrc = (size_t)(bm + row) * K + kb * 32 + c8;
            CP_ASYNC16(sbA + off, Ah + gsrc);
            CP_ASYNC16(sbA + oAl + off, Al + gsrc);
        }
        const uint32_t sbB = smb + st * (BSZ * 2);
        int row = tid >> 3, c8 = (tid & 7) * 8;
        uint32_t off = (uint32_t)((row * B_STR + c8) * 2);
        size_t gsrc = (size_t)(kb * 32 + row) * N + bn + c8;
        CP_ASYNC16(sbB + oBh + off, Wh + gsrc);
        CP_ASYNC16(sbB + oBl + off, Wl + gsrc);
    };

    loadAB(0, 0); CP_COMMIT();

    for (int kb = 0; kb < nkb; kb++) {
        int cur = kb & 1;
        CP_WAIT(0);
        __syncthreads();
        if (kb + 1 < nkb) { loadAB(kb + 1, cur ^ 1); CP_COMMIT(); }
        const uint32_t aBase = smb + cur * (ASZ * 2);
        const uint32_t bBase = smb + cur * (BSZ * 2) + oBh;
        #pragma unroll
        for (int ks = 0; ks < 2; ks++) {
            uint32_t ah[2][4], al[2][4], bh[4][2], bl[4][2];
            #pragma unroll
            for (int mt = 0; mt < 2; mt++) {
                uint32_t addr = aBase + (uint32_t)((wm + mt * 16) * (A_STR * 2) + ks * 32) + aLane;
                ldm_x4(ah[mt][0], ah[mt][1], ah[mt][2], ah[mt][3], addr);
                ldm_x4(al[mt][0], al[mt][1], al[mt][2], al[mt][3], addr + oAl);
            }
            #pragma unroll
            for (int p = 0; p < 2; p++) {
                uint32_t addr = bBase + (uint32_t)(ks * 16 * (B_STR * 2) + (wn + p * 16) * 2) + bLane;
                uint32_t t0, t1, t2, t3;
                ldm_x4t(t0, t1, t2, t3, addr);
                bh[2 * p][0] = t0; bh[2 * p][1] = t1; bh[2 * p + 1][0] = t2; bh[2 * p + 1][1] = t3;
                ldm_x4t(t0, t1, t2, t3, addr + (oBl - oBh));
                bl[2 * p][0] = t0; bl[2 * p][1] = t1; bl[2 * p + 1][0] = t2; bl[2 * p + 1][1] = t3;
            }
            #pragma unroll
            for (int mt = 0; mt < 2; mt++)
                #pragma unroll
                for (int nt = 0; nt < 4; nt++)
                    mma_bf16(acc[mt][nt], ah[mt], bh[nt]);
            #pragma unroll
            for (int mt = 0; mt < 2; mt++)
                #pragma unroll
                for (int nt = 0; nt < 4; nt++)
                    mma_bf16(acc[mt][nt], ah[mt], bl[nt]);
            #pragma unroll
            for (int mt = 0; mt < 2; mt++)
                #pragma unroll
                for (int nt = 0; nt < 4; nt++)
                    mma_bf16(acc[mt][nt], al[mt], bh[nt]);
        }
    }

    #pragma unroll
    for (int mt = 0; mt < 2; mt++) {
        int r0 = bm + wm + mt * 16 + group;
        #pragma unroll
        for (int nt = 0; nt < 4; nt++) {
            int cc = bn + wn + nt * 8 + tig * 2;
            float b0 = bias[cc], b1 = bias[cc + 1];
            float v00 = acc[mt][nt][0] + b0;
            float v01 = acc[mt][nt][1] + b1;
            float v10 = acc[mt][nt][2] + b0;
            float v11 = acc[mt][nt][3] + b1;
            if (act) { v00 = gelu_f(v00); v01 = gelu_f(v01); v10 = gelu_f(v10); v11 = gelu_f(v11); }
            if (Chi) {
                uint32_t hh, ll;
                splitpack2(v00, v01, hh, ll);
                *reinterpret_cast<uint32_t*>(&Chi[(size_t)r0 * N + cc]) = hh;
                *reinterpret_cast<uint32_t*>(&Clo[(size_t)r0 * N + cc]) = ll;
                splitpack2(v10, v11, hh, ll);
                *reinterpret_cast<uint32_t*>(&Chi[(size_t)(r0 + 8) * N + cc]) = hh;
                *reinterpret_cast<uint32_t*>(&Clo[(size_t)(r0 + 8) * N + cc]) = ll;
            } else {
                if (res) {
                    v00 += res[(size_t)r0 * N + cc];       v01 += res[(size_t)r0 * N + cc + 1];
                    v10 += res[(size_t)(r0 + 8) * N + cc]; v11 += res[(size_t)(r0 + 8) * N + cc + 1];
                }
                Cf[(size_t)r0 * N + cc]           = v00;
                Cf[(size_t)r0 * N + cc + 1]       = v01;
                Cf[(size_t)(r0 + 8) * N + cc]     = v10;
                Cf[(size_t)(r0 + 8) * N + cc + 1] = v11;
            }
        }
    }
}

// ---------- bf16x3 GEMM wide (128x128, 2-stage, splitK via blockIdx.z) -------
#define BW_STR 136
#define BWSZ (32 * BW_STR)
#define GEMMW_SMEM ((4 * ASZ + 4 * BWSZ) * 2)

__global__ void __launch_bounds__(256, 2)
gemm_bf3w(const bf16* __restrict__ Ah, const bf16* __restrict__ Al,
          const bf16* __restrict__ Wh, const bf16* __restrict__ Wl,
          const float* __restrict__ bias,
          float* __restrict__ Cf, bf16* __restrict__ Chi, bf16* __restrict__ Clo,
          int M, int N, int K, int act)
{
    extern __shared__ bf16 smem[];
    const uint32_t smb = (uint32_t)__cvta_generic_to_shared(smem);
    const uint32_t oAl = 2 * ASZ * 2;
    const uint32_t oBh = 4 * ASZ * 2;
    const uint32_t oBl = oBh + 2 * BWSZ * 2;

    const int tid  = threadIdx.x;
    const int bm   = blockIdx.y * 128;
    const int bn   = blockIdx.x * 128;
    const int zz   = blockIdx.z;
    const int Ks   = K / gridDim.z;
    const int koff = zz * Ks;
    const int warp = tid >> 5, lane = tid & 31;
    const int wm   = (warp & 3) * 32;
    const int wn   = (warp >> 2) * 64;
    const int group = lane >> 2, tig = lane & 3;
    const int matm = (lane >> 3) & 1;
    const int math = (lane >> 4) & 1;
    const int r7   = lane & 7;
    const uint32_t aLane = (uint32_t)((matm * 8 + r7) * (A_STR * 2) + math * 16);
    const uint32_t bLane = (uint32_t)((matm * 8 + r7) * (BW_STR * 2) + math * 16);

    float acc[2][8][4] = {};
    const int nkb = Ks >> 5;

    auto loadAB = [&](int kb, int st) {
        const uint32_t sbA = smb + st * (ASZ * 2);
        #pragma unroll
        for (int i = 0; i < 2; i++) {
            int s = tid + i * 256;
            int row = s >> 2, c8 = (s & 3) * 8;
            uint32_t off = (uint32_t)((row * A_STR + c8) * 2);
            size_t gsrc = (size_t)(bm + row) * K + koff + kb * 32 + c8;
            CP_ASYNC16(sbA + off, Ah + gsrc);
            CP_ASYNC16(sbA + oAl + off, Al + gsrc);
        }
        const uint32_t sbB = smb + st * (BWSZ * 2);
        #pragma unroll
        for (int i = 0; i < 2; i++) {
            int s = tid + i * 256;
            int row = s >> 4, c8 = (s & 15) * 8;
            uint32_t off = (uint32_t)((row * BW_STR + c8) * 2);
            size_t gsrc = (size_t)(koff + kb * 32 + row) * N + bn + c8;
            CP_ASYNC16(sbB + oBh + off, Wh + gsrc);
            CP_ASYNC16(sbB + oBl + off, Wl + gsrc);
        }
    };

    loadAB(0, 0); CP_COMMIT();

    for (int kb = 0; kb < nkb; kb++) {
        int cur = kb & 1;
        CP_WAIT(0);
        __syncthreads();
        if (kb + 1 < nkb) { loadAB(kb + 1, cur ^ 1); CP_COMMIT(); }
        const uint32_t aBase = smb + cur * (ASZ * 2);
        const uint32_t bBase = smb + cur * (BWSZ * 2) + oBh;
        #pragma unroll
        for (int ks = 0; ks < 2; ks++) {
            uint32_t ah[2][4], al[2][4], bh[8][2], bl[8][2];
            #pragma unroll
            for (int mt = 0; mt < 2; mt++) {
                uint32_t addr = aBase + (uint32_t)((wm + mt * 16) * (A_STR * 2) + ks * 32) + aLane;
                ldm_x4(ah[mt][0], ah[mt][1], ah[mt][2], ah[mt][3], addr);
                ldm_x4(al[mt][0], al[mt][1], al[mt][2], al[mt][3], addr + oAl);
            }
            #pragma unroll
            for (int p = 0; p < 4; p++) {
                uint32_t addr = bBase + (uint32_t)(ks * 16 * (BW_STR * 2) + (wn + p * 16) * 2) + bLane;
                uint32_t t0, t1, t2, t3;
                ldm_x4t(t0, t1, t2, t3, addr);
                bh[2 * p][0] = t0; bh[2 * p][1] = t1; bh[2 * p + 1][0] = t2; bh[2 * p + 1][1] = t3;
                ldm_x4t(t0, t1, t2, t3, addr + (oBl - oBh));
                bl[2 * p][0] = t0; bl[2 * p][1] = t1; bl[2 * p + 1][0] = t2; bl[2 * p + 1][1] = t3;
            }
            #pragma unroll
            for (int mt = 0; mt < 2; mt++)
                #pragma unroll
                for (int nt = 0; nt < 8; nt++)
                    mma_bf16(acc[mt][nt], ah[mt], bh[nt]);
            #pragma unroll
            for (int mt = 0; mt < 2; mt++)
                #pragma unroll
                for (int nt = 0; nt < 8; nt++)
                    mma_bf16(acc[mt][nt], ah[mt], bl[nt]);
            #pragma unroll
            for (int mt = 0; mt < 2; mt++)
                #pragma unroll
                for (int nt = 0; nt < 8; nt++)
                    mma_bf16(acc[mt][nt], al[mt], bh[nt]);
        }
    }

    float* CfZ = Cf ? (Cf + (size_t)zz * M * N) : nullptr;
    #pragma unroll
    for (int mt = 0; mt < 2; mt++) {
        int r0 = bm + wm + mt * 16 + group;
        #pragma unroll
        for (int nt = 0; nt < 8; nt++) {
            int cc = bn + wn + nt * 8 + tig * 2;
            float b0 = (zz == 0) ? bias[cc] : 0.f;
            float b1 = (zz == 0) ? bias[cc + 1] : 0.f;
            float v00 = acc[mt][nt][0] + b0;
            float v01 = acc[mt][nt][1] + b1;
            float v10 = acc[mt][nt][2] + b0;
            float v11 = acc[mt][nt][3] + b1;
            if (act) { v00 = gelu_f(v00); v01 = gelu_f(v01); v10 = gelu_f(v10); v11 = gelu_f(v11); }
            if (Chi) {
                uint32_t hh, ll;
                splitpack2(v00, v01, hh, ll);
                *reinterpret_cast<uint32_t*>(&Chi[(size_t)r0 * N + cc]) = hh;
                *reinterpret_cast<uint32_t*>(&Clo[(size_t)r0 * N + cc]) = ll;
                splitpack2(v10, v11, hh, ll);
                *reinterpret_cast<uint32_t*>(&Chi[(size_t)(r0 + 8) * N + cc]) = hh;
                *reinterpret_cast<uint32_t*>(&Clo[(size_t)(r0 + 8) * N + cc]) = ll;
            } else {
                CfZ[(size_t)r0 * N + cc]           = v00;
                CfZ[(size_t)r0 * N + cc + 1]       = v01;
                CfZ[(size_t)(r0 + 8) * N + cc]     = v10;
                CfZ[(size_t)(r0 + 8) * N + cc + 1] = v11;
            }
        }
    }
}

// ---------------- tensor-core flash attention (unchanged) ----------------
#define AST 72
#define PLB (64 * AST * 2)
#define ATTN_SMEM (8 * PLB + 512)

__global__ void __launch_bounds__(128)
flash_attn_mma(const bf16* __restrict__ qkvh, const bf16* __restrict__ qkvl,
               const int* __restrict__ pad, bf16* __restrict__ ohi, bf16* __restrict__ olo)
{
    extern __shared__ char smraw[];
    const uint32_t smb = (uint32_t)__cvta_generic_to_shared(smraw);
    const uint32_t oQ = 0, oK = 2 * PLB, oV0 = 6 * PLB, oPS = 8 * PLB;

    const int tid  = threadIdx.x;
    const int lane = tid & 31;
    const int w    = tid >> 5;
    const int qt0  = blockIdx.x * 64;
    const int b    = blockIdx.y;
    const int h    = blockIdx.z;

    const int r7 = lane & 7;
    const int bA = (lane >> 3) & 1;
    const int bB = (lane >> 4) & 1;
    const int kRow = bB * 8 + r7;
    const int kCol = bA * 16;
    const int qg0 = qt0 + w * 16 + (lane >> 2);
    const int qg1 = qg0 + 8;

    #pragma unroll
    for (int i = 0; i < 4; i++) {
        int s = tid + i * 128;
        int r = s >> 3, c8 = (s & 7) * 8;
        size_t g = (size_t)(b * TT + qt0 + r) * (3 * DD) + h * DKH + c8;
        uint32_t d = smb + oQ + (uint32_t)((r * AST + c8) * 2);
        CP_ASYNC16(d, qkvh + g);
        CP_ASYNC16(d + PLB, qkvl + g);
    }
    CP_COMMIT();

    int c_start = 4 - (qt0 >> 6);
    if (c_start < 0) c_start = 0;

    auto issueK = [&](int c, int st) {
        int kc0 = qt0 - WWIN + 64 * c;
        #pragma unroll
        for (int i = 0; i < 4; i++) {
            int s = tid + i * 128;
            int r = s >> 3, c8 = (s & 7) * 8;
            size_t g = (size_t)(b * TT + kc0 + r) * (3 * DD) + DD + h * DKH + c8;
            uint32_t d = smb + oK + (uint32_t)(st * 2 * PLB) + (uint32_t)((r * AST + c8) * 2);
            CP_ASYNC16(d, qkvh + g);
            CP_ASYNC16(d + PLB, qkvl + g);
        }
        if (tid < 16)
            CP_ASYNC16(smb + oPS + (uint32_t)(st * 256 + tid * 16), pad + b * TT + kc0 + tid * 4);
    };
    auto issueV = [&](int c, int st) {
        int kc0 = qt0 - WWIN + 64 * c;
        uint32_t base = st ? (smb + oQ) : (smb + oV0);
        #pragma unroll
        for (int i = 0; i < 4; i++) {
            int s = tid + i * 128;
            int r = s >> 3, c8 = (s & 7) * 8;
            size_t g = (size_t)(b * TT + kc0 + r) * (3 * DD) + 2 * DD + h * DKH + c8;
            uint32_t d = base + (uint32_t)((r * AST + c8) * 2);
            CP_ASYNC16(d, qkvh + g);
            CP_ASYNC16(d + PLB, qkvl + g);
        }
    };

    issueK(c_start, 0); CP_COMMIT();
    issueV(c_start, 0); CP_COMMIT();

    CP_WAIT(2);
    __syncthreads();

    uint32_t qfh[4][4], qfl[4][4];
    #pragma unroll
    for (int ks = 0; ks < 4; ks++) {
        uint32_t ad = smb + oQ + (uint32_t)(((w * 16 + bA * 8 + r7) * AST) * 2 + ks * 32 + bB * 16);
        ldm_x4(qfh[ks][0], qfh[ks][1], qfh[ks][2], qfh[ks][3], ad);
        ldm_x4(qfl[ks][0], qfl[ks][1], qfl[ks][2], qfl[ks][3], ad + PLB);
    }

    float Oa[8][4];
    #pragma unroll
    for (int i = 0; i < 8; i++)
        #pragma unroll
        for (int j = 0; j < 4; j++) Oa[i][j] = 0.f;
    float mold[2] = {-1e30f, -1e30f};
    float lrun[2] = {0.f, 0.f};

    int stage = 0;
    for (int c = c_start; c < 5; c++) {
        const int kc0 = qt0 - WWIN + 64 * c;
        CP_WAIT(1);
        __syncthreads();

        float s4[8][4];
        #pragma unroll
        for (int i = 0; i < 8; i++)
            #pragma unroll
            for (int j = 0; j < 4; j++) s4[i][j] = 0.f;
        const uint32_t kb0 = smb + oK + (uint32_t)(stage * 2 * PLB);
        #pragma unroll
        for (int ks = 0; ks < 4; ks++) {
            uint32_t kh[8][2], kl[8][2];
            #pragma unroll
            for (int p = 0; p < 4; p++) {
                uint32_t ad = kb0 + (uint32_t)(((p * 16 + kRow) * AST) * 2 + ks * 32 + kCol);
                ldm_x4(kh[2 * p][0], kh[2 * p][1], kh[2 * p + 1][0], kh[2 * p + 1][1], ad);
                ldm_x4(kl[2 * p][0], kl[2 * p][1], kl[2 * p + 1][0], kl[2 * p + 1][1], ad + PLB);
            }
            #pragma unroll
            for (int nt = 0; nt < 8; nt++) mma_bf16(s4[nt], qfh[ks], kh[nt]);
            #pragma unroll
            for (int nt = 0; nt < 8; nt++) mma_bf16(s4[nt], qfh[ks], kl[nt]);
            #pragma unroll
            for (int nt = 0; nt < 8; nt++) mma_bf16(s4[nt], qfl[ks], kh[nt]);
        }

        if (c < 4) { issueK(c + 1, stage ^ 1); CP_COMMIT(); }

        const int* psS = (const int*)(smraw + oPS + stage * 256);
        const int jb = 2 * (lane & 3);
        #pragma unroll
        for (int nt = 0; nt < 8; nt++) {
            int jj = nt * 8 + jb;
            int j  = kc0 + jj;
            int pd0 = psS[jj], pd1 = psS[jj + 1];
            bool v00 = (j     <= qg0) && (j     >= qg0 - (WWIN - 1)) && !pd0;
            bool v01 = (j + 1 <= qg0) && (j + 1 >= qg0 - (WWIN - 1)) && !pd1;
            bool v10 = (j     <= qg1) && (j     >= qg1 - (WWIN - 1)) && !pd0;
            bool v11 = (j + 1 <= qg1) && (j + 1 >= qg1 - (WWIN - 1)) && !pd1;
            s4[nt][0] = v00 ? s4[nt][0] * 0.125f : -1e30f;
            s4[nt][1] = v01 ? s4[nt][1] * 0.125f : -1e30f;
            s4[nt][2] = v10 ? s4[nt][2] * 0.125f : -1e30f;
            s4[nt][3] = v11 ? s4[nt][3] * 0.125f : -1e30f;
        }

        float mc0 = -1e30f, mc1 = -1e30f;
        #pragma unroll
        for (int nt = 0; nt < 8; nt++) {
            mc0 = fmaxf(mc0, fmaxf(s4[nt][0], s4[nt][1]));
            mc1 = fmaxf(mc1, fmaxf(s4[nt][2], s4[nt][3]));
        }
        mc0 = fmaxf(mc0, __shfl_xor_sync(0xffffffffu, mc0, 1));
        mc0 = fmaxf(mc0, __shfl_xor_sync(0xffffffffu, mc0, 2));
        mc1 = fmaxf(mc1, __shfl_xor_sync(0xffffffffu, mc1, 1));
        mc1 = fmaxf(mc1, __shfl_xor_sync(0xffffffffu, mc1, 2));
        float mn0 = fmaxf(mold[0], mc0);
        float mn1 = fmaxf(mold[1], mc1);
        float al0 = fexp(mold[0] - mn0);
        float al1 = fexp(mold[1] - mn1);
        mold[0] = mn0; mold[1] = mn1;
        float ps0 = 0.f, ps1 = 0.f;
        #pragma unroll
        for (int nt = 0; nt < 8; nt++) {
            float p0 = (s4[nt][0] <= -1e29f) ? 0.f : fexp(s4[nt][0] - mn0);
            float p1 = (s4[nt][1] <= -1e29f) ? 0.f : fexp(s4[nt][1] - mn0);
            float p2 = (s4[nt][2] <= -1e29f) ? 0.f : fexp(s4[nt][2] - mn1);
            float p3 = (s4[nt][3] <= -1e29f) ? 0.f : fexp(s4[nt][3] - mn1);
            s4[nt][0] = p0; s4[nt][1] = p1; s4[nt][2] = p2; s4[nt][3] = p3;
            ps0 += p0 + p1; ps1 += p2 + p3;
        }
        ps0 += __shfl_xor_sync(0xffffffffu, ps0, 1);
        ps0 += __shfl_xor_sync(0xffffffffu, ps0, 2);
        ps1 += __shfl_xor_sync(0xffffffffu, ps1, 1);
        ps1 += __shfl_xor_sync(0xffffffffu, ps1, 2);
        lrun[0] = lrun[0] * al0 + ps0;
        lrun[1] = lrun[1] * al1 + ps1;

        #pragma unroll
        for (int nt = 0; nt < 8; nt++) {
            Oa[nt][0] *= al0; Oa[nt][1] *= al0;
            Oa[nt][2] *= al1; Oa[nt][3] *= al1;
        }

        uint32_t aPh[4][4], aPl[4][4];
        #pragma unroll
        for (int t = 0; t < 4; t++) {
            splitpack2(s4[2 * t][0],     s4[2 * t][1],     aPh[t][0], aPl[t][0]);
            splitpack2(s4[2 * t][2],     s4[2 * t][3],     aPh[t][1], aPl[t][1]);
            splitpack2(s4[2 * t + 1][0], s4[2 * t + 1][1], aPh[t][2], aPl[t][2]);
            splitpack2(s4[2 * t + 1][2], s4[2 * t + 1][3], aPh[t][3], aPl[t][3]);
        }

        if (c < 4) { CP_WAIT(1); } else { CP_WAIT(0); }
        __syncthreads();
        if (c < 4) { issueV(c + 1, stage ^ 1); CP_COMMIT(); }

        const uint32_t vb0 = stage ? (smb + oQ) : (smb + oV0);
        #pragma unroll
        for (int t = 0; t < 4; t++) {
            uint32_t vh[8][2], vl[8][2];
            #pragma unroll
            for (int p = 0; p < 4; p++) {
                uint32_t ad = vb0 + (uint32_t)(((t * 16 + bA * 8 + r7) * AST) * 2 + p * 32 + bB * 16);
                uint32_t t0, t1, t2, t3;
                ldm_x4t(t0, t1, t2, t3, ad);
                vh[2 * p][0] = t0; vh[2 * p][1] = t1; vh[2 * p + 1][0] = t2; vh[2 * p + 1][1] = t3;
                ldm_x4t(t0, t1, t2, t3, ad + PLB);
                vl[2 * p][0] = t0; vl[2 * p][1] = t1; vl[2 * p + 1][0] = t2; vl[2 * p + 1][1] = t3;
            }
            #pragma unroll
            for (int nt = 0; nt < 8; nt++) mma_bf16(Oa[nt], aPh[t], vh[nt]);
            #pragma unroll
            for (int nt = 0; nt < 8; nt++) mma_bf16(Oa[nt], aPh[t], vl[nt]);
            #pragma unroll
            for (int nt = 0; nt < 8; nt++) mma_bf16(Oa[nt], aPl[t], vh[nt]);
        }
        stage ^= 1;
    }

    float inv0 = (lrun[0] > 0.f) ? 1.0f / lrun[0] : 0.f;
    float inv1 = (lrun[1] > 0.f) ? 1.0f / lrun[1] : 0.f;
    int tok0 = b * TT + qt0 + w * 16 + (lane >> 2);
    #pragma unroll
    for (int nt = 0; nt < 8; nt++) {
        int col = h * DKH + nt * 8 + 2 * (lane & 3);
        uint32_t hi, lo;
        splitpack2(Oa[nt][0] * inv0, Oa[nt][1] * inv0, hi, lo);
        *reinterpret_cast<uint32_t*>(&ohi[(size_t)tok0 * DD + col]) = hi;
        *reinterpret_cast<uint32_t*>(&olo[(size_t)tok0 * DD + col]) = lo;
        splitpack2(Oa[nt][2] * inv1, Oa[nt][3] * inv1, hi, lo);
        *reinterpret_cast<uint32_t*>(&ohi[(size_t)(tok0 + 8) * DD + col]) = hi;
        *reinterpret_cast<uint32_t*>(&olo[(size_t)(tok0 + 8) * DD + col]) = lo;
    }
}

__global__ void finish_heads(const float* __restrict__ ho,
                             const float* __restrict__ bhW2, const float* __restrict__ bhb2,
                             const float* __restrict__ ahW2, const float* __restrict__ ahb2,
                             const float* __restrict__ chW2, const float* __restrict__ chb2,
                             float* __restrict__ out)
{
    int token = blockIdx.x;
    int tid = threadIdx.x;
    __shared__ float red[128];
    const float* row = ho + (size_t)token * DD;

    float t0 = row[tid] * bhW2[tid * 2]     + row[tid + 128] * bhW2[(tid + 128) * 2];
    float t1 = row[tid] * bhW2[tid * 2 + 1] + row[tid + 128] * bhW2[(tid + 128) * 2 + 1];
    red[tid] = t0; __syncthreads();
    for (int s = 64; s > 0; s >>= 1) { if (tid < s) red[tid] += red[tid + s]; __syncthreads(); }
    float s0 = red[0]; __syncthreads();
    red[tid] = t1; __syncthreads();
    for (int s = 64; s > 0; s >>= 1) { if (tid < s) red[tid] += red[tid + s]; __syncthreads(); }
    float s1 = red[0]; __syncthreads();
    red[tid] = row[256 + tid] * ahW2[tid]; __syncthreads();
    for (int s = 64; s > 0; s >>= 1) { if (tid < s) red[tid] += red[tid + s]; __syncthreads(); }
    float sa = red[0]; __syncthreads();
    red[tid] = row[384 + tid] * chW2[tid]; __syncthreads();
    for (int s = 64; s > 0; s >>= 1) { if (tid < s) red[tid] += red[tid + s]; __syncthreads(); }
    float sc = red[0];

    if (tid == 0) {
        out[token * 2 + 0] = s0 + bhb2[0];
        out[token * 2 + 1] = s1 + bhb2[1];
        out[2 * NT + token] = sa + ahb2[0];
        out[3 * NT + token] = 1.0f / (1.0f + expf(-(sc + chb2[0])));
    }
}

#define SYM(p, s) cudaGetSymbolAddress((void**)&p, s)

extern "C" void kernel_launch(void* const* d_in, const int* in_sizes, int n_in,
                              void* d_out, int out_size)
{
    const float* x    = (const float*)d_in[0];
    const float* pos  = (const float*)d_in[1];
    const float* Wp   = (const float*)d_in[2];
    const float* bp   = (const float*)d_in[3];
    const float* Wq   = (const float*)d_in[4];
    const float* bq   = (const float*)d_in[5];
    const float* Wk   = (const float*)d_in[6];
    const float* bk   = (const float*)d_in[7];
    const float* Wv   = (const float*)d_in[8];
    const float* bv   = (const float*)d_in[9];
    const float* Wo   = (const float*)d_in[10];
    const float* bo   = (const float*)d_in[11];
    const float* ln1g = (const float*)d_in[12];
    const float* ln1b = (const float*)d_in[13];
    const float* W1   = (const float*)d_in[14];
    const float* b1   = (const float*)d_in[15];
    const float* W2   = (const float*)d_in[16];
    const float* b2   = (const float*)d_in[17];
    const float* ln2g = (const float*)d_in[18];
    const float* ln2b = (const float*)d_in[19];
    const float* bhW1 = (const float*)d_in[20];
    const float* bhb1 = (const float*)d_in[21];
    const float* bhW2 = (const float*)d_in[22];
    const float* bhb2 = (const float*)d_in[23];
    const float* ahW1 = (const float*)d_in[24];
    const float* ahb1 = (const float*)d_in[25];
    const float* ahW2 = (const float*)d_in[26];
    const float* ahb2 = (const float*)d_in[27];
    const float* chW1 = (const float*)d_in[28];
    const float* chb1 = (const float*)d_in[29];
    const float* chW2 = (const float*)d_in[30];
    const float* chb2 = (const float*)d_in[31];
    float* out = (float*)d_out;

    float *p_h, *p_p, *p_ho, *p_bqkv, *p_bhd;
    bf16 *p_hnh, *p_hnl, *p_qkvh, *p_qkvl, *p_oh, *p_ol, *p_ffh, *p_ffl, *p_hsh, *p_hsl;
    bf16 *pw_qkvh, *pw_qkvl, *pw_woh, *pw_wol, *pw_w1h, *pw_w1l, *pw_w2h, *pw_w2l, *pw_hdh, *pw_hdl;
    int* p_pad;
    SYM(p_h, g_h);       SYM(p_p, g_p);
    SYM(p_hnh, g_hn_h);  SYM(p_hnl, g_hn_l);
    SYM(p_qkvh, g_qkv_h); SYM(p_qkvl, g_qkv_l);
    SYM(p_oh, g_o_h);    SYM(p_ol, g_o_l);
    SYM(p_ffh, g_ff_h);  SYM(p_ffl, g_ff_l);
    SYM(p_hsh, g_hs_h);  SYM(p_hsl, g_hs_l);
    SYM(p_ho, g_ho);     SYM(p_pad, g_pad);
    SYM(pw_qkvh, w_qkv_h); SYM(pw_qkvl, w_qkv_l);
    SYM(pw_woh, w_wo_h); SYM(pw_wol, w_wo_l);
    SYM(pw_w1h, w_w1_h); SYM(pw_w1l, w_w1_l);
    SYM(pw_w2h, w_w2_h); SYM(pw_w2l, w_w2_l);
    SYM(pw_hdh, w_hd_h); SYM(pw_hdl, w_hd_l);
    SYM(p_bqkv, b_qkv);  SYM(p_bhd, b_hd);

    cudaFuncSetAttribute(gemm_bf3, cudaFuncAttributeMaxDynamicSharedMemorySize, GEMM_SMEM);
    cudaFuncSetAttribute(gemm_bf3w, cudaFuncAttributeMaxDynamicSharedMemorySize, GEMMW_SMEM);
    cudaFuncSetAttribute(flash_attn_mma, cudaFuncAttributeMaxDynamicSharedMemorySize, ATTN_SMEM);

    prep_all<<<4096, 256>>>(Wq, Wk, Wv, bq, bk, bv, Wo, W1, W2,
                            bhW1, bhb1, ahW1, ahb1, chW1, chb1);
    embed_kernel<<<NT, 128>>>(x, pos, Wp, bp);

    dim3 gQKVw(3 * DD / 128, NT / 128, 1);  // (12, 32)
    dim3 gFFw (DFF / 128,    NT / 128, 1);  // (16, 32)
    dim3 gW2w (DD / 128,     NT / 128, 2);  // (4, 32, 2) splitK
    dim3 gD   (DD / 64,      NT / 128);     // (8, 32)
    dim3 gAtt(TT / 64, NB, NH);

    for (int l = 0; l < NL; l++) {
        if (l == 0)
            ln_kernel<<<NT, 256>>>(p_h, ln1g, ln1b, p_hnh, p_hnl);
        else
            ln_comb<<<NT, 256>>>(p_h, p_p, ln1g + l * DD, ln1b + l * DD, p_hnh, p_hnl);
        gemm_bf3w<<<gQKVw, 256, GEMMW_SMEM>>>(p_hnh, p_hnl,
            pw_qkvh + (size_t)l * DD * 3 * DD, pw_qkvl + (size_t)l * DD * 3 * DD,
            p_bqkv + l * 3 * DD, nullptr, p_qkvh, p_qkvl, NT, 3 * DD, DD, 0);
        flash_attn_mma<<<gAtt, 128, ATTN_SMEM>>>(p_qkvh, p_qkvl, p_pad, p_oh, p_ol);
        gemm_bf3<<<gD, 256, GEMM_SMEM>>>(p_oh, p_ol,
            pw_woh + (size_t)l * DD * DD, pw_wol + (size_t)l * DD * DD,
            bo + l * DD, p_h, p_h, nullptr, nullptr, NT, DD, DD, 0);
        ln_kernel<<<NT, 256>>>(p_h, ln2g + l * DD, ln2b + l * DD, p_hnh, p_hnl);
        gemm_bf3w<<<gFFw, 256, GEMMW_SMEM>>>(p_hnh, p_hnl,
            pw_w1h + (size_t)l * DD * DFF, pw_w1l + (size_t)l * DD * DFF,
            b1 + l * DFF, nullptr, p_ffh, p_ffl, NT, DFF, DD, 1);
        gemm_bf3w<<<gW2w, 256, GEMMW_SMEM>>>(p_ffh, p_ffl,
            pw_w2h + (size_t)l * DFF * DD, pw_w2l + (size_t)l * DFF * DD,
            b2 + l * DD, p_p, nullptr, nullptr, NT, DD, DFF, 0);
    }

    comb_split<<<1024, 256>>>((const float4*)p_h, (const float4*)p_p, p_hsh, p_hsl, NT * DD / 4);
    gemm_bf3<<<gD, 256, GEMM_SMEM>>>(p_hsh, p_hsl, pw_hdh, pw_hdl,
        p_bhd, nullptr, p_ho, nullptr, nullptr, NT, DD, DD, 1);
    finish_heads<<<NT, 128>>>(p_ho, bhW2, bhb2, ahW2, ahb2, chW2, chb2, out);
}

// round 15
// speedup vs baseline: 1.0450x; 1.0140x over previous
#include <cuda_runtime.h>
#include <cuda_bf16.h>
#include <math.h>
#include <stdint.h>

#define NL   6
#define DD   512
#define NH   8
#define DKH  64
#define DFF  2048
#define WWIN 256
#define NB   4
#define TT   1024
#define NT   (NB * TT)

typedef __nv_bfloat16 bf16;
typedef __nv_bfloat162 bf162;

__device__ float g_h    [NT * DD];
__device__ float g_p    [2 * NT * DD];
__device__ bf16  g_hn_h [NT * DD];
__device__ bf16  g_hn_l [NT * DD];
__device__ bf16  g_qkv_h[NT * 3 * DD];
__device__ bf16  g_qkv_l[NT * 3 * DD];
__device__ bf16  g_o_h  [NT * DD];
__device__ bf16  g_o_l  [NT * DD];
__device__ bf16  g_ff_h [NT * DFF];
__device__ bf16  g_ff_l [NT * DFF];
__device__ bf16  g_hs_h [NT * DD];
__device__ bf16  g_hs_l [NT * DD];
__device__ int   g_pad  [NT];

__device__ bf16 w_qkv_h[NL * DD * 3 * DD];
__device__ bf16 w_qkv_l[NL * DD * 3 * DD];
__device__ bf16 w_wo_h [NL * DD * DD];
__device__ bf16 w_wo_l [NL * DD * DD];
__device__ bf16 w_w1_h [NL * DD * DFF];
__device__ bf16 w_w1_l [NL * DD * DFF];
__device__ bf16 w_w2_h [NL * DFF * DD];
__device__ bf16 w_w2_l [NL * DFF * DD];
__device__ bf16 w_hd_h [DD * DD];
__device__ bf16 w_hd_l [DD * DD];
__device__ float b_qkv [NL * 3 * DD];
__device__ float b_hd  [DD];

__device__ __forceinline__ float gelu_f(float x) {
    return 0.5f * x * (1.0f + erff(x * 0.7071067811865476f));
}
__device__ __forceinline__ void split2(float v, bf16& h, bf16& l) {
    h = __float2bfloat16(v);
    l = __float2bfloat16(v - __bfloat162float(h));
}
__device__ __forceinline__ void splitpack2(float x, float y, uint32_t& hi, uint32_t& lo) {
    bf162 H = __floats2bfloat162_rn(x, y);
    bf162 L = __floats2bfloat162_rn(x - __bfloat162float(H.x), y - __bfloat162float(H.y));
    hi = *reinterpret_cast<uint32_t*>(&H);
    lo = *reinterpret_cast<uint32_t*>(&L);
}
__device__ __forceinline__ float fexp(float x) {
    float y = fmaxf(x * 1.4426950408889634f, -126.0f);
    int i = __float2int_rn(y);
    float f = y - (float)i;
    float p = 1.5356298e-4f;
    p = fmaf(p, f, 1.3333558e-3f);
    p = fmaf(p, f, 9.6181291e-3f);
    p = fmaf(p, f, 5.5504109e-2f);
    p = fmaf(p, f, 2.4022651e-1f);
    p = fmaf(p, f, 6.9314718e-1f);
    p = fmaf(p, f, 1.0f);
    return p * __int_as_float((i + 127) << 23);
}
__device__ __forceinline__ void mma_bf16(float* c, const uint32_t* a, const uint32_t* b) {
    asm volatile(
        "mma.sync.aligned.m16n8k16.row.col.f32.bf16.bf16.f32 "
        "{%0,%1,%2,%3},{%4,%5,%6,%7},{%8,%9},{%0,%1,%2,%3};"
        : "+f"(c[0]), "+f"(c[1]), "+f"(c[2]), "+f"(c[3])
        : "r"(a[0]), "r"(a[1]), "r"(a[2]), "r"(a[3]), "r"(b[0]), "r"(b[1]));
}
__device__ __forceinline__ void ldm_x4(uint32_t& r0, uint32_t& r1, uint32_t& r2, uint32_t& r3, uint32_t a) {
    asm volatile("ldmatrix.sync.aligned.m8n8.x4.shared.b16 {%0,%1,%2,%3},[%4];"
                 : "=r"(r0), "=r"(r1), "=r"(r2), "=r"(r3) : "r"(a));
}
__device__ __forceinline__ void ldm_x4t(uint32_t& r0, uint32_t& r1, uint32_t& r2, uint32_t& r3, uint32_t a) {
    asm volatile("ldmatrix.sync.aligned.m8n8.x4.trans.shared.b16 {%0,%1,%2,%3},[%4];"
                 : "=r"(r0), "=r"(r1), "=r"(r2), "=r"(r3) : "r"(a));
}
#define CP_ASYNC16(dst, src) \
    asm volatile("cp.async.cg.shared.global [%0], [%1], 16;\n" :: "r"(dst), "l"(src))
#define CP_COMMIT() asm volatile("cp.async.commit_group;\n")
#define CP_WAIT(n)  asm volatile("cp.async.wait_group %0;\n" :: "n"(n))

__device__ __forceinline__ void split4store(float4 v, bf16* hi, bf16* lo) {
    bf162 h0 = __floats2bfloat162_rn(v.x, v.y);
    bf162 h1 = __floats2bfloat162_rn(v.z, v.w);
    bf162 l0 = __floats2bfloat162_rn(v.x - __bfloat162float(h0.x), v.y - __bfloat162float(h0.y));
    bf162 l1 = __floats2bfloat162_rn(v.z - __bfloat162float(h1.x), v.w - __bfloat162float(h1.y));
    uint2 H = {*(uint32_t*)&h0, *(uint32_t*)&h1};
    uint2 L = {*(uint32_t*)&l0, *(uint32_t*)&l1};
    *reinterpret_cast<uint2*>(hi) = H;
    *reinterpret_cast<uint2*>(lo) = L;
}

// ---------------- merged prep ----------------
#define N4_QKV (NL * DD * 3 * DD / 4)
#define N4_WO  (NL * DD * DD / 4)
#define N4_W1  (NL * DD * DFF / 4)
#define N4_W2  (NL * DFF * DD / 4)
#define N4_HD  (DD * DD / 4)
#define N4_TOT (N4_QKV + N4_WO + N4_W1 + N4_W2 + N4_HD)

__global__ void prep_all(const float* __restrict__ Wq, const float* __restrict__ Wk,
                         const float* __restrict__ Wv, const float* __restrict__ bq,
                         const float* __restrict__ bk, const float* __restrict__ bv,
                         const float* __restrict__ Wo, const float* __restrict__ W1,
                         const float* __restrict__ W2,
                         const float* __restrict__ bhW1, const float* __restrict__ bhb1,
                         const float* __restrict__ ahW1, const float* __restrict__ ahb1,
                         const float* __restrict__ chW1, const float* __restrict__ chb1)
{
    for (int i4 = blockIdx.x * blockDim.x + threadIdx.x; i4 < N4_TOT; i4 += gridDim.x * blockDim.x) {
        if (i4 < N4_QKV) {
            int idx = i4 * 4;
            int l = idx / (DD * 3 * DD);
            int r = idx % (DD * 3 * DD);
            int k = r / (3 * DD);
            int n = r % (3 * DD);
            const float* src;
            if (n < DD)           src = Wq + (size_t)l * DD * DD + k * DD + n;
            else if (n < 2 * DD)  src = Wk + (size_t)l * DD * DD + k * DD + (n - DD);
            else                  src = Wv + (size_t)l * DD * DD + k * DD + (n - 2 * DD);
            split4store(*reinterpret_cast<const float4*>(src), &w_qkv_h[idx], &w_qkv_l[idx]);
        } else if (i4 < N4_QKV + N4_WO) {
            int j = i4 - N4_QKV, idx = j * 4;
            split4store(reinterpret_cast<const float4*>(Wo)[j], &w_wo_h[idx], &w_wo_l[idx]);
        } else if (i4 < N4_QKV + N4_WO + N4_W1) {
            int j = i4 - N4_QKV - N4_WO, idx = j * 4;
            split4store(reinterpret_cast<const float4*>(W1)[j], &w_w1_h[idx], &w_w1_l[idx]);
        } else if (i4 < N4_QKV + N4_WO + N4_W1 + N4_W2) {
            int j = i4 - N4_QKV - N4_WO - N4_W1, idx = j * 4;
            split4store(reinterpret_cast<const float4*>(W2)[j], &w_w2_h[idx], &w_w2_l[idx]);
        } else {
            int j = i4 - (N4_QKV + N4_WO + N4_W1 + N4_W2);
            int idx = j * 4;
            int k = idx / DD, n = idx % DD;
            const float* src;
            if (n < 256)      src = bhW1 + k * 256 + n;
            else if (n < 384) src = ahW1 + k * 128 + (n - 256);
            else              src = chW1 + k * 128 + (n - 384);
            split4store(*reinterpret_cast<const float4*>(src), &w_hd_h[idx], &w_hd_l[idx]);
        }
    }
    for (int i = blockIdx.x * blockDim.x + threadIdx.x; i < NL * 3 * DD; i += gridDim.x * blockDim.x) {
        int l = i / (3 * DD), n = i % (3 * DD);
        b_qkv[i] = (n < DD) ? bq[l * DD + n] : (n < 2 * DD) ? bk[l * DD + n - DD] : bv[l * DD + n - 2 * DD];
    }
    for (int n = blockIdx.x * blockDim.x + threadIdx.x; n < DD; n += gridDim.x * blockDim.x)
        b_hd[n] = (n < 256) ? bhb1[n] : (n < 384) ? ahb1[n - 256] : chb1[n - 384];
}

__global__ void embed_kernel(const float* __restrict__ x, const float* __restrict__ pos,
                             const float* __restrict__ Wp, const float* __restrict__ bp)
{
    int token = blockIdx.x;
    int t = token % TT;
    float xv = x[token];
    if (threadIdx.x == 0) g_pad[token] = (xv == -1.0f) ? 1 : 0;
    for (int d = threadIdx.x; d < DD; d += blockDim.x)
        g_h[(size_t)token * DD + d] = xv * Wp[d] + bp[d] + pos[(size_t)t * DD + d];
}

// ---------------- LN core ----------------
__device__ __forceinline__ void ln_core(int token, int tid, float v0, float v1,
                                        const float* gg, const float* bb,
                                        bf16* outh, bf16* outl)
{
    __shared__ float red[8];
    __shared__ float stat[2];
    float s = v0 + v1;
    #pragma unroll
    for (int o = 16; o; o >>= 1) s += __shfl_down_sync(0xffffffffu, s, o);
    if ((tid & 31) == 0) red[tid >> 5] = s;
    __syncthreads();
    if (tid == 0) {
        float tt = 0.f;
        #pragma unroll
        for (int i = 0; i < 8; i++) tt += red[i];
        stat[0] = tt * (1.0f / DD);
    }
    __syncthreads();
    float mean = stat[0];
    float d0 = v0 - mean, d1 = v1 - mean;
    float q = d0 * d0 + d1 * d1;
    #pragma unroll
    for (int o = 16; o; o >>= 1) q += __shfl_down_sync(0xffffffffu, q, o);
    __syncthreads();
    if ((tid & 31) == 0) red[tid >> 5] = q;
    __syncthreads();
    if (tid == 0) {
        float tt = 0.f;
        #pragma unroll
        for (int i = 0; i < 8; i++) tt += red[i];
        stat[1] = rsqrtf(tt * (1.0f / DD) + 1e-5f);
    }
    __syncthreads();
    float inv = stat[1];
    float y0 = d0 * inv * gg[tid]       + bb[tid];
    float y1 = d1 * inv * gg[tid + 256] + bb[tid + 256];
    split2(y0, outh[(size_t)token * DD + tid],       outl[(size_t)token * DD + tid]);
    split2(y1, outh[(size_t)token * DD + tid + 256], outl[(size_t)token * DD + tid + 256]);
}

__global__ void ln_kernel(const float* __restrict__ in, const float* __restrict__ gg,
                          const float* __restrict__ bb, bf16* __restrict__ outh,
                          bf16* __restrict__ outl)
{
    int token = blockIdx.x;
    int tid = threadIdx.x;
    size_t i0 = (size_t)token * DD + tid;
    ln_core(token, tid, in[i0], in[i0 + 256], gg, bb, outh, outl);
}

__global__ void ln_comb(float* __restrict__ h, const float* __restrict__ p,
                        const float* __restrict__ gg, const float* __restrict__ bb,
                        bf16* __restrict__ outh, bf16* __restrict__ outl)
{
    int token = blockIdx.x;
    int tid = threadIdx.x;
    size_t i0 = (size_t)token * DD + tid, i1 = i0 + 256;
    const size_t PO = (size_t)NT * DD;
    float v0 = h[i0] + p[i0] + p[PO + i0];
    float v1 = h[i1] + p[i1] + p[PO + i1];
    h[i0] = v0; h[i1] = v1;
    ln_core(token, tid, v0, v1, gg, bb, outh, outl);
}

__global__ void comb_split(const float4* __restrict__ h, const float4* __restrict__ p,
                           bf16* __restrict__ hi, bf16* __restrict__ lo, int n4)
{
    for (int i = blockIdx.x * blockDim.x + threadIdx.x; i < n4; i += gridDim.x * blockDim.x) {
        float4 a = h[i], b0 = p[i], b1 = p[n4 + i];
        float4 v = make_float4(a.x + b0.x + b1.x, a.y + b0.y + b1.y,
                               a.z + b0.z + b1.z, a.w + b0.w + b1.w);
        split4store(v, hi + i * 4, lo + i * 4);
    }
}

// ---------- bf16x3 GEMM wide (128x128, 2-stage, splitK via blockIdx.z) -------
#define A_STR 40
#define ASZ (128 * A_STR)
#define BW_STR 136
#define BWSZ (32 * BW_STR)
#define GEMMW_SMEM ((4 * ASZ + 4 * BWSZ) * 2)

__global__ void __launch_bounds__(256, 2)
gemm_bf3w(const bf16* __restrict__ Ah, const bf16* __restrict__ Al,
          const bf16* __restrict__ Wh, const bf16* __restrict__ Wl,
          const float* __restrict__ bias,
          float* __restrict__ Cf, bf16* __restrict__ Chi, bf16* __restrict__ Clo,
          int M, int N, int K, int act)
{
    extern __shared__ bf16 smem[];
    const uint32_t smb = (uint32_t)__cvta_generic_to_shared(smem);
    const uint32_t oAl = 2 * ASZ * 2;
    const uint32_t oBh = 4 * ASZ * 2;
    const uint32_t oBl = oBh + 2 * BWSZ * 2;

    const int tid  = threadIdx.x;
    const int bm   = blockIdx.y * 128;
    const int bn   = blockIdx.x * 128;
    const int zz   = blockIdx.z;
    const int Ks   = K / gridDim.z;
    const int koff = zz * Ks;
    const int warp = tid >> 5, lane = tid & 31;
    const int wm   = (warp & 3) * 32;
    const int wn   = (warp >> 2) * 64;
    const int group = lane >> 2, tig = lane & 3;
    const int matm = (lane >> 3) & 1;
    const int math = (lane >> 4) & 1;
    const int r7   = lane & 7;
    const uint32_t aLane = (uint32_t)((matm * 8 + r7) * (A_STR * 2) + math * 16);
    const uint32_t bLane = (uint32_t)((matm * 8 + r7) * (BW_STR * 2) + math * 16);

    float acc[2][8][4] = {};
    const int nkb = Ks >> 5;

    auto loadAB = [&](int kb, int st) {
        const uint32_t sbA = smb + st * (ASZ * 2);
        #pragma unroll
        for (int i = 0; i < 2; i++) {
            int s = tid + i * 256;
            int row = s >> 2, c8 = (s & 3) * 8;
            uint32_t off = (uint32_t)((row * A_STR + c8) * 2);
            size_t gsrc = (size_t)(bm + row) * K + koff + kb * 32 + c8;
            CP_ASYNC16(sbA + off, Ah + gsrc);
            CP_ASYNC16(sbA + oAl + off, Al + gsrc);
        }
        const uint32_t sbB = smb + st * (BWSZ * 2);
        #pragma unroll
        for (int i = 0; i < 2; i++) {
            int s = tid + i * 256;
            int row = s >> 4, c8 = (s & 15) * 8;
            uint32_t off = (uint32_t)((row * BW_STR + c8) * 2);
            size_t gsrc = (size_t)(koff + kb * 32 + row) * N + bn + c8;
            CP_ASYNC16(sbB + oBh + off, Wh + gsrc);
            CP_ASYNC16(sbB + oBl + off, Wl + gsrc);
        }
    };

    loadAB(0, 0); CP_COMMIT();

    for (int kb = 0; kb < nkb; kb++) {
        int cur = kb & 1;
        CP_WAIT(0);
        __syncthreads();
        if (kb + 1 < nkb) { loadAB(kb + 1, cur ^ 1); CP_COMMIT(); }
        const uint32_t aBase = smb + cur * (ASZ * 2);
        const uint32_t bBase = smb + cur * (BWSZ * 2) + oBh;
        #pragma unroll
        for (int ks = 0; ks < 2; ks++) {
            uint32_t ah[2][4], al[2][4], bh[8][2], bl[8][2];
            #pragma unroll
            for (int mt = 0; mt < 2; mt++) {
                uint32_t addr = aBase + (uint32_t)((wm + mt * 16) * (A_STR * 2) + ks * 32) + aLane;
                ldm_x4(ah[mt][0], ah[mt][1], ah[mt][2], ah[mt][3], addr);
                ldm_x4(al[mt][0], al[mt][1], al[mt][2], al[mt][3], addr + oAl);
            }
            #pragma unroll
            for (int p = 0; p < 4; p++) {
                uint32_t addr = bBase + (uint32_t)(ks * 16 * (BW_STR * 2) + (wn + p * 16) * 2) + bLane;
                uint32_t t0, t1, t2, t3;
                ldm_x4t(t0, t1, t2, t3, addr);
                bh[2 * p][0] = t0; bh[2 * p][1] = t1; bh[2 * p + 1][0] = t2; bh[2 * p + 1][1] = t3;
                ldm_x4t(t0, t1, t2, t3, addr + (oBl - oBh));
                bl[2 * p][0] = t0; bl[2 * p][1] = t1; bl[2 * p + 1][0] = t2; bl[2 * p + 1][1] = t3;
            }
            #pragma unroll
            for (int mt = 0; mt < 2; mt++)
                #pragma unroll
                for (int nt = 0; nt < 8; nt++)
                    mma_bf16(acc[mt][nt], ah[mt], bh[nt]);
            #pragma unroll
            for (int mt = 0; mt < 2; mt++)
                #pragma unroll
                for (int nt = 0; nt < 8; nt++)
                    mma_bf16(acc[mt][nt], ah[mt], bl[nt]);
            #pragma unroll
            for (int mt = 0; mt < 2; mt++)
                #pragma unroll
                for (int nt = 0; nt < 8; nt++)
                    mma_bf16(acc[mt][nt], al[mt], bh[nt]);
        }
    }

    float* CfZ = Cf ? (Cf + (size_t)zz * M * N) : nullptr;
    #pragma unroll
    for (int mt = 0; mt < 2; mt++) {
        int r0 = bm + wm + mt * 16 + group;
        #pragma unroll
        for (int nt = 0; nt < 8; nt++) {
            int cc = bn + wn + nt * 8 + tig * 2;
            float b0 = (zz == 0) ? bias[cc] : 0.f;
            float b1 = (zz == 0) ? bias[cc + 1] : 0.f;
            float v00 = acc[mt][nt][0] + b0;
            float v01 = acc[mt][nt][1] + b1;
            float v10 = acc[mt][nt][2] + b0;
            float v11 = acc[mt][nt][3] + b1;
            if (act) { v00 = gelu_f(v00); v01 = gelu_f(v01); v10 = gelu_f(v10); v11 = gelu_f(v11); }
            if (Chi) {
                uint32_t hh, ll;
                splitpack2(v00, v01, hh, ll);
                *reinterpret_cast<uint32_t*>(&Chi[(size_t)r0 * N + cc]) = hh;
                *reinterpret_cast<uint32_t*>(&Clo[(size_t)r0 * N + cc]) = ll;
                splitpack2(v10, v11, hh, ll);
                *reinterpret_cast<uint32_t*>(&Chi[(size_t)(r0 + 8) * N + cc]) = hh;
                *reinterpret_cast<uint32_t*>(&Clo[(size_t)(r0 + 8) * N + cc]) = ll;
            } else {
                CfZ[(size_t)r0 * N + cc]           = v00;
                CfZ[(size_t)r0 * N + cc + 1]       = v01;
                CfZ[(size_t)(r0 + 8) * N + cc]     = v10;
                CfZ[(size_t)(r0 + 8) * N + cc + 1] = v11;
            }
        }
    }
}

// ---------------- tensor-core flash attention ----------------
#define AST 72
#define PLB (64 * AST * 2)
#define ATTN_SMEM (8 * PLB + 512)

__global__ void __launch_bounds__(128)
flash_attn_mma(const bf16* __restrict__ qkvh, const bf16* __restrict__ qkvl,
               const int* __restrict__ pad, bf16* __restrict__ ohi, bf16* __restrict__ olo)
{
    extern __shared__ char smraw[];
    const uint32_t smb = (uint32_t)__cvta_generic_to_shared(smraw);
    const uint32_t oQ = 0, oK = 2 * PLB, oV0 = 6 * PLB, oPS = 8 * PLB;

    const int tid  = threadIdx.x;
    const int lane = tid & 31;
    const int w    = tid >> 5;
    const int qt0  = blockIdx.x * 64;
    const int b    = blockIdx.y;
    const int h    = blockIdx.z;

    const int r7 = lane & 7;
    const int bA = (lane >> 3) & 1;
    const int bB = (lane >> 4) & 1;
    const int kRow = bB * 8 + r7;
    const int kCol = bA * 16;
    const int qg0 = qt0 + w * 16 + (lane >> 2);
    const int qg1 = qg0 + 8;

    #pragma unroll
    for (int i = 0; i < 4; i++) {
        int s = tid + i * 128;
        int r = s >> 3, c8 = (s & 7) * 8;
        size_t g = (size_t)(b * TT + qt0 + r) * (3 * DD) + h * DKH + c8;
        uint32_t d = smb + oQ + (uint32_t)((r * AST + c8) * 2);
        CP_ASYNC16(d, qkvh + g);
        CP_ASYNC16(d + PLB, qkvl + g);
    }
    CP_COMMIT();

    int c_start = 4 - (qt0 >> 6);
    if (c_start < 0) c_start = 0;

    auto issueK = [&](int c, int st) {
        int kc0 = qt0 - WWIN + 64 * c;
        #pragma unroll
        for (int i = 0; i < 4; i++) {
            int s = tid + i * 128;
            int r = s >> 3, c8 = (s & 7) * 8;
            size_t g = (size_t)(b * TT + kc0 + r) * (3 * DD) + DD + h * DKH + c8;
            uint32_t d = smb + oK + (uint32_t)(st * 2 * PLB) + (uint32_t)((r * AST + c8) * 2);
            CP_ASYNC16(d, qkvh + g);
            CP_ASYNC16(d + PLB, qkvl + g);
        }
        if (tid < 16)
            CP_ASYNC16(smb + oPS + (uint32_t)(st * 256 + tid * 16), pad + b * TT + kc0 + tid * 4);
    };
    auto issueV = [&](int c, int st) {
        int kc0 = qt0 - WWIN + 64 * c;
        uint32_t base = st ? (smb + oQ) : (smb + oV0);
        #pragma unroll
        for (int i = 0; i < 4; i++) {
            int s = tid + i * 128;
            int r = s >> 3, c8 = (s & 7) * 8;
            size_t g = (size_t)(b * TT + kc0 + r) * (3 * DD) + 2 * DD + h * DKH + c8;
            uint32_t d = base + (uint32_t)((r * AST + c8) * 2);
            CP_ASYNC16(d, qkvh + g);
            CP_ASYNC16(d + PLB, qkvl + g);
        }
    };

    issueK(c_start, 0); CP_COMMIT();
    issueV(c_start, 0); CP_COMMIT();

    CP_WAIT(2);
    __syncthreads();

    uint32_t qfh[4][4], qfl[4][4];
    #pragma unroll
    for (int ks = 0; ks < 4; ks++) {
        uint32_t ad = smb + oQ + (uint32_t)(((w * 16 + bA * 8 + r7) * AST) * 2 + ks * 32 + bB * 16);
        ldm_x4(qfh[ks][0], qfh[ks][1], qfh[ks][2], qfh[ks][3], ad);
        ldm_x4(qfl[ks][0], qfl[ks][1], qfl[ks][2], qfl[ks][3], ad + PLB);
    }

    float Oa[8][4];
    #pragma unroll
    for (int i = 0; i < 8; i++)
        #pragma unroll
        for (int j = 0; j < 4; j++) Oa[i][j] = 0.f;
    float mold[2] = {-1e30f, -1e30f};
    float lrun[2] = {0.f, 0.f};

    int stage = 0;
    for (int c = c_start; c < 5; c++) {
        const int kc0 = qt0 - WWIN + 64 * c;
        CP_WAIT(1);
        __syncthreads();

        float s4[8][4];
        #pragma unroll
        for (int i = 0; i < 8; i++)
            #pragma unroll
            for (int j = 0; j < 4; j++) s4[i][j] = 0.f;
        const uint32_t kb0 = smb + oK + (uint32_t)(stage * 2 * PLB);
        #pragma unroll
        for (int ks = 0; ks < 4; ks++) {
            uint32_t kh[8][2], kl[8][2];
            #pragma unroll
            for (int p = 0; p < 4; p++) {
                uint32_t ad = kb0 + (uint32_t)(((p * 16 + kRow) * AST) * 2 + ks * 32 + kCol);
                ldm_x4(kh[2 * p][0], kh[2 * p][1], kh[2 * p + 1][0], kh[2 * p + 1][1], ad);
                ldm_x4(kl[2 * p][0], kl[2 * p][1], kl[2 * p + 1][0], kl[2 * p + 1][1], ad + PLB);
            }
            #pragma unroll
            for (int nt = 0; nt < 8; nt++) mma_bf16(s4[nt], qfh[ks], kh[nt]);
            #pragma unroll
            for (int nt = 0; nt < 8; nt++) mma_bf16(s4[nt], qfh[ks], kl[nt]);
            #pragma unroll
            for (int nt = 0; nt < 8; nt++) mma_bf16(s4[nt], qfl[ks], kh[nt]);
        }

        if (c < 4) { issueK(c + 1, stage ^ 1); CP_COMMIT(); }

        const int* psS = (const int*)(smraw + oPS + stage * 256);
        const int jb = 2 * (lane & 3);
        #pragma unroll
        for (int nt = 0; nt < 8; nt++) {
            int jj = nt * 8 + jb;
            int j  = kc0 + jj;
            int pd0 = psS[jj], pd1 = psS[jj + 1];
            bool v00 = (j     <= qg0) && (j     >= qg0 - (WWIN - 1)) && !pd0;
            bool v01 = (j + 1 <= qg0) && (j + 1 >= qg0 - (WWIN - 1)) && !pd1;
            bool v10 = (j     <= qg1) && (j     >= qg1 - (WWIN - 1)) && !pd0;
            bool v11 = (j + 1 <= qg1) && (j + 1 >= qg1 - (WWIN - 1)) && !pd1;
            s4[nt][0] = v00 ? s4[nt][0] * 0.125f : -1e30f;
            s4[nt][1] = v01 ? s4[nt][1] * 0.125f : -1e30f;
            s4[nt][2] = v10 ? s4[nt][2] * 0.125f : -1e30f;
            s4[nt][3] = v11 ? s4[nt][3] * 0.125f : -1e30f;
        }

        float mc0 = -1e30f, mc1 = -1e30f;
        #pragma unroll
        for (int nt = 0; nt < 8; nt++) {
            mc0 = fmaxf(mc0, fmaxf(s4[nt][0], s4[nt][1]));
            mc1 = fmaxf(mc1, fmaxf(s4[nt][2], s4[nt][3]));
        }
        mc0 = fmaxf(mc0, __shfl_xor_sync(0xffffffffu, mc0, 1));
        mc0 = fmaxf(mc0, __shfl_xor_sync(0xffffffffu, mc0, 2));
        mc1 = fmaxf(mc1, __shfl_xor_sync(0xffffffffu, mc1, 1));
        mc1 = fmaxf(mc1, __shfl_xor_sync(0xffffffffu, mc1, 2));
        float mn0 = fmaxf(mold[0], mc0);
        float mn1 = fmaxf(mold[1], mc1);
        float al0 = fexp(mold[0] - mn0);
        float al1 = fexp(mold[1] - mn1);
        mold[0] = mn0; mold[1] = mn1;
        float ps0 = 0.f, ps1 = 0.f;
        #pragma unroll
        for (int nt = 0; nt < 8; nt++) {
            float p0 = (s4[nt][0] <= -1e29f) ? 0.f : fexp(s4[nt][0] - mn0);
            float p1 = (s4[nt][1] <= -1e29f) ? 0.f : fexp(s4[nt][1] - mn0);
            float p2 = (s4[nt][2] <= -1e29f) ? 0.f : fexp(s4[nt][2] - mn1);
            float p3 = (s4[nt][3] <= -1e29f) ? 0.f : fexp(s4[nt][3] - mn1);
            s4[nt][0] = p0; s4[nt][1] = p1; s4[nt][2] = p2; s4[nt][3] = p3;
            ps0 += p0 + p1; ps1 += p2 + p3;
        }
        ps0 += __shfl_xor_sync(0xffffffffu, ps0, 1);
        ps0 += __shfl_xor_sync(0xffffffffu, ps0, 2);
        ps1 += __shfl_xor_sync(0xffffffffu, ps1, 1);
        ps1 += __shfl_xor_sync(0xffffffffu, ps1, 2);
        lrun[0] = lrun[0] * al0 + ps0;
        lrun[1] = lrun[1] * al1 + ps1;

        #pragma unroll
        for (int nt = 0; nt < 8; nt++) {
            Oa[nt][0] *= al0; Oa[nt][1] *= al0;
            Oa[nt][2] *= al1; Oa[nt][3] *= al1;
        }

        uint32_t aPh[4][4], aPl[4][4];
        #pragma unroll
        for (int t = 0; t < 4; t++) {
            splitpack2(s4[2 * t][0],     s4[2 * t][1],     aPh[t][0], aPl[t][0]);
            splitpack2(s4[2 * t][2],     s4[2 * t][3],     aPh[t][1], aPl[t][1]);
            splitpack2(s4[2 * t + 1][0], s4[2 * t + 1][1], aPh[t][2], aPl[t][2]);
            splitpack2(s4[2 * t + 1][2], s4[2 * t + 1][3], aPh[t][3], aPl[t][3]);
        }

        if (c < 4) { CP_WAIT(1); } else { CP_WAIT(0); }
        __syncthreads();
        if (c < 4) { issueV(c + 1, stage ^ 1); CP_COMMIT(); }

        const uint32_t vb0 = stage ? (smb + oQ) : (smb + oV0);
        #pragma unroll
        for (int t = 0; t < 4; t++) {
            uint32_t vh[8][2], vl[8][2];
            #pragma unroll
            for (int p = 0; p < 4; p++) {
                uint32_t ad = vb0 + (uint32_t)(((t * 16 + bA * 8 + r7) * AST) * 2 + p * 32 + bB * 16);
                uint32_t t0, t1, t2, t3;
                ldm_x4t(t0, t1, t2, t3, ad);
                vh[2 * p][0] = t0; vh[2 * p][1] = t1; vh[2 * p + 1][0] = t2; vh[2 * p + 1][1] = t3;
                ldm_x4t(t0, t1, t2, t3, ad + PLB);
                vl[2 * p][0] = t0; vl[2 * p][1] = t1; vl[2 * p + 1][0] = t2; vl[2 * p + 1][1] = t3;
            }
            #pragma unroll
            for (int nt = 0; nt < 8; nt++) mma_bf16(Oa[nt], aPh[t], vh[nt]);
            #pragma unroll
            for (int nt = 0; nt < 8; nt++) mma_bf16(Oa[nt], aPh[t], vl[nt]);
            #pragma unroll
            for (int nt = 0; nt < 8; nt++) mma_bf16(Oa[nt], aPl[t], vh[nt]);
        }
        stage ^= 1;
    }

    float inv0 = (lrun[0] > 0.f) ? 1.0f / lrun[0] : 0.f;
    float inv1 = (lrun[1] > 0.f) ? 1.0f / lrun[1] : 0.f;
    int tok0 = b * TT + qt0 + w * 16 + (lane >> 2);
    #pragma unroll
    for (int nt = 0; nt < 8; nt++) {
        int col = h * DKH + nt * 8 + 2 * (lane & 3);
        uint32_t hi, lo;
        splitpack2(Oa[nt][0] * inv0, Oa[nt][1] * inv0, hi, lo);
        *reinterpret_cast<uint32_t*>(&ohi[(size_t)tok0 * DD + col]) = hi;
        *reinterpret_cast<uint32_t*>(&olo[(size_t)tok0 * DD + col]) = lo;
        splitpack2(Oa[nt][2] * inv1, Oa[nt][3] * inv1, hi, lo);
        *reinterpret_cast<uint32_t*>(&ohi[(size_t)(tok0 + 8) * DD + col]) = hi;
        *reinterpret_cast<uint32_t*>(&olo[(size_t)(tok0 + 8) * DD + col]) = lo;
    }
}

// ---------------- head finish (splitK combine + bias + gelu + proj) ---------
__global__ void finish_heads(const float* __restrict__ p, const float* __restrict__ bhd,
                             const float* __restrict__ bhW2, const float* __restrict__ bhb2,
                             const float* __restrict__ ahW2, const float* __restrict__ ahb2,
                             const float* __restrict__ chW2, const float* __restrict__ chb2,
                             float* __restrict__ out)
{
    int token = blockIdx.x;
    int tid = threadIdx.x;
    __shared__ float red[128];
    const size_t PO = (size_t)NT * DD;
    const float* r0 = p + (size_t)token * DD;
    const float* r1 = r0 + PO;

    float vA = gelu_f(r0[tid] + r1[tid] + bhd[tid]);
    float vB = gelu_f(r0[tid + 128] + r1[tid + 128] + bhd[tid + 128]);
    float vC = gelu_f(r0[tid + 256] + r1[tid + 256] + bhd[tid + 256]);
    float vD = gelu_f(r0[tid + 384] + r1[tid + 384] + bhd[tid + 384]);

    float t0 = vA * bhW2[tid * 2]     + vB * bhW2[(tid + 128) * 2];
    float t1 = vA * bhW2[tid * 2 + 1] + vB * bhW2[(tid + 128) * 2 + 1];
    red[tid] = t0; __syncthreads();
    for (int s = 64; s > 0; s >>= 1) { if (tid < s) red[tid] += red[tid + s]; __syncthreads(); }
    float s0 = red[0]; __syncthreads();
    red[tid] = t1; __syncthreads();
    for (int s = 64; s > 0; s >>= 1) { if (tid < s) red[tid] += red[tid + s]; __syncthreads(); }
    float s1 = red[0]; __syncthreads();
    red[tid] = vC * ahW2[tid]; __syncthreads();
    for (int s = 64; s > 0; s >>= 1) { if (tid < s) red[tid] += red[tid + s]; __syncthreads(); }
    float sa = red[0]; __syncthreads();
    red[tid] = vD * chW2[tid]; __syncthreads();
    for (int s = 64; s > 0; s >>= 1) { if (tid < s) red[tid] += red[tid + s]; __syncthreads(); }
    float sc = red[0];

    if (tid == 0) {
        out[token * 2 + 0] = s0 + bhb2[0];
        out[token * 2 + 1] = s1 + bhb2[1];
        out[2 * NT + token] = sa + ahb2[0];
        out[3 * NT + token] = 1.0f / (1.0f + expf(-(sc + chb2[0])));
    }
}

#define SYM(p, s) cudaGetSymbolAddress((void**)&p, s)

extern "C" void kernel_launch(void* const* d_in, const int* in_sizes, int n_in,
                              void* d_out, int out_size)
{
    const float* x    = (const float*)d_in[0];
    const float* pos  = (const float*)d_in[1];
    const float* Wp   = (const float*)d_in[2];
    const float* bp   = (const float*)d_in[3];
    const float* Wq   = (const float*)d_in[4];
    const float* bq   = (const float*)d_in[5];
    const float* Wk   = (const float*)d_in[6];
    const float* bk   = (const float*)d_in[7];
    const float* Wv   = (const float*)d_in[8];
    const float* bv   = (const float*)d_in[9];
    const float* Wo   = (const float*)d_in[10];
    const float* bo   = (const float*)d_in[11];
    const float* ln1g = (const float*)d_in[12];
    const float* ln1b = (const float*)d_in[13];
    const float* W1   = (const float*)d_in[14];
    const float* b1   = (const float*)d_in[15];
    const float* W2   = (const float*)d_in[16];
    const float* b2   = (const float*)d_in[17];
    const float* ln2g = (const float*)d_in[18];
    const float* ln2b = (const float*)d_in[19];
    const float* bhW1 = (const float*)d_in[20];
    const float* bhb1 = (const float*)d_in[21];
    const float* bhW2 = (const float*)d_in[22];
    const float* bhb2 = (const float*)d_in[23];
    const float* ahW1 = (const float*)d_in[24];
    const float* ahb1 = (const float*)d_in[25];
    const float* ahW2 = (const float*)d_in[26];
    const float* ahb2 = (const float*)d_in[27];
    const float* chW1 = (const float*)d_in[28];
    const float* chb1 = (const float*)d_in[29];
    const float* chW2 = (const float*)d_in[30];
    const float* chb2 = (const float*)d_in[31];
    float* out = (float*)d_out;

    float *p_h, *p_p, *p_bqkv, *p_bhd;
    bf16 *p_hnh, *p_hnl, *p_qkvh, *p_qkvl, *p_oh, *p_ol, *p_ffh, *p_ffl, *p_hsh, *p_hsl;
    bf16 *pw_qkvh, *pw_qkvl, *pw_woh, *pw_wol, *pw_w1h, *pw_w1l, *pw_w2h, *pw_w2l, *pw_hdh, *pw_hdl;
    int* p_pad;
    SYM(p_h, g_h);       SYM(p_p, g_p);
    SYM(p_hnh, g_hn_h);  SYM(p_hnl, g_hn_l);
    SYM(p_qkvh, g_qkv_h); SYM(p_qkvl, g_qkv_l);
    SYM(p_oh, g_o_h);    SYM(p_ol, g_o_l);
    SYM(p_ffh, g_ff_h);  SYM(p_ffl, g_ff_l);
    SYM(p_hsh, g_hs_h);  SYM(p_hsl, g_hs_l);
    SYM(p_pad, g_pad);
    SYM(pw_qkvh, w_qkv_h); SYM(pw_qkvl, w_qkv_l);
    SYM(pw_woh, w_wo_h); SYM(pw_wol, w_wo_l);
    SYM(pw_w1h, w_w1_h); SYM(pw_w1l, w_w1_l);
    SYM(pw_w2h, w_w2_h); SYM(pw_w2l, w_w2_l);
    SYM(pw_hdh, w_hd_h); SYM(pw_hdl, w_hd_l);
    SYM(p_bqkv, b_qkv);  SYM(p_bhd, b_hd);

    cudaFuncSetAttribute(gemm_bf3w, cudaFuncAttributeMaxDynamicSharedMemorySize, GEMMW_SMEM);
    cudaFuncSetAttribute(flash_attn_mma, cudaFuncAttributeMaxDynamicSharedMemorySize, ATTN_SMEM);

    prep_all<<<4096, 256>>>(Wq, Wk, Wv, bq, bk, bv, Wo, W1, W2,
                            bhW1, bhb1, ahW1, ahb1, chW1, chb1);
    embed_kernel<<<NT, 128>>>(x, pos, Wp, bp);

    dim3 gQKVw(3 * DD / 128, NT / 128, 1);  // (12, 32)
    dim3 gFFw (DFF / 128,    NT / 128, 1);  // (16, 32)
    dim3 gDw  (DD / 128,     NT / 128, 2);  // (4, 32, 2) splitK
    dim3 gAtt(TT / 64, NB, NH);

    for (int l = 0; l < NL; l++) {
        if (l == 0)
            ln_kernel<<<NT, 256>>>(p_h, ln1g, ln1b, p_hnh, p_hnl);
        else
            ln_comb<<<NT, 256>>>(p_h, p_p, ln1g + l * DD, ln1b + l * DD, p_hnh, p_hnl);
        gemm_bf3w<<<gQKVw, 256, GEMMW_SMEM>>>(p_hnh, p_hnl,
            pw_qkvh + (size_t)l * DD * 3 * DD, pw_qkvl + (size_t)l * DD * 3 * DD,
            p_bqkv + l * 3 * DD, nullptr, p_qkvh, p_qkvl, NT, 3 * DD, DD, 0);
        flash_attn_mma<<<gAtt, 128, ATTN_SMEM>>>(p_qkvh, p_qkvl, p_pad, p_oh, p_ol);
        gemm_bf3w<<<gDw, 256, GEMMW_SMEM>>>(p_oh, p_ol,
            pw_woh + (size_t)l * DD * DD, pw_wol + (size_t)l * DD * DD,
            bo + l * DD, p_p, nullptr, nullptr, NT, DD, DD, 0);
        ln_comb<<<NT, 256>>>(p_h, p_p, ln2g + l * DD, ln2b + l * DD, p_hnh, p_hnl);
        gemm_bf3w<<<gFFw, 256, GEMMW_SMEM>>>(p_hnh, p_hnl,
            pw_w1h + (size_t)l * DD * DFF, pw_w1l + (size_t)l * DD * DFF,
            b1 + l * DFF, nullptr, p_ffh, p_ffl, NT, DFF, DD, 1);
        gemm_bf3w<<<gDw, 256, GEMMW_SMEM>>>(p_ffh, p_ffl,
            pw_w2h + (size_t)l * DFF * DD, pw_w2l + (size_t)l * DFF * DD,
            b2 + l * DD, p_p, nullptr, nullptr, NT, DD, DFF, 0);
    }

    comb_split<<<1024, 256>>>((const float4*)p_h, (const float4*)p_p, p_hsh, p_hsl, NT * DD / 4);
    gemm_bf3w<<<gDw, 256, GEMMW_SMEM>>>(p_hsh, p_hsl, pw_hdh, pw_hdl,
        p_bhd, p_p, nullptr, nullptr, NT, DD, DD, 0);
    finish_heads<<<NT, 128>>>(p_p, p_bhd, bhW2, bhb2, ahW2, ahb2, chW2, chb2, out);
}

// round 16
// speedup vs baseline: 1.0476x; 1.0024x over previous
#include <cuda_runtime.h>
#include <cuda_bf16.h>
#include <math.h>
#include <stdint.h>

#define NL   6
#define DD   512
#define NH   8
#define DKH  64
#define DFF  2048
#define WWIN 256
#define NB   4
#define TT   1024
#define NT   (NB * TT)

typedef __nv_bfloat16 bf16;
typedef __nv_bfloat162 bf162;

__device__ float g_h    [NT * DD];
__device__ float g_p    [2 * NT * DD];
__device__ bf16  g_hn_h [NT * DD];
__device__ bf16  g_hn_l [NT * DD];
__device__ bf16  g_qkv_h[NT * 3 * DD];
__device__ bf16  g_qkv_l[NT * 3 * DD];
__device__ bf16  g_o_h  [NT * DD];
__device__ bf16  g_o_l  [NT * DD];
__device__ bf16  g_ff_h [NT * DFF];
__device__ bf16  g_ff_l [NT * DFF];
__device__ bf16  g_hs_h [NT * DD];
__device__ bf16  g_hs_l [NT * DD];
__device__ int   g_pad  [NT];

__device__ bf16 w_qkv_h[NL * DD * 3 * DD];
__device__ bf16 w_qkv_l[NL * DD * 3 * DD];
__device__ bf16 w_wo_h [NL * DD * DD];
__device__ bf16 w_wo_l [NL * DD * DD];
__device__ bf16 w_w1_h [NL * DD * DFF];
__device__ bf16 w_w1_l [NL * DD * DFF];
__device__ bf16 w_w2_h [NL * DFF * DD];
__device__ bf16 w_w2_l [NL * DFF * DD];
__device__ bf16 w_hd_h [DD * DD];
__device__ bf16 w_hd_l [DD * DD];
__device__ float b_qkv [NL * 3 * DD];
__device__ float b_hd  [DD];

__device__ __forceinline__ float gelu_f(float x) {
    return 0.5f * x * (1.0f + erff(x * 0.7071067811865476f));
}
__device__ __forceinline__ void split2(float v, bf16& h, bf16& l) {
    h = __float2bfloat16(v);
    l = __float2bfloat16(v - __bfloat162float(h));
}
__device__ __forceinline__ void splitpack2(float x, float y, uint32_t& hi, uint32_t& lo) {
    bf162 H = __floats2bfloat162_rn(x, y);
    bf162 L = __floats2bfloat162_rn(x - __bfloat162float(H.x), y - __bfloat162float(H.y));
    hi = *reinterpret_cast<uint32_t*>(&H);
    lo = *reinterpret_cast<uint32_t*>(&L);
}
__device__ __forceinline__ float fexp(float x) {
    float y = fmaxf(x * 1.4426950408889634f, -126.0f);
    int i = __float2int_rn(y);
    float f = y - (float)i;
    float p = 1.5356298e-4f;
    p = fmaf(p, f, 1.3333558e-3f);
    p = fmaf(p, f, 9.6181291e-3f);
    p = fmaf(p, f, 5.5504109e-2f);
    p = fmaf(p, f, 2.4022651e-1f);
    p = fmaf(p, f, 6.9314718e-1f);
    p = fmaf(p, f, 1.0f);
    return p * __int_as_float((i + 127) << 23);
}
__device__ __forceinline__ void mma_bf16(float* c, const uint32_t* a, const uint32_t* b) {
    asm volatile(
        "mma.sync.aligned.m16n8k16.row.col.f32.bf16.bf16.f32 "
        "{%0,%1,%2,%3},{%4,%5,%6,%7},{%8,%9},{%0,%1,%2,%3};"
        : "+f"(c[0]), "+f"(c[1]), "+f"(c[2]), "+f"(c[3])
        : "r"(a[0]), "r"(a[1]), "r"(a[2]), "r"(a[3]), "r"(b[0]), "r"(b[1]));
}
__device__ __forceinline__ void ldm_x4(uint32_t& r0, uint32_t& r1, uint32_t& r2, uint32_t& r3, uint32_t a) {
    asm volatile("ldmatrix.sync.aligned.m8n8.x4.shared.b16 {%0,%1,%2,%3},[%4];"
                 : "=r"(r0), "=r"(r1), "=r"(r2), "=r"(r3) : "r"(a));
}
__device__ __forceinline__ void ldm_x4t(uint32_t& r0, uint32_t& r1, uint32_t& r2, uint32_t& r3, uint32_t a) {
    asm volatile("ldmatrix.sync.aligned.m8n8.x4.trans.shared.b16 {%0,%1,%2,%3},[%4];"
                 : "=r"(r0), "=r"(r1), "=r"(r2), "=r"(r3) : "r"(a));
}
#define CP_ASYNC16(dst, src) \
    asm volatile("cp.async.cg.shared.global [%0], [%1], 16;\n" :: "r"(dst), "l"(src))
#define CP_COMMIT() asm volatile("cp.async.commit_group;\n")
#define CP_WAIT(n)  asm volatile("cp.async.wait_group %0;\n" :: "n"(n))

__device__ __forceinline__ void split4store(float4 v, bf16* hi, bf16* lo) {
    bf162 h0 = __floats2bfloat162_rn(v.x, v.y);
    bf162 h1 = __floats2bfloat162_rn(v.z, v.w);
    bf162 l0 = __floats2bfloat162_rn(v.x - __bfloat162float(h0.x), v.y - __bfloat162float(h0.y));
    bf162 l1 = __floats2bfloat162_rn(v.z - __bfloat162float(h1.x), v.w - __bfloat162float(h1.y));
    uint2 H = {*(uint32_t*)&h0, *(uint32_t*)&h1};
    uint2 L = {*(uint32_t*)&l0, *(uint32_t*)&l1};
    *reinterpret_cast<uint2*>(hi) = H;
    *reinterpret_cast<uint2*>(lo) = L;
}

// ---------------- merged prep ----------------
#define N4_QKV (NL * DD * 3 * DD / 4)
#define N4_WO  (NL * DD * DD / 4)
#define N4_W1  (NL * DD * DFF / 4)
#define N4_W2  (NL * DFF * DD / 4)
#define N4_HD  (DD * DD / 4)
#define N4_TOT (N4_QKV + N4_WO + N4_W1 + N4_W2 + N4_HD)

__global__ void prep_all(const float* __restrict__ Wq, const float* __restrict__ Wk,
                         const float* __restrict__ Wv, const float* __restrict__ bq,
                         const float* __restrict__ bk, const float* __restrict__ bv,
                         const float* __restrict__ Wo, const float* __restrict__ W1,
                         const float* __restrict__ W2,
                         const float* __restrict__ bhW1, const float* __restrict__ bhb1,
                         const float* __restrict__ ahW1, const float* __restrict__ ahb1,
                         const float* __restrict__ chW1, const float* __restrict__ chb1)
{
    for (int i4 = blockIdx.x * blockDim.x + threadIdx.x; i4 < N4_TOT; i4 += gridDim.x * blockDim.x) {
        if (i4 < N4_QKV) {
            int idx = i4 * 4;
            int l = idx / (DD * 3 * DD);
            int r = idx % (DD * 3 * DD);
            int k = r / (3 * DD);
            int n = r % (3 * DD);
            const float* src;
            if (n < DD)           src = Wq + (size_t)l * DD * DD + k * DD + n;
            else if (n < 2 * DD)  src = Wk + (size_t)l * DD * DD + k * DD + (n - DD);
            else                  src = Wv + (size_t)l * DD * DD + k * DD + (n - 2 * DD);
            split4store(*reinterpret_cast<const float4*>(src), &w_qkv_h[idx], &w_qkv_l[idx]);
        } else if (i4 < N4_QKV + N4_WO) {
            int j = i4 - N4_QKV, idx = j * 4;
            split4store(reinterpret_cast<const float4*>(Wo)[j], &w_wo_h[idx], &w_wo_l[idx]);
        } else if (i4 < N4_QKV + N4_WO + N4_W1) {
            int j = i4 - N4_QKV - N4_WO, idx = j * 4;
            split4store(reinterpret_cast<const float4*>(W1)[j], &w_w1_h[idx], &w_w1_l[idx]);
        } else if (i4 < N4_QKV + N4_WO + N4_W1 + N4_W2) {
            int j = i4 - N4_QKV - N4_WO - N4_W1, idx = j * 4;
            split4store(reinterpret_cast<const float4*>(W2)[j], &w_w2_h[idx], &w_w2_l[idx]);
        } else {
            int j = i4 - (N4_QKV + N4_WO + N4_W1 + N4_W2);
            int idx = j * 4;
            int k = idx / DD, n = idx % DD;
            const float* src;
            if (n < 256)      src = bhW1 + k * 256 + n;
            else if (n < 384) src = ahW1 + k * 128 + (n - 256);
            else              src = chW1 + k * 128 + (n - 384);
            split4store(*reinterpret_cast<const float4*>(src), &w_hd_h[idx], &w_hd_l[idx]);
        }
    }
    for (int i = blockIdx.x * blockDim.x + threadIdx.x; i < NL * 3 * DD; i += gridDim.x * blockDim.x) {
        int l = i / (3 * DD), n = i % (3 * DD);
        b_qkv[i] = (n < DD) ? bq[l * DD + n] : (n < 2 * DD) ? bk[l * DD + n - DD] : bv[l * DD + n - 2 * DD];
    }
    for (int n = blockIdx.x * blockDim.x + threadIdx.x; n < DD; n += gridDim.x * blockDim.x)
        b_hd[n] = (n < 256) ? bhb1[n] : (n < 384) ? ahb1[n - 256] : chb1[n - 384];
}

__global__ void embed_kernel(const float* __restrict__ x, const float* __restrict__ pos,
                             const float* __restrict__ Wp, const float* __restrict__ bp)
{
    int token = blockIdx.x;
    int t = token % TT;
    float xv = x[token];
    if (threadIdx.x == 0) g_pad[token] = (xv == -1.0f) ? 1 : 0;
    for (int d = threadIdx.x; d < DD; d += blockDim.x)
        g_h[(size_t)token * DD + d] = xv * Wp[d] + bp[d] + pos[(size_t)t * DD + d];
}

// ---------------- LN core ----------------
__device__ __forceinline__ void ln_core(int token, int tid, float v0, float v1,
                                        const float* gg, const float* bb,
                                        bf16* outh, bf16* outl)
{
    __shared__ float red[8];
    __shared__ float stat[2];
    float s = v0 + v1;
    #pragma unroll
    for (int o = 16; o; o >>= 1) s += __shfl_down_sync(0xffffffffu, s, o);
    if ((tid & 31) == 0) red[tid >> 5] = s;
    __syncthreads();
    if (tid == 0) {
        float tt = 0.f;
        #pragma unroll
        for (int i = 0; i < 8; i++) tt += red[i];
        stat[0] = tt * (1.0f / DD);
    }
    __syncthreads();
    float mean = stat[0];
    float d0 = v0 - mean, d1 = v1 - mean;
    float q = d0 * d0 + d1 * d1;
    #pragma unroll
    for (int o = 16; o; o >>= 1) q += __shfl_down_sync(0xffffffffu, q, o);
    __syncthreads();
    if ((tid & 31) == 0) red[tid >> 5] = q;
    __syncthreads();
    if (tid == 0) {
        float tt = 0.f;
        #pragma unroll
        for (int i = 0; i < 8; i++) tt += red[i];
        stat[1] = rsqrtf(tt * (1.0f / DD) + 1e-5f);
    }
    __syncthreads();
    float inv = stat[1];
    float y0 = d0 * inv * gg[tid]       + bb[tid];
    float y1 = d1 * inv * gg[tid + 256] + bb[tid + 256];
    split2(y0, outh[(size_t)token * DD + tid],       outl[(size_t)token * DD + tid]);
    split2(y1, outh[(size_t)token * DD + tid + 256], outl[(size_t)token * DD + tid + 256]);
}

__global__ void ln_kernel(const float* __restrict__ in, const float* __restrict__ gg,
                          const float* __restrict__ bb, bf16* __restrict__ outh,
                          bf16* __restrict__ outl)
{
    int token = blockIdx.x;
    int tid = threadIdx.x;
    size_t i0 = (size_t)token * DD + tid;
    ln_core(token, tid, in[i0], in[i0 + 256], gg, bb, outh, outl);
}

__global__ void ln_comb(float* __restrict__ h, const float* __restrict__ p,
                        const float* __restrict__ gg, const float* __restrict__ bb,
                        bf16* __restrict__ outh, bf16* __restrict__ outl)
{
    int token = blockIdx.x;
    int tid = threadIdx.x;
    size_t i0 = (size_t)token * DD + tid, i1 = i0 + 256;
    const size_t PO = (size_t)NT * DD;
    float v0 = h[i0] + p[i0] + p[PO + i0];
    float v1 = h[i1] + p[i1] + p[PO + i1];
    h[i0] = v0; h[i1] = v1;
    ln_core(token, tid, v0, v1, gg, bb, outh, outl);
}

__global__ void comb_split(const float4* __restrict__ h, const float4* __restrict__ p,
                           bf16* __restrict__ hi, bf16* __restrict__ lo, int n4)
{
    for (int i = blockIdx.x * blockDim.x + threadIdx.x; i < n4; i += gridDim.x * blockDim.x) {
        float4 a = h[i], b0 = p[i], b1 = p[n4 + i];
        float4 v = make_float4(a.x + b0.x + b1.x, a.y + b0.y + b1.y,
                               a.z + b0.z + b1.z, a.w + b0.w + b1.w);
        split4store(v, hi + i * 4, lo + i * 4);
    }
}

// ---------- bf16x3 GEMM wide (128x128, 2-stage, splitK via blockIdx.z) -------
#define A_STR 40
#define ASZ (128 * A_STR)
#define BW_STR 136
#define BWSZ (32 * BW_STR)
#define GEMMW_SMEM ((4 * ASZ + 4 * BWSZ) * 2)

__global__ void __launch_bounds__(256, 2)
gemm_bf3w(const bf16* __restrict__ Ah, const bf16* __restrict__ Al,
          const bf16* __restrict__ Wh, const bf16* __restrict__ Wl,
          const float* __restrict__ bias,
          float* __restrict__ Cf, bf16* __restrict__ Chi, bf16* __restrict__ Clo,
          int M, int N, int K, int act)
{
    extern __shared__ bf16 smem[];
    const uint32_t smb = (uint32_t)__cvta_generic_to_shared(smem);
    const uint32_t oAl = 2 * ASZ * 2;
    const uint32_t oBh = 4 * ASZ * 2;
    const uint32_t oBl = oBh + 2 * BWSZ * 2;

    const int tid  = threadIdx.x;
    const int bm   = blockIdx.y * 128;
    const int bn   = blockIdx.x * 128;
    const int zz   = blockIdx.z;
    const int Ks   = K / gridDim.z;
    const int koff = zz * Ks;
    const int warp = tid >> 5, lane = tid & 31;
    const int wm   = (warp & 3) * 32;
    const int wn   = (warp >> 2) * 64;
    const int group = lane >> 2, tig = lane & 3;
    const int matm = (lane >> 3) & 1;
    const int math = (lane >> 4) & 1;
    const int r7   = lane & 7;
    const uint32_t aLane = (uint32_t)((matm * 8 + r7) * (A_STR * 2) + math * 16);
    const uint32_t bLane = (uint32_t)((matm * 8 + r7) * (BW_STR * 2) + math * 16);

    float acc[2][8][4] = {};
    const int nkb = Ks >> 5;

    auto loadAB = [&](int kb, int st) {
        const uint32_t sbA = smb + st * (ASZ * 2);
        #pragma unroll
        for (int i = 0; i < 2; i++) {
            int s = tid + i * 256;
            int row = s >> 2, c8 = (s & 3) * 8;
            uint32_t off = (uint32_t)((row * A_STR + c8) * 2);
            size_t gsrc = (size_t)(bm + row) * K + koff + kb * 32 + c8;
            CP_ASYNC16(sbA + off, Ah + gsrc);
            CP_ASYNC16(sbA + oAl + off, Al + gsrc);
        }
        const uint32_t sbB = smb + st * (BWSZ * 2);
        #pragma unroll
        for (int i = 0; i < 2; i++) {
            int s = tid + i * 256;
            int row = s >> 4, c8 = (s & 15) * 8;
            uint32_t off = (uint32_t)((row * BW_STR + c8) * 2);
            size_t gsrc = (size_t)(koff + kb * 32 + row) * N + bn + c8;
            CP_ASYNC16(sbB + oBh + off, Wh + gsrc);
            CP_ASYNC16(sbB + oBl + off, Wl + gsrc);
        }
    };

    loadAB(0, 0); CP_COMMIT();

    for (int kb = 0; kb < nkb; kb++) {
        int cur = kb & 1;
        CP_WAIT(0);
        __syncthreads();
        if (kb + 1 < nkb) { loadAB(kb + 1, cur ^ 1); CP_COMMIT(); }
        const uint32_t aBase = smb + cur * (ASZ * 2);
        const uint32_t bBase = smb + cur * (BWSZ * 2) + oBh;
        #pragma unroll
        for (int ks = 0; ks < 2; ks++) {
            uint32_t ah[2][4], al[2][4], bh[8][2], bl[8][2];
            #pragma unroll
            for (int mt = 0; mt < 2; mt++) {
                uint32_t addr = aBase + (uint32_t)((wm + mt * 16) * (A_STR * 2) + ks * 32) + aLane;
                ldm_x4(ah[mt][0], ah[mt][1], ah[mt][2], ah[mt][3], addr);
                ldm_x4(al[mt][0], al[mt][1], al[mt][2], al[mt][3], addr + oAl);
            }
            #pragma unroll
            for (int p = 0; p < 4; p++) {
                uint32_t addr = bBase + (uint32_t)(ks * 16 * (BW_STR * 2) + (wn + p * 16) * 2) + bLane;
                uint32_t t0, t1, t2, t3;
                ldm_x4t(t0, t1, t2, t3, addr);
                bh[2 * p][0] = t0; bh[2 * p][1] = t1; bh[2 * p + 1][0] = t2; bh[2 * p + 1][1] = t3;
                ldm_x4t(t0, t1, t2, t3, addr + (oBl - oBh));
                bl[2 * p][0] = t0; bl[2 * p][1] = t1; bl[2 * p + 1][0] = t2; bl[2 * p + 1][1] = t3;
            }
            #pragma unroll
            for (int mt = 0; mt < 2; mt++)
                #pragma unroll
                for (int nt = 0; nt < 8; nt++)
                    mma_bf16(acc[mt][nt], ah[mt], bh[nt]);
            #pragma unroll
            for (int mt = 0; mt < 2; mt++)
                #pragma unroll
                for (int nt = 0; nt < 8; nt++)
                    mma_bf16(acc[mt][nt], ah[mt], bl[nt]);
            #pragma unroll
            for (int mt = 0; mt < 2; mt++)
                #pragma unroll
                for (int nt = 0; nt < 8; nt++)
                    mma_bf16(acc[mt][nt], al[mt], bh[nt]);
        }
    }

    float* CfZ = Cf ? (Cf + (size_t)zz * M * N) : nullptr;
    #pragma unroll
    for (int mt = 0; mt < 2; mt++) {
        int r0 = bm + wm + mt * 16 + group;
        #pragma unroll
        for (int nt = 0; nt < 8; nt++) {
            int cc = bn + wn + nt * 8 + tig * 2;
            float b0 = (zz == 0) ? bias[cc] : 0.f;
            float b1 = (zz == 0) ? bias[cc + 1] : 0.f;
            float v00 = acc[mt][nt][0] + b0;
            float v01 = acc[mt][nt][1] + b1;
            float v10 = acc[mt][nt][2] + b0;
            float v11 = acc[mt][nt][3] + b1;
            if (act) { v00 = gelu_f(v00); v01 = gelu_f(v01); v10 = gelu_f(v10); v11 = gelu_f(v11); }
            if (Chi) {
                uint32_t hh, ll;
                splitpack2(v00, v01, hh, ll);
                *reinterpret_cast<uint32_t*>(&Chi[(size_t)r0 * N + cc]) = hh;
                *reinterpret_cast<uint32_t*>(&Clo[(size_t)r0 * N + cc]) = ll;
                splitpack2(v10, v11, hh, ll);
                *reinterpret_cast<uint32_t*>(&Chi[(size_t)(r0 + 8) * N + cc]) = hh;
                *reinterpret_cast<uint32_t*>(&Clo[(size_t)(r0 + 8) * N + cc]) = ll;
            } else {
                CfZ[(size_t)r0 * N + cc]           = v00;
                CfZ[(size_t)r0 * N + cc + 1]       = v01;
                CfZ[(size_t)(r0 + 8) * N + cc]     = v10;
                CfZ[(size_t)(r0 + 8) * N + cc + 1] = v11;
            }
        }
    }
}

// ------- tensor-core flash attention: 6 smem planes, single-buffer V, 4 CTA/SM
#define AST 72
#define PLB (64 * AST * 2)
#define ATTN_SMEM (6 * PLB + 512)   // 55808

__global__ void __launch_bounds__(128, 4)
flash_attn_mma(const bf16* __restrict__ qkvh, const bf16* __restrict__ qkvl,
               const int* __restrict__ pad, bf16* __restrict__ ohi, bf16* __restrict__ olo)
{
    extern __shared__ char smraw[];
    const uint32_t smb = (uint32_t)__cvta_generic_to_shared(smraw);
    const uint32_t oQ = 0, oK = 2 * PLB, oPS = 6 * PLB;   // V aliases oQ

    const int tid  = threadIdx.x;
    const int lane = tid & 31;
    const int w    = tid >> 5;
    const int qt0  = blockIdx.x * 64;
    const int b    = blockIdx.y;
    const int h    = blockIdx.z;

    const int r7 = lane & 7;
    const int bA = (lane >> 3) & 1;
    const int bB = (lane >> 4) & 1;
    const int kRow = bB * 8 + r7;
    const int kCol = bA * 16;
    const int qg0 = qt0 + w * 16 + (lane >> 2);
    const int qg1 = qg0 + 8;

    // Q load into oQ
    #pragma unroll
    for (int i = 0; i < 4; i++) {
        int s = tid + i * 128;
        int r = s >> 3, c8 = (s & 7) * 8;
        size_t g = (size_t)(b * TT + qt0 + r) * (3 * DD) + h * DKH + c8;
        uint32_t d = smb + oQ + (uint32_t)((r * AST + c8) * 2);
        CP_ASYNC16(d, qkvh + g);
        CP_ASYNC16(d + PLB, qkvl + g);
    }
    CP_COMMIT();

    int c_start = 4 - (qt0 >> 6);
    if (c_start < 0) c_start = 0;

    auto issueK = [&](int c, int st) {
        int kc0 = qt0 - WWIN + 64 * c;
        #pragma unroll
        for (int i = 0; i < 4; i++) {
            int s = tid + i * 128;
            int r = s >> 3, c8 = (s & 7) * 8;
            size_t g = (size_t)(b * TT + kc0 + r) * (3 * DD) + DD + h * DKH + c8;
            uint32_t d = smb + oK + (uint32_t)(st * 2 * PLB) + (uint32_t)((r * AST + c8) * 2);
            CP_ASYNC16(d, qkvh + g);
            CP_ASYNC16(d + PLB, qkvl + g);
        }
        if (tid < 16)
            CP_ASYNC16(smb + oPS + (uint32_t)(st * 256 + tid * 16), pad + b * TT + kc0 + tid * 4);
    };
    auto issueV = [&](int c) {
        int kc0 = qt0 - WWIN + 64 * c;
        #pragma unroll
        for (int i = 0; i < 4; i++) {
            int s = tid + i * 128;
            int r = s >> 3, c8 = (s & 7) * 8;
            size_t g = (size_t)(b * TT + kc0 + r) * (3 * DD) + 2 * DD + h * DKH + c8;
            uint32_t d = smb + oQ + (uint32_t)((r * AST + c8) * 2);
            CP_ASYNC16(d, qkvh + g);
            CP_ASYNC16(d + PLB, qkvl + g);
        }
    };

    issueK(c_start, 0); CP_COMMIT();

    CP_WAIT(1);             // Q ready (K outstanding)
    __syncthreads();

    uint32_t qfh[4][4], qfl[4][4];
    #pragma unroll
    for (int ks = 0; ks < 4; ks++) {
        uint32_t ad = smb + oQ + (uint32_t)(((w * 16 + bA * 8 + r7) * AST) * 2 + ks * 32 + bB * 16);
        ldm_x4(qfh[ks][0], qfh[ks][1], qfh[ks][2], qfh[ks][3], ad);
        ldm_x4(qfl[ks][0], qfl[ks][1], qfl[ks][2], qfl[ks][3], ad + PLB);
    }
    __syncthreads();        // all warps done reading Q
    issueV(c_start); CP_COMMIT();   // V(c_start) overwrites Q region

    float Oa[8][4];
    #pragma unroll
    for (int i = 0; i < 8; i++)
        #pragma unroll
        for (int j = 0; j < 4; j++) Oa[i][j] = 0.f;
    float mold[2] = {-1e30f, -1e30f};
    float lrun[2] = {0.f, 0.f};

    int stage = 0;
    for (int c = c_start; c < 5; c++) {
        const int kc0 = qt0 - WWIN + 64 * c;
        CP_WAIT(1);         // K(c) ready
        __syncthreads();

        float s4[8][4];
        #pragma unroll
        for (int i = 0; i < 8; i++)
            #pragma unroll
            for (int j = 0; j < 4; j++) s4[i][j] = 0.f;
        const uint32_t kb0 = smb + oK + (uint32_t)(stage * 2 * PLB);
        #pragma unroll
        for (int ks = 0; ks < 4; ks++) {
            #pragma unroll
            for (int p = 0; p < 4; p++) {
                uint32_t ad = kb0 + (uint32_t)(((p * 16 + kRow) * AST) * 2 + ks * 32 + kCol);
                uint32_t h0, h1, h2, h3, l0, l1, l2, l3;
                ldm_x4(h0, h1, h2, h3, ad);
                ldm_x4(l0, l1, l2, l3, ad + PLB);
                uint32_t bh0[2] = {h0, h1}, bh1[2] = {h2, h3};
                uint32_t bl0[2] = {l0, l1}, bl1[2] = {l2, l3};
                mma_bf16(s4[2 * p],     qfh[ks], bh0);
                mma_bf16(s4[2 * p + 1], qfh[ks], bh1);
                mma_bf16(s4[2 * p],     qfh[ks], bl0);
                mma_bf16(s4[2 * p + 1], qfh[ks], bl1);
                mma_bf16(s4[2 * p],     qfl[ks], bh0);
                mma_bf16(s4[2 * p + 1], qfl[ks], bh1);
            }
        }

        if (c < 4) { issueK(c + 1, stage ^ 1); CP_COMMIT(); }

        const int* psS = (const int*)(smraw + oPS + stage * 256);
        const int jb = 2 * (lane & 3);
        #pragma unroll
        for (int nt = 0; nt < 8; nt++) {
            int jj = nt * 8 + jb;
            int j  = kc0 + jj;
            int pd0 = psS[jj], pd1 = psS[jj + 1];
            bool v00 = (j     <= qg0) && (j     >= qg0 - (WWIN - 1)) && !pd0;
            bool v01 = (j + 1 <= qg0) && (j + 1 >= qg0 - (WWIN - 1)) && !pd1;
            bool v10 = (j     <= qg1) && (j     >= qg1 - (WWIN - 1)) && !pd0;
            bool v11 = (j + 1 <= qg1) && (j + 1 >= qg1 - (WWIN - 1)) && !pd1;
            s4[nt][0] = v00 ? s4[nt][0] * 0.125f : -1e30f;
            s4[nt][1] = v01 ? s4[nt][1] * 0.125f : -1e30f;
            s4[nt][2] = v10 ? s4[nt][2] * 0.125f : -1e30f;
            s4[nt][3] = v11 ? s4[nt][3] * 0.125f : -1e30f;
        }

        float mc0 = -1e30f, mc1 = -1e30f;
        #pragma unroll
        for (int nt = 0; nt < 8; nt++) {
            mc0 = fmaxf(mc0, fmaxf(s4[nt][0], s4[nt][1]));
            mc1 = fmaxf(mc1, fmaxf(s4[nt][2], s4[nt][3]));
        }
        mc0 = fmaxf(mc0, __shfl_xor_sync(0xffffffffu, mc0, 1));
        mc0 = fmaxf(mc0, __shfl_xor_sync(0xffffffffu, mc0, 2));
        mc1 = fmaxf(mc1, __shfl_xor_sync(0xffffffffu, mc1, 1));
        mc1 = fmaxf(mc1, __shfl_xor_sync(0xffffffffu, mc1, 2));
        float mn0 = fmaxf(mold[0], mc0);
        float mn1 = fmaxf(mold[1], mc1);
        float al0 = fexp(mold[0] - mn0);
        float al1 = fexp(mold[1] - mn1);
        mold[0] = mn0; mold[1] = mn1;
        float ps0 = 0.f, ps1 = 0.f;
        #pragma unroll
        for (int nt = 0; nt < 8; nt++) {
            float p0 = (s4[nt][0] <= -1e29f) ? 0.f : fexp(s4[nt][0] - mn0);
            float p1 = (s4[nt][1] <= -1e29f) ? 0.f : fexp(s4[nt][1] - mn0);
            float p2 = (s4[nt][2] <= -1e29f) ? 0.f : fexp(s4[nt][2] - mn1);
            float p3 = (s4[nt][3] <= -1e29f) ? 0.f : fexp(s4[nt][3] - mn1);
            s4[nt][0] = p0; s4[nt][1] = p1; s4[nt][2] = p2; s4[nt][3] = p3;
            ps0 += p0 + p1; ps1 += p2 + p3;
        }
        ps0 += __shfl_xor_sync(0xffffffffu, ps0, 1);
        ps0 += __shfl_xor_sync(0xffffffffu, ps0, 2);
        ps1 += __shfl_xor_sync(0xffffffffu, ps1, 1);
        ps1 += __shfl_xor_sync(0xffffffffu, ps1, 2);
        lrun[0] = lrun[0] * al0 + ps0;
        lrun[1] = lrun[1] * al1 + ps1;

        #pragma unroll
        for (int nt = 0; nt < 8; nt++) {
            Oa[nt][0] *= al0; Oa[nt][1] *= al0;
            Oa[nt][2] *= al1; Oa[nt][3] *= al1;
        }

        if (c < 4) { CP_WAIT(1); } else { CP_WAIT(0); }   // V(c) ready
        __syncthreads();

        // PV: pack P per-t, fused ldsm+mma per-p (low register pressure)
        #pragma unroll
        for (int t = 0; t < 4; t++) {
            uint32_t aPh[4], aPl[4];
            splitpack2(s4[2 * t][0],     s4[2 * t][1],     aPh[0], aPl[0]);
            splitpack2(s4[2 * t][2],     s4[2 * t][3],     aPh[1], aPl[1]);
            splitpack2(s4[2 * t + 1][0], s4[2 * t + 1][1], aPh[2], aPl[2]);
            splitpack2(s4[2 * t + 1][2], s4[2 * t + 1][3], aPh[3], aPl[3]);
            #pragma unroll
            for (int p = 0; p < 4; p++) {
                uint32_t ad = smb + oQ + (uint32_t)(((t * 16 + bA * 8 + r7) * AST) * 2 + p * 32 + bB * 16);
                uint32_t h0, h1, h2, h3, l0, l1, l2, l3;
                ldm_x4t(h0, h1, h2, h3, ad);
                ldm_x4t(l0, l1, l2, l3, ad + PLB);
                uint32_t vh0[2] = {h0, h1}, vh1[2] = {h2, h3};
                uint32_t vl0[2] = {l0, l1}, vl1[2] = {l2, l3};
                mma_bf16(Oa[2 * p],     aPh, vh0);
                mma_bf16(Oa[2 * p + 1], aPh, vh1);
                mma_bf16(Oa[2 * p],     aPh, vl0);
                mma_bf16(Oa[2 * p + 1], aPh, vl1);
                mma_bf16(Oa[2 * p],     aPl, vh0);
                mma_bf16(Oa[2 * p + 1], aPl, vh1);
            }
        }
        __syncthreads();        // all PV reads of V(c) complete
        if (c < 4) { issueV(c + 1); CP_COMMIT(); }
        stage ^= 1;
    }

    float inv0 = (lrun[0] > 0.f) ? 1.0f / lrun[0] : 0.f;
    float inv1 = (lrun[1] > 0.f) ? 1.0f / lrun[1] : 0.f;
    int tok0 = b * TT + qt0 + w * 16 + (lane >> 2);
    #pragma unroll
    for (int nt = 0; nt < 8; nt++) {
        int col = h * DKH + nt * 8 + 2 * (lane & 3);
        uint32_t hi, lo;
        splitpack2(Oa[nt][0] * inv0, Oa[nt][1] * inv0, hi, lo);
        *reinterpret_cast<uint32_t*>(&ohi[(size_t)tok0 * DD + col]) = hi;
        *reinterpret_cast<uint32_t*>(&olo[(size_t)tok0 * DD + col]) = lo;
        splitpack2(Oa[nt][2] * inv1, Oa[nt][3] * inv1, hi, lo);
        *reinterpret_cast<uint32_t*>(&ohi[(size_t)(tok0 + 8) * DD + col]) = hi;
        *reinterpret_cast<uint32_t*>(&olo[(size_t)(tok0 + 8) * DD + col]) = lo;
    }
}

// ---------------- head finish ----------------
__global__ void finish_heads(const float* __restrict__ p, const float* __restrict__ bhd,
                             const float* __restrict__ bhW2, const float* __restrict__ bhb2,
                             const float* __restrict__ ahW2, const float* __restrict__ ahb2,
                             const float* __restrict__ chW2, const float* __restrict__ chb2,
                             float* __restrict__ out)
{
    int token = blockIdx.x;
    int tid = threadIdx.x;
    __shared__ float red[128];
    const size_t PO = (size_t)NT * DD;
    const float* r0 = p + (size_t)token * DD;
    const float* r1 = r0 + PO;

    float vA = gelu_f(r0[tid] + r1[tid] + bhd[tid]);
    float vB = gelu_f(r0[tid + 128] + r1[tid + 128] + bhd[tid + 128]);
    float vC = gelu_f(r0[tid + 256] + r1[tid + 256] + bhd[tid + 256]);
    float vD = gelu_f(r0[tid + 384] + r1[tid + 384] + bhd[tid + 384]);

    float t0 = vA * bhW2[tid * 2]     + vB * bhW2[(tid + 128) * 2];
    float t1 = vA * bhW2[tid * 2 + 1] + vB * bhW2[(tid + 128) * 2 + 1];
    red[tid] = t0; __syncthreads();
    for (int s = 64; s > 0; s >>= 1) { if (tid < s) red[tid] += red[tid + s]; __syncthreads(); }
    float s0 = red[0]; __syncthreads();
    red[tid] = t1; __syncthreads();
    for (int s = 64; s > 0; s >>= 1) { if (tid < s) red[tid] += red[tid + s]; __syncthreads(); }
    float s1 = red[0]; __syncthreads();
    red[tid] = vC * ahW2[tid]; __syncthreads();
    for (int s = 64; s > 0; s >>= 1) { if (tid < s) red[tid] += red[tid + s]; __syncthreads(); }
    float sa = red[0]; __syncthreads();
    red[tid] = vD * chW2[tid]; __syncthreads();
    for (int s = 64; s > 0; s >>= 1) { if (tid < s) red[tid] += red[tid + s]; __syncthreads(); }
    float sc = red[0];

    if (tid == 0) {
        out[token * 2 + 0] = s0 + bhb2[0];
        out[token * 2 + 1] = s1 + bhb2[1];
        out[2 * NT + token] = sa + ahb2[0];
        out[3 * NT + token] = 1.0f / (1.0f + expf(-(sc + chb2[0])));
    }
}

#define SYM(p, s) cudaGetSymbolAddress((void**)&p, s)

extern "C" void kernel_launch(void* const* d_in, const int* in_sizes, int n_in,
                              void* d_out, int out_size)
{
    const float* x    = (const float*)d_in[0];
    const float* pos  = (const float*)d_in[1];
    const float* Wp   = (const float*)d_in[2];
    const float* bp   = (const float*)d_in[3];
    const float* Wq   = (const float*)d_in[4];
    const float* bq   = (const float*)d_in[5];
    const float* Wk   = (const float*)d_in[6];
    const float* bk   = (const float*)d_in[7];
    const float* Wv   = (const float*)d_in[8];
    const float* bv   = (const float*)d_in[9];
    const float* Wo   = (const float*)d_in[10];
    const float* bo   = (const float*)d_in[11];
    const float* ln1g = (const float*)d_in[12];
    const float* ln1b = (const float*)d_in[13];
    const float* W1   = (const float*)d_in[14];
    const float* b1   = (const float*)d_in[15];
    const float* W2   = (const float*)d_in[16];
    const float* b2   = (const float*)d_in[17];
    const float* ln2g = (const float*)d_in[18];
    const float* ln2b = (const float*)d_in[19];
    const float* bhW1 = (const float*)d_in[20];
    const float* bhb1 = (const float*)d_in[21];
    const float* bhW2 = (const float*)d_in[22];
    const float* bhb2 = (const float*)d_in[23];
    const float* ahW1 = (const float*)d_in[24];
    const float* ahb1 = (const float*)d_in[25];
    const float* ahW2 = (const float*)d_in[26];
    const float* ahb2 = (const float*)d_in[27];
    const float* chW1 = (const float*)d_in[28];
    const float* chb1 = (const float*)d_in[29];
    const float* chW2 = (const float*)d_in[30];
    const float* chb2 = (const float*)d_in[31];
    float* out = (float*)d_out;

    float *p_h, *p_p, *p_bqkv, *p_bhd;
    bf16 *p_hnh, *p_hnl, *p_qkvh, *p_qkvl, *p_oh, *p_ol, *p_ffh, *p_ffl, *p_hsh, *p_hsl;
    bf16 *pw_qkvh, *pw_qkvl, *pw_woh, *pw_wol, *pw_w1h, *pw_w1l, *pw_w2h, *pw_w2l, *pw_hdh, *pw_hdl;
    int* p_pad;
    SYM(p_h, g_h);       SYM(p_p, g_p);
    SYM(p_hnh, g_hn_h);  SYM(p_hnl, g_hn_l);
    SYM(p_qkvh, g_qkv_h); SYM(p_qkvl, g_qkv_l);
    SYM(p_oh, g_o_h);    SYM(p_ol, g_o_l);
    SYM(p_ffh, g_ff_h);  SYM(p_ffl, g_ff_l);
    SYM(p_hsh, g_hs_h);  SYM(p_hsl, g_hs_l);
    SYM(p_pad, g_pad);
    SYM(pw_qkvh, w_qkv_h); SYM(pw_qkvl, w_qkv_l);
    SYM(pw_woh, w_wo_h); SYM(pw_wol, w_wo_l);
    SYM(pw_w1h, w_w1_h); SYM(pw_w1l, w_w1_l);
    SYM(pw_w2h, w_w2_h); SYM(pw_w2l, w_w2_l);
    SYM(pw_hdh, w_hd_h); SYM(pw_hdl, w_hd_l);
    SYM(p_bqkv, b_qkv);  SYM(p_bhd, b_hd);

    cudaFuncSetAttribute(gemm_bf3w, cudaFuncAttributeMaxDynamicSharedMemorySize, GEMMW_SMEM);
    cudaFuncSetAttribute(flash_attn_mma, cudaFuncAttributeMaxDynamicSharedMemorySize, ATTN_SMEM);

    prep_all<<<4096, 256>>>(Wq, Wk, Wv, bq, bk, bv, Wo, W1, W2,
                            bhW1, bhb1, ahW1, ahb1, chW1, chb1);
    embed_kernel<<<NT, 128>>>(x, pos, Wp, bp);

    dim3 gQKVw(3 * DD / 128, NT / 128, 1);
    dim3 gFFw (DFF / 128,    NT / 128, 1);
    dim3 gDw  (DD / 128,     NT / 128, 2);
    dim3 gAtt(TT / 64, NB, NH);

    for (int l = 0; l < NL; l++) {
        if (l == 0)
            ln_kernel<<<NT, 256>>>(p_h, ln1g, ln1b, p_hnh, p_hnl);
        else
            ln_comb<<<NT, 256>>>(p_h, p_p, ln1g + l * DD, ln1b + l * DD, p_hnh, p_hnl);
        gemm_bf3w<<<gQKVw, 256, GEMMW_SMEM>>>(p_hnh, p_hnl,
            pw_qkvh + (size_t)l * DD * 3 * DD, pw_qkvl + (size_t)l * DD * 3 * DD,
            p_bqkv + l * 3 * DD, nullptr, p_qkvh, p_qkvl, NT, 3 * DD, DD, 0);
        flash_attn_mma<<<gAtt, 128, ATTN_SMEM>>>(p_qkvh, p_qkvl, p_pad, p_oh, p_ol);
        gemm_bf3w<<<gDw, 256, GEMMW_SMEM>>>(p_oh, p_ol,
            pw_woh + (size_t)l * DD * DD, pw_wol + (size_t)l * DD * DD,
            bo + l * DD, p_p, nullptr, nullptr, NT, DD, DD, 0);
        ln_comb<<<NT, 256>>>(p_h, p_p, ln2g + l * DD, ln2b + l * DD, p_hnh, p_hnl);
        gemm_bf3w<<<gFFw, 256, GEMMW_SMEM>>>(p_hnh, p_hnl,
            pw_w1h + (size_t)l * DD * DFF, pw_w1l + (size_t)l * DD * DFF,
            b1 + l * DFF, nullptr, p_ffh, p_ffl, NT, DFF, DD, 1);
        gemm_bf3w<<<gDw, 256, GEMMW_SMEM>>>(p_ffh, p_ffl,
            pw_w2h + (size_t)l * DFF * DD, pw_w2l + (size_t)l * DFF * DD,
            b2 + l * DD, p_p, nullptr, nullptr, NT, DD, DFF, 0);
    }

    comb_split<<<1024, 256>>>((const float4*)p_h, (const float4*)p_p, p_hsh, p_hsl, NT * DD / 4);
    gemm_bf3w<<<gDw, 256, GEMMW_SMEM>>>(p_hsh, p_hsl, pw_hdh, pw_hdl,
        p_bhd, p_p, nullptr, nullptr, NT, DD, DD, 0);
    finish_heads<<<NT, 128>>>(p_p, p_bhd, bhW2, bhb2, ahW2, ahb2, chW2, chb2, out);
}